// round 3
// baseline (speedup 1.0000x reference)
#include <cuda_runtime.h>
#include <math.h>
#include <float.h>

// Problem constants
#define B_    8
#define T_    512
#define IDIM  1799
#define D_    256
#define H_    4
#define FF_   2048
#define L_    16
#define DK    64
#define BT    (B_*T_)    // 4096
#define BH    (B_*H_)    // 32
#define NPK   1023       // distinct rel-pos rows: t-s+511 in [0,1022]

// ------------------------- scratch (device globals) -------------------------
__device__ float g_x[BT*D_];
__device__ float g_y[BT*D_];
__device__ float g_q[BT*D_];
__device__ float g_k[BT*D_];
__device__ float g_v[BT*D_];
__device__ float g_o[BT*D_];
__device__ float g_ff[BT*FF_];
__device__ float g_att[(size_t)BH*T_*T_];   // 33.5 MB
__device__ float g_pkn[NPK*DK];

// ------------------------- block reductions -------------------------
__device__ __forceinline__ float block_sum(float v) {
    __shared__ float sh[33];
    #pragma unroll
    for (int o = 16; o > 0; o >>= 1) v += __shfl_xor_sync(0xffffffffu, v, o);
    int lane = threadIdx.x & 31, w = threadIdx.x >> 5;
    if (lane == 0) sh[w] = v;
    __syncthreads();
    int nw = blockDim.x >> 5;
    float r = (threadIdx.x < nw) ? sh[threadIdx.x] : 0.0f;
    if (w == 0) {
        #pragma unroll
        for (int o = 16; o > 0; o >>= 1) r += __shfl_xor_sync(0xffffffffu, r, o);
        if (lane == 0) sh[32] = r;
    }
    __syncthreads();
    float out = sh[32];
    __syncthreads();
    return out;
}

__device__ __forceinline__ float block_max(float v) {
    __shared__ float shm[33];
    #pragma unroll
    for (int o = 16; o > 0; o >>= 1) v = fmaxf(v, __shfl_xor_sync(0xffffffffu, v, o));
    int lane = threadIdx.x & 31, w = threadIdx.x >> 5;
    if (lane == 0) shm[w] = v;
    __syncthreads();
    int nw = blockDim.x >> 5;
    float r = (threadIdx.x < nw) ? shm[threadIdx.x] : -FLT_MAX;
    if (w == 0) {
        #pragma unroll
        for (int o = 16; o > 0; o >>= 1) r = fmaxf(r, __shfl_xor_sync(0xffffffffu, r, o));
        if (lane == 0) shm[32] = r;
    }
    __syncthreads();
    float out = shm[32];
    __syncthreads();
    return out;
}

// ------------------------- LayerNorm (one block per row) -------------------------
// width == blockDim.x (256 or 64)
__global__ void ln_kernel(const float* __restrict__ in, float* __restrict__ out,
                          const float* __restrict__ g, const float* __restrict__ bb,
                          int width, int relu) {
    size_t row = blockIdx.x;
    float x = in[row * width + threadIdx.x];
    float mean = block_sum(x) / (float)width;
    float d = x - mean;
    float var = block_sum(d * d) / (float)width;
    float y = d * rsqrtf(var + 1e-12f) * g[threadIdx.x] + bb[threadIdx.x];
    if (relu) y = fmaxf(y, 0.0f);
    out[row * width + threadIdx.x] = y;
}

// ------------------------- SGEMM: C[M,N] = A[M,K] @ B[N,K]^T + bias -------------------------
// mode bit0: relu, bit1: add residual R[M,N]
// BM=128, BN=64, BK=16; 256 threads; 8x4 accum per thread.
// M % 128 == 0 and N % 64 == 0 guaranteed by the caller; K arbitrary (guarded).
__global__ __launch_bounds__(256) void sgemm_nt(
    const float* __restrict__ A, const float* __restrict__ Bm,
    const float* __restrict__ bias, const float* __restrict__ R,
    float* __restrict__ C, int M, int N, int K, int mode)
{
    __shared__ float As[16 * 132];
    __shared__ float Bs[16 * 68];
    int tid = threadIdx.x;
    int tx = tid & 15, ty = tid >> 4;
    int row0 = blockIdx.y * 128;
    int col0 = blockIdx.x * 64;

    float acc[8][4];
    #pragma unroll
    for (int i = 0; i < 8; i++)
        #pragma unroll
        for (int j = 0; j < 4; j++) acc[i][j] = 0.0f;

    const float* Ab = A + (size_t)row0 * K;
    const float* Bb = Bm + (size_t)col0 * K;

    int ktiles = (K + 15) >> 4;
    for (int kt = 0; kt < ktiles; ++kt) {
        int k0 = kt << 4;
        // A tile: 128x16, 8 elems/thread, coalesced along K
        #pragma unroll
        for (int i = 0; i < 8; i++) {
            int idx = tid + i * 256;
            int r = idx >> 4, c = idx & 15;
            int kk = k0 + c;
            As[c * 132 + r] = (kk < K) ? Ab[(size_t)r * K + kk] : 0.0f;
        }
        // B tile: 64x16, 4 elems/thread
        #pragma unroll
        for (int i = 0; i < 4; i++) {
            int idx = tid + i * 256;
            int r = idx >> 4, c = idx & 15;
            int kk = k0 + c;
            Bs[c * 68 + r] = (kk < K) ? Bb[(size_t)r * K + kk] : 0.0f;
        }
        __syncthreads();
        #pragma unroll
        for (int kk = 0; kk < 16; kk++) {
            float4 a0 = *(const float4*)&As[kk * 132 + ty * 8];
            float4 a1 = *(const float4*)&As[kk * 132 + ty * 8 + 4];
            float4 b0 = *(const float4*)&Bs[kk * 68 + tx * 4];
            float a[8] = {a0.x, a0.y, a0.z, a0.w, a1.x, a1.y, a1.z, a1.w};
            float bv[4] = {b0.x, b0.y, b0.z, b0.w};
            #pragma unroll
            for (int i = 0; i < 8; i++)
                #pragma unroll
                for (int j = 0; j < 4; j++)
                    acc[i][j] = fmaf(a[i], bv[j], acc[i][j]);
        }
        __syncthreads();
    }

    float4 bia = *(const float4*)&bias[col0 + tx * 4];
    #pragma unroll
    for (int i = 0; i < 8; i++) {
        size_t row = row0 + ty * 8 + i;
        float4 c4;
        c4.x = acc[i][0] + bia.x;
        c4.y = acc[i][1] + bia.y;
        c4.z = acc[i][2] + bia.z;
        c4.w = acc[i][3] + bia.w;
        if (mode & 2) {
            float4 r4 = *(const float4*)&R[row * N + col0 + tx * 4];
            c4.x += r4.x; c4.y += r4.y; c4.z += r4.z; c4.w += r4.w;
        }
        if (mode & 1) {
            c4.x = fmaxf(c4.x, 0.0f); c4.y = fmaxf(c4.y, 0.0f);
            c4.z = fmaxf(c4.z, 0.0f); c4.w = fmaxf(c4.w, 0.0f);
        }
        *(float4*)&C[row * N + col0 + tx * 4] = c4;
    }
}

// ------------------------- scores: S[bh,t,s] = scale * q[t] . (k[s] + pkn[t-s+511]) -----------
// grid (s_tiles=8, t_tiles=8, bh=32), 256 threads, 64x64 output tile, 4x4/thread
__global__ __launch_bounds__(256) void scores_kernel(
    const float* __restrict__ q, const float* __restrict__ k,
    const int* __restrict__ masks, float* __restrict__ att)
{
    __shared__ float Qs[16 * 68];
    __shared__ float Ks[16 * 68];
    __shared__ float Ps[16 * 128];   // 127 diag rows x 16 d
    int tid = threadIdx.x;
    int tx = tid & 15, ty = tid >> 4;
    int s0 = blockIdx.x * 64, t0 = blockIdx.y * 64, bh = blockIdx.z;
    int b = bh >> 2, h = bh & 3;

    const float* qb = q + ((size_t)(b * T_ + t0)) * D_ + h * DK;
    const float* kb = k + ((size_t)(b * T_ + s0)) * D_ + h * DK;
    const float* pb = g_pkn + (size_t)(t0 - s0 + 448) * DK;  // local delta 0..126

    float acc[4][4];
    #pragma unroll
    for (int i = 0; i < 4; i++)
        #pragma unroll
        for (int j = 0; j < 4; j++) acc[i][j] = 0.0f;

    for (int dt = 0; dt < 4; dt++) {
        #pragma unroll
        for (int i = 0; i < 4; i++) {
            int idx = tid + i * 256;
            int r = idx >> 4, c = idx & 15;
            Qs[c * 68 + r] = qb[(size_t)r * D_ + dt * 16 + c];
            Ks[c * 68 + r] = kb[(size_t)r * D_ + dt * 16 + c];
        }
        #pragma unroll
        for (int i = 0; i < 8; i++) {
            int idx = tid + i * 256;
            if (idx < 127 * 16) {
                int r = idx >> 4, c = idx & 15;
                Ps[c * 128 + r] = pb[(size_t)r * DK + dt * 16 + c];
            }
        }
        __syncthreads();
        #pragma unroll
        for (int dd = 0; dd < 16; dd++) {
            float aq[4], ak[4];
            #pragma unroll
            for (int i = 0; i < 4; i++) aq[i] = Qs[dd * 68 + ty * 4 + i];
            #pragma unroll
            for (int j = 0; j < 4; j++) ak[j] = Ks[dd * 68 + tx * 4 + j];
            #pragma unroll
            for (int i = 0; i < 4; i++)
                #pragma unroll
                for (int j = 0; j < 4; j++) {
                    int dl = (ty * 4 + i) - (tx * 4 + j) + 63;
                    acc[i][j] = fmaf(aq[i], ak[j] + Ps[dd * 128 + dl], acc[i][j]);
                }
        }
        __syncthreads();
    }

    const float scale = 0.125f;  // 1/sqrt(64)
    float* ob = att + ((size_t)bh * T_ + t0) * T_ + s0;
    #pragma unroll
    for (int i = 0; i < 4; i++) {
        #pragma unroll
        for (int j = 0; j < 4; j++) {
            int s = s0 + tx * 4 + j;
            float vv = acc[i][j] * scale;
            if (masks[b * T_ + s] == 0) vv = -FLT_MAX;
            ob[(size_t)(ty * 4 + i) * T_ + tx * 4 + j] = vv;
        }
    }
}

// ------------------------- softmax over s (row of 512), in place -------------------------
// grid (t=512, bh=32), 128 threads x 4 elems
__global__ __launch_bounds__(128) void softmax_kernel(float* __restrict__ att,
                                                      const int* __restrict__ masks) {
    int t = blockIdx.x, bh = blockIdx.y;
    int b = bh >> 2;
    float* row = att + ((size_t)bh * T_ + t) * T_;
    int tid = threadIdx.x;
    float v[4];
    #pragma unroll
    for (int j = 0; j < 4; j++) v[j] = row[tid + j * 128];
    float mx = fmaxf(fmaxf(v[0], v[1]), fmaxf(v[2], v[3]));
    mx = block_max(mx);
    float e[4], s = 0.0f;
    #pragma unroll
    for (int j = 0; j < 4; j++) { e[j] = expf(v[j] - mx); s += e[j]; }
    s = block_sum(s);
    float inv = 1.0f / s;
    #pragma unroll
    for (int j = 0; j < 4; j++) {
        int si = tid + j * 128;
        row[si] = (masks[b * T_ + si] != 0) ? e[j] * inv : 0.0f;
    }
}

// ------------------------- attn @ V : o[b,t, h*64+d] -------------------------
// grid (t_tiles=8, bh=32), 256 threads, 64(t) x 64(d) tile, 4x4/thread
__global__ __launch_bounds__(256) void attnv_kernel(const float* __restrict__ att,
                                                    const float* __restrict__ v,
                                                    float* __restrict__ o) {
    __shared__ float As2[16 * 68];
    __shared__ float Vs[16 * 68];
    int tid = threadIdx.x;
    int tx = tid & 15, ty = tid >> 4;
    int t0 = blockIdx.x * 64, bh = blockIdx.y;
    int b = bh >> 2, h = bh & 3;
    const float* ab = att + ((size_t)bh * T_ + t0) * T_;
    const float* vb = v + ((size_t)(b * T_)) * D_ + h * DK;

    float acc[4][4];
    #pragma unroll
    for (int i = 0; i < 4; i++)
        #pragma unroll
        for (int j = 0; j < 4; j++) acc[i][j] = 0.0f;

    for (int st = 0; st < 32; st++) {
        #pragma unroll
        for (int i = 0; i < 4; i++) {
            int idx = tid + i * 256;
            int r = idx >> 4, c = idx & 15;
            As2[c * 68 + r] = ab[(size_t)r * T_ + st * 16 + c];
        }
        #pragma unroll
        for (int i = 0; i < 4; i++) {
            int idx = tid + i * 256;
            int r = idx >> 6, c = idx & 63;
            Vs[r * 68 + c] = vb[(size_t)(st * 16 + r) * D_ + c];
        }
        __syncthreads();
        #pragma unroll
        for (int sk = 0; sk < 16; sk++) {
            float4 a4 = *(const float4*)&As2[sk * 68 + ty * 4];
            float4 v4 = *(const float4*)&Vs[sk * 68 + tx * 4];
            float a[4] = {a4.x, a4.y, a4.z, a4.w};
            float w[4] = {v4.x, v4.y, v4.z, v4.w};
            #pragma unroll
            for (int i = 0; i < 4; i++)
                #pragma unroll
                for (int j = 0; j < 4; j++)
                    acc[i][j] = fmaf(a[i], w[j], acc[i][j]);
        }
        __syncthreads();
    }
    #pragma unroll
    for (int i = 0; i < 4; i++) {
        float4 c4 = {acc[i][0], acc[i][1], acc[i][2], acc[i][3]};
        *(float4*)&o[((size_t)(b * T_ + t0 + ty * 4 + i)) * D_ + h * DK + tx * 4] = c4;
    }
}

// ------------------------- host orchestration -------------------------
extern "C" void kernel_launch(void* const* d_in, const int* in_sizes, int n_in,
                              void* d_out, int out_size) {
    const float* xs      = (const float*)d_in[0];
    const int*   masks   = (const int*)  d_in[1];
    const float* emb_w   = (const float*)d_in[2];
    const float* emb_b   = (const float*)d_in[3];
    const float* emb_g   = (const float*)d_in[4];
    const float* emb_bt  = (const float*)d_in[5];
    const float* pe_k    = (const float*)d_in[6];
    const float* Wq      = (const float*)d_in[7];
    const float* bq      = (const float*)d_in[8];
    const float* Wk      = (const float*)d_in[9];
    const float* bk      = (const float*)d_in[10];
    const float* Wv      = (const float*)d_in[11];
    const float* bv      = (const float*)d_in[12];
    const float* Wo      = (const float*)d_in[13];
    const float* bo      = (const float*)d_in[14];
    const float* ln1_g   = (const float*)d_in[15];
    const float* ln1_b   = (const float*)d_in[16];
    const float* ln2_g   = (const float*)d_in[17];
    const float* ln2_b   = (const float*)d_in[18];
    const float* lnk_g   = (const float*)d_in[19];
    const float* lnk_b   = (const float*)d_in[20];
    const float* W1      = (const float*)d_in[21];
    const float* b1      = (const float*)d_in[22];
    const float* W2      = (const float*)d_in[23];
    const float* b2      = (const float*)d_in[24];
    const float* after_g = (const float*)d_in[25];
    const float* after_b = (const float*)d_in[26];
    float* out = (float*)d_out;

    float *x, *y, *q, *k, *v, *o, *ff, *att, *pkn;
    cudaGetSymbolAddress((void**)&x,   g_x);
    cudaGetSymbolAddress((void**)&y,   g_y);
    cudaGetSymbolAddress((void**)&q,   g_q);
    cudaGetSymbolAddress((void**)&k,   g_k);
    cudaGetSymbolAddress((void**)&v,   g_v);
    cudaGetSymbolAddress((void**)&o,   g_o);
    cudaGetSymbolAddress((void**)&ff,  g_ff);
    cudaGetSymbolAddress((void**)&att, g_att);
    cudaGetSymbolAddress((void**)&pkn, g_pkn);

    dim3 gProj(D_ / 64, BT / 128);    // (4, 32)
    dim3 gFF1(FF_ / 64, BT / 128);    // (32, 32)

    // embed: GEMM + bias -> LN -> ReLU
    sgemm_nt<<<gProj, 256>>>(xs, emb_w, emb_b, nullptr, y, BT, D_, IDIM, 0);
    ln_kernel<<<BT, 256>>>(y, x, emb_g, emb_bt, D_, 1);

    for (int l = 0; l < L_; l++) {
        // ln1 and normalized rel-pos rows for this layer
        ln_kernel<<<BT, 256>>>(x, y, ln1_g + l * D_, ln1_b + l * D_, D_, 0);
        ln_kernel<<<NPK, DK>>>(pe_k + 489 * DK, pkn, lnk_g + l * DK, lnk_b + l * DK, DK, 0);

        // q/k/v projections
        sgemm_nt<<<gProj, 256>>>(y, Wq + (size_t)l * D_ * D_, bq + l * D_, nullptr, q, BT, D_, D_, 0);
        sgemm_nt<<<gProj, 256>>>(y, Wk + (size_t)l * D_ * D_, bk + l * D_, nullptr, k, BT, D_, D_, 0);
        sgemm_nt<<<gProj, 256>>>(y, Wv + (size_t)l * D_ * D_, bv + l * D_, nullptr, v, BT, D_, D_, 0);

        // attention
        scores_kernel<<<dim3(8, 8, BH), 256>>>(q, k, masks, att);
        softmax_kernel<<<dim3(T_, BH), 128>>>(att, masks);
        attnv_kernel<<<dim3(8, BH), 256>>>(att, v, o);

        // output projection + residual
        sgemm_nt<<<gProj, 256>>>(o, Wo + (size_t)l * D_ * D_, bo + l * D_, x, x, BT, D_, D_, 2);

        // FFN
        ln_kernel<<<BT, 256>>>(x, y, ln2_g + l * D_, ln2_b + l * D_, D_, 0);
        sgemm_nt<<<gFF1, 256>>>(y, W1 + (size_t)l * FF_ * D_, b1 + l * FF_, nullptr, ff, BT, FF_, D_, 1);
        sgemm_nt<<<gProj, 256>>>(ff, W2 + (size_t)l * D_ * FF_, b2 + l * D_, x, x, BT, D_, FF_, 2);
    }

    // final LN
    ln_kernel<<<BT, 256>>>(x, out, after_g, after_b, D_, 0);
}

// round 4
// speedup vs baseline: 1.5891x; 1.5891x over previous
#include <cuda_runtime.h>
#include <math.h>
#include <float.h>

// Problem constants
#define B_    8
#define T_    512
#define IDIM  1799
#define D_    256
#define H_    4
#define FF_   2048
#define L_    16
#define DK    64
#define BT    (B_*T_)    // 4096
#define BH    (B_*H_)    // 32
#define NPK   1023       // distinct rel-pos rows: t-s+511 in [0,1022]

// ------------------------- scratch (device globals) -------------------------
__device__ float g_x[BT*D_];
__device__ float g_y[BT*D_];
__device__ float g_q[BT*D_];
__device__ float g_k[BT*D_];
__device__ float g_v[BT*D_];
__device__ float g_o[BT*D_];
__device__ float g_ff[BT*FF_];
__device__ float g_att[(size_t)BH*T_*T_];   // 33.5 MB
__device__ float g_pkn[NPK*DK];

// ------------------------- block reductions -------------------------
__device__ __forceinline__ float block_sum(float v) {
    __shared__ float sh[33];
    #pragma unroll
    for (int o = 16; o > 0; o >>= 1) v += __shfl_xor_sync(0xffffffffu, v, o);
    int lane = threadIdx.x & 31, w = threadIdx.x >> 5;
    if (lane == 0) sh[w] = v;
    __syncthreads();
    int nw = blockDim.x >> 5;
    float r = (threadIdx.x < nw) ? sh[threadIdx.x] : 0.0f;
    if (w == 0) {
        #pragma unroll
        for (int o = 16; o > 0; o >>= 1) r += __shfl_xor_sync(0xffffffffu, r, o);
        if (lane == 0) sh[32] = r;
    }
    __syncthreads();
    float out = sh[32];
    __syncthreads();
    return out;
}

__device__ __forceinline__ float block_max(float v) {
    __shared__ float shm[33];
    #pragma unroll
    for (int o = 16; o > 0; o >>= 1) v = fmaxf(v, __shfl_xor_sync(0xffffffffu, v, o));
    int lane = threadIdx.x & 31, w = threadIdx.x >> 5;
    if (lane == 0) shm[w] = v;
    __syncthreads();
    int nw = blockDim.x >> 5;
    float r = (threadIdx.x < nw) ? shm[threadIdx.x] : -FLT_MAX;
    if (w == 0) {
        #pragma unroll
        for (int o = 16; o > 0; o >>= 1) r = fmaxf(r, __shfl_xor_sync(0xffffffffu, r, o));
        if (lane == 0) shm[32] = r;
    }
    __syncthreads();
    float out = shm[32];
    __syncthreads();
    return out;
}

// ------------------------- LayerNorm (one block per row) -------------------------
__global__ void ln_kernel(const float* __restrict__ in, float* __restrict__ out,
                          const float* __restrict__ g, const float* __restrict__ bb,
                          int width, int relu) {
    size_t row = blockIdx.x;
    float x = in[row * width + threadIdx.x];
    float mean = block_sum(x) / (float)width;
    float d = x - mean;
    float var = block_sum(d * d) / (float)width;
    float y = d * rsqrtf(var + 1e-12f) * g[threadIdx.x] + bb[threadIdx.x];
    if (relu) y = fmaxf(y, 0.0f);
    out[row * width + threadIdx.x] = y;
}

// ------------------------- tf32 helpers -------------------------
__device__ __forceinline__ unsigned f2tf(float f) {
    unsigned r;
    asm("cvt.rna.tf32.f32 %0, %1;" : "=r"(r) : "f"(f));
    return r;
}

__device__ __forceinline__ void mma_tf32(float c[4],
                                         unsigned a0, unsigned a1, unsigned a2, unsigned a3,
                                         unsigned b0, unsigned b1) {
    asm volatile(
        "mma.sync.aligned.m16n8k8.row.col.f32.tf32.tf32.f32 "
        "{%0,%1,%2,%3}, {%4,%5,%6,%7}, {%8,%9}, {%0,%1,%2,%3};"
        : "+f"(c[0]), "+f"(c[1]), "+f"(c[2]), "+f"(c[3])
        : "r"(a0), "r"(a1), "r"(a2), "r"(a3), "r"(b0), "r"(b1));
}

// ------------------------- TF32 tensor-core GEMM -------------------------
// C[M,N] = A[M,K] @ B[N,K]^T + bias  (mode bit0: relu, bit1: add residual R)
// BM=BN=64, BK=32, 128 threads = 4 warps (2x2), warp tile 32x32.
// M,N multiples of 64; K arbitrary (guarded scalar path when K%4 != 0).
#define SSTR 36   // smem row stride in words (BK=32 + 4 pad): conflict-free frags
__global__ __launch_bounds__(128) void tgemm_nt(
    const float* __restrict__ A, const float* __restrict__ Bm,
    const float* __restrict__ bias, const float* __restrict__ R,
    float* __restrict__ C, int M, int N, int K, int mode)
{
    __shared__ unsigned As[64 * SSTR];
    __shared__ unsigned Bs[64 * SSTR];

    int tid = threadIdx.x;
    int lane = tid & 31, warp = tid >> 5;
    int wm = warp >> 1, wn = warp & 1;           // 2x2 warp grid
    int g = lane >> 2, tg = lane & 3;            // quad row / in-quad col

    int r0 = blockIdx.y * 64;                    // M offset
    int c0 = blockIdx.x * 64;                    // N offset

    const float* Ab = A + (size_t)r0 * K;
    const float* Bb = Bm + (size_t)c0 * K;

    float acc[2][4][4];
    #pragma unroll
    for (int mt = 0; mt < 2; mt++)
        #pragma unroll
        for (int nt = 0; nt < 4; nt++)
            #pragma unroll
            for (int e = 0; e < 4; e++) acc[mt][nt][e] = 0.0f;

    bool vec = ((K & 3) == 0);

    for (int k0 = 0; k0 < K; k0 += 32) {
        if (vec) {
            // 64 rows x 8 float4 = 512 float4 per tile, 4 per thread
            #pragma unroll
            for (int i = 0; i < 4; i++) {
                int idx = tid + i * 128;
                int r = idx >> 3, c4 = idx & 7;
                float4 av = *(const float4*)&Ab[(size_t)r * K + k0 + c4 * 4];
                float4 bv = *(const float4*)&Bb[(size_t)r * K + k0 + c4 * 4];
                unsigned* ap = &As[r * SSTR + c4 * 4];
                unsigned* bp = &Bs[r * SSTR + c4 * 4];
                ap[0] = f2tf(av.x); ap[1] = f2tf(av.y); ap[2] = f2tf(av.z); ap[3] = f2tf(av.w);
                bp[0] = f2tf(bv.x); bp[1] = f2tf(bv.y); bp[2] = f2tf(bv.z); bp[3] = f2tf(bv.w);
            }
        } else {
            #pragma unroll
            for (int i = 0; i < 16; i++) {
                int idx = tid + i * 128;
                int r = idx >> 5, c = idx & 31;
                int kk = k0 + c;
                float av = (kk < K) ? Ab[(size_t)r * K + kk] : 0.0f;
                float bv = (kk < K) ? Bb[(size_t)r * K + kk] : 0.0f;
                As[r * SSTR + c] = f2tf(av);
                Bs[r * SSTR + c] = f2tf(bv);
            }
        }
        __syncthreads();

        #pragma unroll
        for (int kc = 0; kc < 4; kc++) {
            int ko = kc * 8;
            unsigned a[2][4], b[4][2];
            #pragma unroll
            for (int mt = 0; mt < 2; mt++) {
                int row = wm * 32 + mt * 16 + g;
                a[mt][0] = As[row * SSTR + ko + tg];
                a[mt][1] = As[(row + 8) * SSTR + ko + tg];
                a[mt][2] = As[row * SSTR + ko + tg + 4];
                a[mt][3] = As[(row + 8) * SSTR + ko + tg + 4];
            }
            #pragma unroll
            for (int nt = 0; nt < 4; nt++) {
                int col = wn * 32 + nt * 8 + g;
                b[nt][0] = Bs[col * SSTR + ko + tg];
                b[nt][1] = Bs[col * SSTR + ko + tg + 4];
            }
            #pragma unroll
            for (int mt = 0; mt < 2; mt++)
                #pragma unroll
                for (int nt = 0; nt < 4; nt++)
                    mma_tf32(acc[mt][nt], a[mt][0], a[mt][1], a[mt][2], a[mt][3],
                             b[nt][0], b[nt][1]);
        }
        __syncthreads();
    }

    // epilogue: c0,c1 at (row, col..col+1), c2,c3 at (row+8, col..col+1)
    #pragma unroll
    for (int mt = 0; mt < 2; mt++) {
        int row = r0 + wm * 32 + mt * 16 + g;
        #pragma unroll
        for (int nt = 0; nt < 4; nt++) {
            int col = c0 + wn * 32 + nt * 8 + 2 * tg;
            float2 bi = *(const float2*)&bias[col];
            #pragma unroll
            for (int half = 0; half < 2; half++) {
                int rr = row + half * 8;
                float x0 = acc[mt][nt][half * 2 + 0] + bi.x;
                float x1 = acc[mt][nt][half * 2 + 1] + bi.y;
                if (mode & 2) {
                    float2 rv = *(const float2*)&R[(size_t)rr * N + col];
                    x0 += rv.x; x1 += rv.y;
                }
                if (mode & 1) { x0 = fmaxf(x0, 0.0f); x1 = fmaxf(x1, 0.0f); }
                float2 o2 = {x0, x1};
                *(float2*)&C[(size_t)rr * N + col] = o2;
            }
        }
    }
}

// ------------------------- scores: S[bh,t,s] = scale * q[t] . (k[s] + pkn[t-s+511]) -----------
__global__ __launch_bounds__(256) void scores_kernel(
    const float* __restrict__ q, const float* __restrict__ k,
    const int* __restrict__ masks, float* __restrict__ att)
{
    __shared__ float Qs[16 * 68];
    __shared__ float Ks[16 * 68];
    __shared__ float Ps[16 * 128];
    int tid = threadIdx.x;
    int tx = tid & 15, ty = tid >> 4;
    int s0 = blockIdx.x * 64, t0 = blockIdx.y * 64, bh = blockIdx.z;
    int b = bh >> 2, h = bh & 3;

    const float* qb = q + ((size_t)(b * T_ + t0)) * D_ + h * DK;
    const float* kb = k + ((size_t)(b * T_ + s0)) * D_ + h * DK;
    const float* pb = g_pkn + (size_t)(t0 - s0 + 448) * DK;

    float acc[4][4];
    #pragma unroll
    for (int i = 0; i < 4; i++)
        #pragma unroll
        for (int j = 0; j < 4; j++) acc[i][j] = 0.0f;

    for (int dt = 0; dt < 4; dt++) {
        #pragma unroll
        for (int i = 0; i < 4; i++) {
            int idx = tid + i * 256;
            int r = idx >> 4, c = idx & 15;
            Qs[c * 68 + r] = qb[(size_t)r * D_ + dt * 16 + c];
            Ks[c * 68 + r] = kb[(size_t)r * D_ + dt * 16 + c];
        }
        #pragma unroll
        for (int i = 0; i < 8; i++) {
            int idx = tid + i * 256;
            if (idx < 127 * 16) {
                int r = idx >> 4, c = idx & 15;
                Ps[c * 128 + r] = pb[(size_t)r * DK + dt * 16 + c];
            }
        }
        __syncthreads();
        #pragma unroll
        for (int dd = 0; dd < 16; dd++) {
            float aq[4], ak[4];
            #pragma unroll
            for (int i = 0; i < 4; i++) aq[i] = Qs[dd * 68 + ty * 4 + i];
            #pragma unroll
            for (int j = 0; j < 4; j++) ak[j] = Ks[dd * 68 + tx * 4 + j];
            #pragma unroll
            for (int i = 0; i < 4; i++)
                #pragma unroll
                for (int j = 0; j < 4; j++) {
                    int dl = (ty * 4 + i) - (tx * 4 + j) + 63;
                    acc[i][j] = fmaf(aq[i], ak[j] + Ps[dd * 128 + dl], acc[i][j]);
                }
        }
        __syncthreads();
    }

    const float scale = 0.125f;
    float* ob = att + ((size_t)bh * T_ + t0) * T_ + s0;
    #pragma unroll
    for (int i = 0; i < 4; i++) {
        #pragma unroll
        for (int j = 0; j < 4; j++) {
            int s = s0 + tx * 4 + j;
            float vv = acc[i][j] * scale;
            if (masks[b * T_ + s] == 0) vv = -FLT_MAX;
            ob[(size_t)(ty * 4 + i) * T_ + tx * 4 + j] = vv;
        }
    }
}

// ------------------------- softmax over s (row of 512), in place -------------------------
__global__ __launch_bounds__(128) void softmax_kernel(float* __restrict__ att,
                                                      const int* __restrict__ masks) {
    int t = blockIdx.x, bh = blockIdx.y;
    int b = bh >> 2;
    float* row = att + ((size_t)bh * T_ + t) * T_;
    int tid = threadIdx.x;
    float v[4];
    #pragma unroll
    for (int j = 0; j < 4; j++) v[j] = row[tid + j * 128];
    float mx = fmaxf(fmaxf(v[0], v[1]), fmaxf(v[2], v[3]));
    mx = block_max(mx);
    float e[4], s = 0.0f;
    #pragma unroll
    for (int j = 0; j < 4; j++) { e[j] = expf(v[j] - mx); s += e[j]; }
    s = block_sum(s);
    float inv = 1.0f / s;
    #pragma unroll
    for (int j = 0; j < 4; j++) {
        int si = tid + j * 128;
        row[si] = (masks[b * T_ + si] != 0) ? e[j] * inv : 0.0f;
    }
}

// ------------------------- attn @ V : o[b,t, h*64+d] -------------------------
__global__ __launch_bounds__(256) void attnv_kernel(const float* __restrict__ att,
                                                    const float* __restrict__ v,
                                                    float* __restrict__ o) {
    __shared__ float As2[16 * 68];
    __shared__ float Vs[16 * 68];
    int tid = threadIdx.x;
    int tx = tid & 15, ty = tid >> 4;
    int t0 = blockIdx.x * 64, bh = blockIdx.y;
    int b = bh >> 2, h = bh & 3;
    const float* ab = att + ((size_t)bh * T_ + t0) * T_;
    const float* vb = v + ((size_t)(b * T_)) * D_ + h * DK;

    float acc[4][4];
    #pragma unroll
    for (int i = 0; i < 4; i++)
        #pragma unroll
        for (int j = 0; j < 4; j++) acc[i][j] = 0.0f;

    for (int st = 0; st < 32; st++) {
        #pragma unroll
        for (int i = 0; i < 4; i++) {
            int idx = tid + i * 256;
            int r = idx >> 4, c = idx & 15;
            As2[c * 68 + r] = ab[(size_t)r * T_ + st * 16 + c];
        }
        #pragma unroll
        for (int i = 0; i < 4; i++) {
            int idx = tid + i * 256;
            int r = idx >> 6, c = idx & 63;
            Vs[r * 68 + c] = vb[(size_t)(st * 16 + r) * D_ + c];
        }
        __syncthreads();
        #pragma unroll
        for (int sk = 0; sk < 16; sk++) {
            float4 a4 = *(const float4*)&As2[sk * 68 + ty * 4];
            float4 v4 = *(const float4*)&Vs[sk * 68 + tx * 4];
            float a[4] = {a4.x, a4.y, a4.z, a4.w};
            float w[4] = {v4.x, v4.y, v4.z, v4.w};
            #pragma unroll
            for (int i = 0; i < 4; i++)
                #pragma unroll
                for (int j = 0; j < 4; j++)
                    acc[i][j] = fmaf(a[i], w[j], acc[i][j]);
        }
        __syncthreads();
    }
    #pragma unroll
    for (int i = 0; i < 4; i++) {
        float4 c4 = {acc[i][0], acc[i][1], acc[i][2], acc[i][3]};
        *(float4*)&o[((size_t)(b * T_ + t0 + ty * 4 + i)) * D_ + h * DK + tx * 4] = c4;
    }
}

// ------------------------- host orchestration -------------------------
extern "C" void kernel_launch(void* const* d_in, const int* in_sizes, int n_in,
                              void* d_out, int out_size) {
    const float* xs      = (const float*)d_in[0];
    const int*   masks   = (const int*)  d_in[1];
    const float* emb_w   = (const float*)d_in[2];
    const float* emb_b   = (const float*)d_in[3];
    const float* emb_g   = (const float*)d_in[4];
    const float* emb_bt  = (const float*)d_in[5];
    const float* pe_k    = (const float*)d_in[6];
    const float* Wq      = (const float*)d_in[7];
    const float* bq      = (const float*)d_in[8];
    const float* Wk      = (const float*)d_in[9];
    const float* bk      = (const float*)d_in[10];
    const float* Wv      = (const float*)d_in[11];
    const float* bv      = (const float*)d_in[12];
    const float* Wo      = (const float*)d_in[13];
    const float* bo      = (const float*)d_in[14];
    const float* ln1_g   = (const float*)d_in[15];
    const float* ln1_b   = (const float*)d_in[16];
    const float* ln2_g   = (const float*)d_in[17];
    const float* ln2_b   = (const float*)d_in[18];
    const float* lnk_g   = (const float*)d_in[19];
    const float* lnk_b   = (const float*)d_in[20];
    const float* W1      = (const float*)d_in[21];
    const float* b1      = (const float*)d_in[22];
    const float* W2      = (const float*)d_in[23];
    const float* b2      = (const float*)d_in[24];
    const float* after_g = (const float*)d_in[25];
    const float* after_b = (const float*)d_in[26];
    float* out = (float*)d_out;

    float *x, *y, *q, *k, *v, *o, *ff, *att, *pkn;
    cudaGetSymbolAddress((void**)&x,   g_x);
    cudaGetSymbolAddress((void**)&y,   g_y);
    cudaGetSymbolAddress((void**)&q,   g_q);
    cudaGetSymbolAddress((void**)&k,   g_k);
    cudaGetSymbolAddress((void**)&v,   g_v);
    cudaGetSymbolAddress((void**)&o,   g_o);
    cudaGetSymbolAddress((void**)&ff,  g_ff);
    cudaGetSymbolAddress((void**)&att, g_att);
    cudaGetSymbolAddress((void**)&pkn, g_pkn);

    dim3 gProj(D_ / 64, BT / 64);     // (4, 64)  = 256 blocks
    dim3 gFF1(FF_ / 64, BT / 64);     // (32, 64) = 2048 blocks

    // embed: GEMM + bias -> LN -> ReLU
    tgemm_nt<<<gProj, 128>>>(xs, emb_w, emb_b, nullptr, y, BT, D_, IDIM, 0);
    ln_kernel<<<BT, 256>>>(y, x, emb_g, emb_bt, D_, 1);

    for (int l = 0; l < L_; l++) {
        ln_kernel<<<BT, 256>>>(x, y, ln1_g + l * D_, ln1_b + l * D_, D_, 0);
        ln_kernel<<<NPK, DK>>>(pe_k + 489 * DK, pkn, lnk_g + l * DK, lnk_b + l * DK, DK, 0);

        tgemm_nt<<<gProj, 128>>>(y, Wq + (size_t)l * D_ * D_, bq + l * D_, nullptr, q, BT, D_, D_, 0);
        tgemm_nt<<<gProj, 128>>>(y, Wk + (size_t)l * D_ * D_, bk + l * D_, nullptr, k, BT, D_, D_, 0);
        tgemm_nt<<<gProj, 128>>>(y, Wv + (size_t)l * D_ * D_, bv + l * D_, nullptr, v, BT, D_, D_, 0);

        scores_kernel<<<dim3(8, 8, BH), 256>>>(q, k, masks, att);
        softmax_kernel<<<dim3(T_, BH), 128>>>(att, masks);
        attnv_kernel<<<dim3(8, BH), 256>>>(att, v, o);

        tgemm_nt<<<gProj, 128>>>(o, Wo + (size_t)l * D_ * D_, bo + l * D_, x, x, BT, D_, D_, 2);

        ln_kernel<<<BT, 256>>>(x, y, ln2_g + l * D_, ln2_b + l * D_, D_, 0);
        tgemm_nt<<<gFF1, 128>>>(y, W1 + (size_t)l * FF_ * D_, b1 + l * FF_, nullptr, ff, BT, FF_, D_, 1);
        tgemm_nt<<<gProj, 128>>>(ff, W2 + (size_t)l * D_ * FF_, b2 + l * D_, x, x, BT, D_, FF_, 2);
    }

    ln_kernel<<<BT, 256>>>(x, out, after_g, after_b, D_, 0);
}

// round 5
// speedup vs baseline: 2.1953x; 1.3815x over previous
#include <cuda_runtime.h>
#include <math.h>
#include <float.h>

// Problem constants
#define B_    8
#define T_    512
#define IDIM  1799
#define D_    256
#define H_    4
#define FF_   2048
#define L_    16
#define DK    64
#define BT    (B_*T_)    // 4096
#define BH    (B_*H_)    // 32
#define NPK   1023       // distinct rel-pos rows: t-s+511 in [0,1022]

// ------------------------- scratch (device globals) -------------------------
__device__ float g_x[BT*D_];
__device__ float g_y[BT*D_];
__device__ float g_q[BT*D_];
__device__ float g_k[BT*D_];
__device__ float g_v[BT*D_];
__device__ float g_o[BT*D_];
__device__ float g_ff[BT*FF_];
__device__ float g_att[(size_t)BH*T_*T_];   // 33.5 MB
__device__ float g_pkn[(size_t)L_*NPK*DK];  // all layers, 4.2 MB

// ------------------------- block reductions -------------------------
__device__ __forceinline__ float block_sum(float v) {
    __shared__ float sh[33];
    #pragma unroll
    for (int o = 16; o > 0; o >>= 1) v += __shfl_xor_sync(0xffffffffu, v, o);
    int lane = threadIdx.x & 31, w = threadIdx.x >> 5;
    if (lane == 0) sh[w] = v;
    __syncthreads();
    int nw = blockDim.x >> 5;
    float r = (threadIdx.x < nw) ? sh[threadIdx.x] : 0.0f;
    if (w == 0) {
        #pragma unroll
        for (int o = 16; o > 0; o >>= 1) r += __shfl_xor_sync(0xffffffffu, r, o);
        if (lane == 0) sh[32] = r;
    }
    __syncthreads();
    float out = sh[32];
    __syncthreads();
    return out;
}

__device__ __forceinline__ float block_max(float v) {
    __shared__ float shm[33];
    #pragma unroll
    for (int o = 16; o > 0; o >>= 1) v = fmaxf(v, __shfl_xor_sync(0xffffffffu, v, o));
    int lane = threadIdx.x & 31, w = threadIdx.x >> 5;
    if (lane == 0) shm[w] = v;
    __syncthreads();
    int nw = blockDim.x >> 5;
    float r = (threadIdx.x < nw) ? shm[threadIdx.x] : -FLT_MAX;
    if (w == 0) {
        #pragma unroll
        for (int o = 16; o > 0; o >>= 1) r = fmaxf(r, __shfl_xor_sync(0xffffffffu, r, o));
        if (lane == 0) shm[32] = r;
    }
    __syncthreads();
    float out = shm[32];
    __syncthreads();
    return out;
}

// ------------------------- LayerNorm (one block per row) -------------------------
__global__ void ln_kernel(const float* __restrict__ in, float* __restrict__ out,
                          const float* __restrict__ g, const float* __restrict__ bb,
                          int width, int relu) {
    size_t row = blockIdx.x;
    float x = in[row * width + threadIdx.x];
    float mean = block_sum(x) / (float)width;
    float d = x - mean;
    float var = block_sum(d * d) / (float)width;
    float y = d * rsqrtf(var + 1e-12f) * g[threadIdx.x] + bb[threadIdx.x];
    if (relu) y = fmaxf(y, 0.0f);
    out[row * width + threadIdx.x] = y;
}

// all-layers pkn LN: grid (NPK, L), block 64
__global__ void ln_pkn_all(const float* __restrict__ pe_k, float* __restrict__ pkn,
                           const float* __restrict__ lnk_g, const float* __restrict__ lnk_b) {
    int row = blockIdx.x, l = blockIdx.y;
    float x = pe_k[(size_t)(489 + row) * DK + threadIdx.x];
    float mean = block_sum(x) / (float)DK;
    float d = x - mean;
    float var = block_sum(d * d) / (float)DK;
    float y = d * rsqrtf(var + 1e-12f) * lnk_g[l * DK + threadIdx.x] + lnk_b[l * DK + threadIdx.x];
    pkn[((size_t)l * NPK + row) * DK + threadIdx.x] = y;
}

// ------------------------- tf32 helpers -------------------------
__device__ __forceinline__ unsigned f2tf(float f) {
    unsigned r;
    asm("cvt.rna.tf32.f32 %0, %1;" : "=r"(r) : "f"(f));
    return r;
}

__device__ __forceinline__ void mma_tf32(float c[4],
                                         unsigned a0, unsigned a1, unsigned a2, unsigned a3,
                                         unsigned b0, unsigned b1) {
    asm volatile(
        "mma.sync.aligned.m16n8k8.row.col.f32.tf32.tf32.f32 "
        "{%0,%1,%2,%3}, {%4,%5,%6,%7}, {%8,%9}, {%0,%1,%2,%3};"
        : "+f"(c[0]), "+f"(c[1]), "+f"(c[2]), "+f"(c[3])
        : "r"(a0), "r"(a1), "r"(a2), "r"(a3), "r"(b0), "r"(b1));
}

// ------------------------- TF32 tensor-core GEMM body -------------------------
// C[M,N] = A[M,K] @ B[N,K]^T + bias  (mode bit0: relu, bit1: add residual R)
// One 64x64 block tile; 128 threads = 4 warps (2x2), warp tile 32x32.
#define SSTR 36
__device__ __forceinline__ void tgemm_body(
    const float* __restrict__ A, const float* __restrict__ Bm,
    const float* __restrict__ bias, const float* __restrict__ R,
    float* __restrict__ C, int N, int K, int mode, int r0, int c0)
{
    __shared__ unsigned As[64 * SSTR];
    __shared__ unsigned Bs[64 * SSTR];

    int tid = threadIdx.x;
    int lane = tid & 31, warp = tid >> 5;
    int wm = warp >> 1, wn = warp & 1;
    int g = lane >> 2, tg = lane & 3;

    const float* Ab = A + (size_t)r0 * K;
    const float* Bb = Bm + (size_t)c0 * K;

    float acc[2][4][4];
    #pragma unroll
    for (int mt = 0; mt < 2; mt++)
        #pragma unroll
        for (int nt = 0; nt < 4; nt++)
            #pragma unroll
            for (int e = 0; e < 4; e++) acc[mt][nt][e] = 0.0f;

    bool vec = ((K & 3) == 0);

    for (int k0 = 0; k0 < K; k0 += 32) {
        if (vec) {
            #pragma unroll
            for (int i = 0; i < 4; i++) {
                int idx = tid + i * 128;
                int r = idx >> 3, c4 = idx & 7;
                float4 av = *(const float4*)&Ab[(size_t)r * K + k0 + c4 * 4];
                float4 bv = *(const float4*)&Bb[(size_t)r * K + k0 + c4 * 4];
                unsigned* ap = &As[r * SSTR + c4 * 4];
                unsigned* bp = &Bs[r * SSTR + c4 * 4];
                ap[0] = f2tf(av.x); ap[1] = f2tf(av.y); ap[2] = f2tf(av.z); ap[3] = f2tf(av.w);
                bp[0] = f2tf(bv.x); bp[1] = f2tf(bv.y); bp[2] = f2tf(bv.z); bp[3] = f2tf(bv.w);
            }
        } else {
            #pragma unroll
            for (int i = 0; i < 16; i++) {
                int idx = tid + i * 128;
                int r = idx >> 5, c = idx & 31;
                int kk = k0 + c;
                float av = (kk < K) ? Ab[(size_t)r * K + kk] : 0.0f;
                float bv = (kk < K) ? Bb[(size_t)r * K + kk] : 0.0f;
                As[r * SSTR + c] = f2tf(av);
                Bs[r * SSTR + c] = f2tf(bv);
            }
        }
        __syncthreads();

        #pragma unroll
        for (int kc = 0; kc < 4; kc++) {
            int ko = kc * 8;
            unsigned a[2][4], b[4][2];
            #pragma unroll
            for (int mt = 0; mt < 2; mt++) {
                int row = wm * 32 + mt * 16 + g;
                a[mt][0] = As[row * SSTR + ko + tg];
                a[mt][1] = As[(row + 8) * SSTR + ko + tg];
                a[mt][2] = As[row * SSTR + ko + tg + 4];
                a[mt][3] = As[(row + 8) * SSTR + ko + tg + 4];
            }
            #pragma unroll
            for (int nt = 0; nt < 4; nt++) {
                int col = wn * 32 + nt * 8 + g;
                b[nt][0] = Bs[col * SSTR + ko + tg];
                b[nt][1] = Bs[col * SSTR + ko + tg + 4];
            }
            #pragma unroll
            for (int mt = 0; mt < 2; mt++)
                #pragma unroll
                for (int nt = 0; nt < 4; nt++)
                    mma_tf32(acc[mt][nt], a[mt][0], a[mt][1], a[mt][2], a[mt][3],
                             b[nt][0], b[nt][1]);
        }
        __syncthreads();
    }

    #pragma unroll
    for (int mt = 0; mt < 2; mt++) {
        int row = r0 + wm * 32 + mt * 16 + g;
        #pragma unroll
        for (int nt = 0; nt < 4; nt++) {
            int col = c0 + wn * 32 + nt * 8 + 2 * tg;
            float2 bi = *(const float2*)&bias[col];
            #pragma unroll
            for (int half = 0; half < 2; half++) {
                int rr = row + half * 8;
                float x0 = acc[mt][nt][half * 2 + 0] + bi.x;
                float x1 = acc[mt][nt][half * 2 + 1] + bi.y;
                if (mode & 2) {
                    float2 rv = *(const float2*)&R[(size_t)rr * N + col];
                    x0 += rv.x; x1 += rv.y;
                }
                if (mode & 1) { x0 = fmaxf(x0, 0.0f); x1 = fmaxf(x1, 0.0f); }
                float2 o2 = {x0, x1};
                *(float2*)&C[(size_t)rr * N + col] = o2;
            }
        }
    }
}

__global__ __launch_bounds__(128) void tgemm_nt(
    const float* __restrict__ A, const float* __restrict__ Bm,
    const float* __restrict__ bias, const float* __restrict__ R,
    float* __restrict__ C, int M, int N, int K, int mode)
{
    tgemm_body(A, Bm, bias, R, C, N, K, mode, blockIdx.y * 64, blockIdx.x * 64);
}

// batched Q/K/V projection: blockIdx.z selects which of the three
__global__ __launch_bounds__(128) void tgemm_qkv(
    const float* __restrict__ A,
    const float* __restrict__ Wq, const float* __restrict__ Wk, const float* __restrict__ Wv,
    const float* __restrict__ bq, const float* __restrict__ bk, const float* __restrict__ bv,
    float* __restrict__ q, float* __restrict__ k, float* __restrict__ v)
{
    const float* W; const float* bi; float* C;
    if (blockIdx.z == 0)      { W = Wq; bi = bq; C = q; }
    else if (blockIdx.z == 1) { W = Wk; bi = bk; C = k; }
    else                      { W = Wv; bi = bv; C = v; }
    tgemm_body(A, W, bi, nullptr, C, D_, D_, 0, blockIdx.y * 64, blockIdx.x * 64);
}

// ------------------------- scores via tf32 MMA -------------------------
// S[bh,t,s] = scale * ( Q.K^T  +  R[t, t-s+63] ),  R = Q_tile @ PknLocal^T
// grid (8,8,32), 128 threads (2x2 warps). A-part warp tile 32x32; R-part 32x64.
__global__ __launch_bounds__(128) void scores_mma(
    const float* __restrict__ q, const float* __restrict__ k,
    const float* __restrict__ pkn_l, const int* __restrict__ masks,
    float* __restrict__ att)
{
    __shared__ char sbuf[(64 + 64 + 128) * SSTR * 4];   // 36864 B; Rs (33792 B) aliases it
    unsigned* Qs = (unsigned*)sbuf;
    unsigned* Ks = Qs + 64 * SSTR;
    unsigned* Ps = Ks + 64 * SSTR;
    float*    Rs = (float*)sbuf;                        // reused after MMA loop

    int tid = threadIdx.x;
    int lane = tid & 31, warp = tid >> 5;
    int wm = warp >> 1, wn = warp & 1;
    int g = lane >> 2, tg = lane & 3;

    int s0 = blockIdx.x * 64, t0 = blockIdx.y * 64, bh = blockIdx.z;
    int b = bh >> 2, h = bh & 3;

    const float* qb = q + ((size_t)(b * T_ + t0)) * D_ + h * DK;
    const float* kb = k + ((size_t)(b * T_ + s0)) * D_ + h * DK;
    const float* pb = pkn_l + (size_t)(t0 - s0 + 448) * DK;   // local dl in [0,126]

    float accA[2][4][4];
    float accR[2][8][4];
    #pragma unroll
    for (int mt = 0; mt < 2; mt++) {
        #pragma unroll
        for (int nt = 0; nt < 4; nt++)
            #pragma unroll
            for (int e = 0; e < 4; e++) accA[mt][nt][e] = 0.0f;
        #pragma unroll
        for (int nt = 0; nt < 8; nt++)
            #pragma unroll
            for (int e = 0; e < 4; e++) accR[mt][nt][e] = 0.0f;
    }

    for (int dt = 0; dt < 2; dt++) {
        int d0 = dt * 32;
        // Q, K tiles: 64x32 each
        #pragma unroll
        for (int i = 0; i < 4; i++) {
            int idx = tid + i * 128;
            int r = idx >> 3, c4 = idx & 7;
            float4 qv = *(const float4*)&qb[(size_t)r * D_ + d0 + c4 * 4];
            float4 kv = *(const float4*)&kb[(size_t)r * D_ + d0 + c4 * 4];
            unsigned* qp = &Qs[r * SSTR + c4 * 4];
            unsigned* kp = &Ks[r * SSTR + c4 * 4];
            qp[0] = f2tf(qv.x); qp[1] = f2tf(qv.y); qp[2] = f2tf(qv.z); qp[3] = f2tf(qv.w);
            kp[0] = f2tf(kv.x); kp[1] = f2tf(kv.y); kp[2] = f2tf(kv.z); kp[3] = f2tf(kv.w);
        }
        // P tile: 128x32 (rows 0..126 real, row 127 zero)
        #pragma unroll
        for (int i = 0; i < 8; i++) {
            int idx = tid + i * 128;
            int r = idx >> 3, c4 = idx & 7;
            unsigned* pp = &Ps[r * SSTR + c4 * 4];
            if (r < 127) {
                float4 pv = *(const float4*)&pb[(size_t)r * DK + d0 + c4 * 4];
                pp[0] = f2tf(pv.x); pp[1] = f2tf(pv.y); pp[2] = f2tf(pv.z); pp[3] = f2tf(pv.w);
            } else {
                pp[0] = 0u; pp[1] = 0u; pp[2] = 0u; pp[3] = 0u;
            }
        }
        __syncthreads();

        #pragma unroll
        for (int kc = 0; kc < 4; kc++) {
            int ko = kc * 8;
            unsigned a[2][4];
            #pragma unroll
            for (int mt = 0; mt < 2; mt++) {
                int row = wm * 32 + mt * 16 + g;
                a[mt][0] = Qs[row * SSTR + ko + tg];
                a[mt][1] = Qs[(row + 8) * SSTR + ko + tg];
                a[mt][2] = Qs[row * SSTR + ko + tg + 4];
                a[mt][3] = Qs[(row + 8) * SSTR + ko + tg + 4];
            }
            // K part
            #pragma unroll
            for (int nt = 0; nt < 4; nt++) {
                int col = wn * 32 + nt * 8 + g;
                unsigned b0 = Ks[col * SSTR + ko + tg];
                unsigned b1 = Ks[col * SSTR + ko + tg + 4];
                #pragma unroll
                for (int mt = 0; mt < 2; mt++)
                    mma_tf32(accA[mt][nt], a[mt][0], a[mt][1], a[mt][2], a[mt][3], b0, b1);
            }
            // rel-pos part
            #pragma unroll
            for (int nt = 0; nt < 8; nt++) {
                int col = wn * 64 + nt * 8 + g;
                unsigned b0 = Ps[col * SSTR + ko + tg];
                unsigned b1 = Ps[col * SSTR + ko + tg + 4];
                #pragma unroll
                for (int mt = 0; mt < 2; mt++)
                    mma_tf32(accR[mt][nt], a[mt][0], a[mt][1], a[mt][2], a[mt][3], b0, b1);
            }
        }
        __syncthreads();
    }

    // spill R to smem (Rs[64][132]); all frag reads done, safe to alias
    #pragma unroll
    for (int mt = 0; mt < 2; mt++) {
        int row = wm * 32 + mt * 16 + g;
        #pragma unroll
        for (int nt = 0; nt < 8; nt++) {
            int col = wn * 64 + nt * 8 + 2 * tg;
            Rs[row * 132 + col]       = accR[mt][nt][0];
            Rs[row * 132 + col + 1]   = accR[mt][nt][1];
            Rs[(row + 8) * 132 + col]     = accR[mt][nt][2];
            Rs[(row + 8) * 132 + col + 1] = accR[mt][nt][3];
        }
    }
    __syncthreads();

    const float scale = 0.125f;  // 1/sqrt(64)
    float* ob = att + ((size_t)bh * T_ + t0) * T_ + s0;
    #pragma unroll
    for (int mt = 0; mt < 2; mt++) {
        int rbase = wm * 32 + mt * 16 + g;
        #pragma unroll
        for (int nt = 0; nt < 4; nt++) {
            int cbase = wn * 32 + nt * 8 + 2 * tg;
            #pragma unroll
            for (int half = 0; half < 2; half++) {
                int rl = rbase + half * 8;
                #pragma unroll
                for (int e = 0; e < 2; e++) {
                    int cl = cbase + e;
                    float vv = (accA[mt][nt][half * 2 + e] + Rs[rl * 132 + (rl - cl + 63)]) * scale;
                    if (masks[b * T_ + s0 + cl] == 0) vv = -FLT_MAX;
                    ob[(size_t)rl * T_ + cl] = vv;
                }
            }
        }
    }
}

// ------------------------- softmax over s (row of 512), in place -------------------------
__global__ __launch_bounds__(128) void softmax_kernel(float* __restrict__ att,
                                                      const int* __restrict__ masks) {
    int t = blockIdx.x, bh = blockIdx.y;
    int b = bh >> 2;
    float* row = att + ((size_t)bh * T_ + t) * T_;
    int tid = threadIdx.x;
    float v[4];
    #pragma unroll
    for (int j = 0; j < 4; j++) v[j] = row[tid + j * 128];
    float mx = fmaxf(fmaxf(v[0], v[1]), fmaxf(v[2], v[3]));
    mx = block_max(mx);
    float e[4], s = 0.0f;
    #pragma unroll
    for (int j = 0; j < 4; j++) { e[j] = expf(v[j] - mx); s += e[j]; }
    s = block_sum(s);
    float inv = 1.0f / s;
    #pragma unroll
    for (int j = 0; j < 4; j++) {
        int si = tid + j * 128;
        row[si] = (masks[b * T_ + si] != 0) ? e[j] * inv : 0.0f;
    }
}

// ------------------------- attn @ V via tf32 MMA -------------------------
// O_tile[64(t),64(d)] = P[64,512] @ V[512,64]; grid (8, 32), 128 threads (2x2 warps)
#define VSTR 37
__global__ __launch_bounds__(128) void attnv_mma(const float* __restrict__ att,
                                                 const float* __restrict__ v,
                                                 float* __restrict__ o) {
    __shared__ unsigned As[64 * SSTR];   // P tile (m x k)
    __shared__ unsigned Bs[64 * VSTR];   // V^T tile ([d][s_local])

    int tid = threadIdx.x;
    int lane = tid & 31, warp = tid >> 5;
    int wm = warp >> 1, wn = warp & 1;
    int g = lane >> 2, tg = lane & 3;

    int t0 = blockIdx.x * 64, bh = blockIdx.y;
    int b = bh >> 2, h = bh & 3;
    const float* ab = att + ((size_t)bh * T_ + t0) * T_;
    const float* vb = v + ((size_t)(b * T_)) * D_ + h * DK;

    float acc[2][4][4];
    #pragma unroll
    for (int mt = 0; mt < 2; mt++)
        #pragma unroll
        for (int nt = 0; nt < 4; nt++)
            #pragma unroll
            for (int e = 0; e < 4; e++) acc[mt][nt][e] = 0.0f;

    for (int st = 0; st < 16; st++) {
        // P tile 64x32
        #pragma unroll
        for (int i = 0; i < 4; i++) {
            int idx = tid + i * 128;
            int r = idx >> 3, c4 = idx & 7;
            float4 pv = *(const float4*)&ab[(size_t)r * T_ + st * 32 + c4 * 4];
            unsigned* pp = &As[r * SSTR + c4 * 4];
            pp[0] = f2tf(pv.x); pp[1] = f2tf(pv.y); pp[2] = f2tf(pv.z); pp[3] = f2tf(pv.w);
        }
        // V tile 32(s) x 64(d), store transposed -> Bs[d][s_local]
        #pragma unroll
        for (int i = 0; i < 4; i++) {
            int idx = tid + i * 128;
            int r = idx >> 4, c4 = idx & 15;
            float4 vv = *(const float4*)&vb[(size_t)(st * 32 + r) * D_ + c4 * 4];
            Bs[(c4 * 4 + 0) * VSTR + r] = f2tf(vv.x);
            Bs[(c4 * 4 + 1) * VSTR + r] = f2tf(vv.y);
            Bs[(c4 * 4 + 2) * VSTR + r] = f2tf(vv.z);
            Bs[(c4 * 4 + 3) * VSTR + r] = f2tf(vv.w);
        }
        __syncthreads();

        #pragma unroll
        for (int kc = 0; kc < 4; kc++) {
            int ko = kc * 8;
            unsigned a[2][4], bfr[4][2];
            #pragma unroll
            for (int mt = 0; mt < 2; mt++) {
                int row = wm * 32 + mt * 16 + g;
                a[mt][0] = As[row * SSTR + ko + tg];
                a[mt][1] = As[(row + 8) * SSTR + ko + tg];
                a[mt][2] = As[row * SSTR + ko + tg + 4];
                a[mt][3] = As[(row + 8) * SSTR + ko + tg + 4];
            }
            #pragma unroll
            for (int nt = 0; nt < 4; nt++) {
                int col = wn * 32 + nt * 8 + g;
                bfr[nt][0] = Bs[col * VSTR + ko + tg];
                bfr[nt][1] = Bs[col * VSTR + ko + tg + 4];
            }
            #pragma unroll
            for (int mt = 0; mt < 2; mt++)
                #pragma unroll
                for (int nt = 0; nt < 4; nt++)
                    mma_tf32(acc[mt][nt], a[mt][0], a[mt][1], a[mt][2], a[mt][3],
                             bfr[nt][0], bfr[nt][1]);
        }
        __syncthreads();
    }

    #pragma unroll
    for (int mt = 0; mt < 2; mt++) {
        int row = wm * 32 + mt * 16 + g;
        #pragma unroll
        for (int nt = 0; nt < 4; nt++) {
            int col = wn * 32 + nt * 8 + 2 * tg;
            #pragma unroll
            for (int half = 0; half < 2; half++) {
                int rr = row + half * 8;
                float2 o2 = {acc[mt][nt][half * 2 + 0], acc[mt][nt][half * 2 + 1]};
                *(float2*)&o[((size_t)(b * T_ + t0 + rr)) * D_ + h * DK + col] = o2;
            }
        }
    }
}

// ------------------------- host orchestration -------------------------
extern "C" void kernel_launch(void* const* d_in, const int* in_sizes, int n_in,
                              void* d_out, int out_size) {
    const float* xs      = (const float*)d_in[0];
    const int*   masks   = (const int*)  d_in[1];
    const float* emb_w   = (const float*)d_in[2];
    const float* emb_b   = (const float*)d_in[3];
    const float* emb_g   = (const float*)d_in[4];
    const float* emb_bt  = (const float*)d_in[5];
    const float* pe_k    = (const float*)d_in[6];
    const float* Wq      = (const float*)d_in[7];
    const float* bq      = (const float*)d_in[8];
    const float* Wk      = (const float*)d_in[9];
    const float* bk      = (const float*)d_in[10];
    const float* Wv      = (const float*)d_in[11];
    const float* bv      = (const float*)d_in[12];
    const float* Wo      = (const float*)d_in[13];
    const float* bo      = (const float*)d_in[14];
    const float* ln1_g   = (const float*)d_in[15];
    const float* ln1_b   = (const float*)d_in[16];
    const float* ln2_g   = (const float*)d_in[17];
    const float* ln2_b   = (const float*)d_in[18];
    const float* lnk_g   = (const float*)d_in[19];
    const float* lnk_b   = (const float*)d_in[20];
    const float* W1      = (const float*)d_in[21];
    const float* b1      = (const float*)d_in[22];
    const float* W2      = (const float*)d_in[23];
    const float* b2      = (const float*)d_in[24];
    const float* after_g = (const float*)d_in[25];
    const float* after_b = (const float*)d_in[26];
    float* out = (float*)d_out;

    float *x, *y, *q, *k, *v, *o, *ff, *att, *pkn;
    cudaGetSymbolAddress((void**)&x,   g_x);
    cudaGetSymbolAddress((void**)&y,   g_y);
    cudaGetSymbolAddress((void**)&q,   g_q);
    cudaGetSymbolAddress((void**)&k,   g_k);
    cudaGetSymbolAddress((void**)&v,   g_v);
    cudaGetSymbolAddress((void**)&o,   g_o);
    cudaGetSymbolAddress((void**)&ff,  g_ff);
    cudaGetSymbolAddress((void**)&att, g_att);
    cudaGetSymbolAddress((void**)&pkn, g_pkn);

    dim3 gProj(D_ / 64, BT / 64);        // (4, 64)
    dim3 gQKV(D_ / 64, BT / 64, 3);      // (4, 64, 3)
    dim3 gFF1(FF_ / 64, BT / 64);        // (32, 64)

    // embed: GEMM + bias -> LN -> ReLU; pkn LN for all layers upfront
    tgemm_nt<<<gProj, 128>>>(xs, emb_w, emb_b, nullptr, y, BT, D_, IDIM, 0);
    ln_pkn_all<<<dim3(NPK, L_), 64>>>(pe_k, pkn, lnk_g, lnk_b);
    ln_kernel<<<BT, 256>>>(y, x, emb_g, emb_bt, D_, 1);

    for (int l = 0; l < L_; l++) {
        ln_kernel<<<BT, 256>>>(x, y, ln1_g + l * D_, ln1_b + l * D_, D_, 0);

        tgemm_qkv<<<gQKV, 128>>>(y,
            Wq + (size_t)l * D_ * D_, Wk + (size_t)l * D_ * D_, Wv + (size_t)l * D_ * D_,
            bq + l * D_, bk + l * D_, bv + l * D_, q, k, v);

        scores_mma<<<dim3(8, 8, BH), 128>>>(q, k, pkn + (size_t)l * NPK * DK, masks, att);
        softmax_kernel<<<dim3(T_, BH), 128>>>(att, masks);
        attnv_mma<<<dim3(8, BH), 128>>>(att, v, o);

        tgemm_nt<<<gProj, 128>>>(o, Wo + (size_t)l * D_ * D_, bo + l * D_, x, x, BT, D_, D_, 2);

        ln_kernel<<<BT, 256>>>(x, y, ln2_g + l * D_, ln2_b + l * D_, D_, 0);
        tgemm_nt<<<gFF1, 128>>>(y, W1 + (size_t)l * FF_ * D_, b1 + l * FF_, nullptr, ff, BT, FF_, D_, 1);
        tgemm_nt<<<gProj, 128>>>(ff, W2 + (size_t)l * D_ * FF_, b2 + l * D_, x, x, BT, D_, FF_, 2);
    }

    ln_kernel<<<BT, 256>>>(x, out, after_g, after_b, D_, 0);
}

// round 6
// speedup vs baseline: 2.3108x; 1.0526x over previous
#include <cuda_runtime.h>
#include <math.h>
#include <float.h>

// Problem constants
#define B_    8
#define T_    512
#define IDIM  1799
#define D_    256
#define H_    4
#define FF_   2048
#define L_    16
#define DK    64
#define BT    (B_*T_)    // 4096
#define BH    (B_*H_)    // 32
#define NPK   1023       // distinct rel-pos rows: t-s+511 in [0,1022]

// ------------------------- scratch (device globals) -------------------------
__device__ float g_x[BT*D_];
__device__ float g_y[BT*D_];
__device__ float g_q[BT*D_];
__device__ float g_k[BT*D_];
__device__ float g_v[BT*D_];
__device__ float g_o[BT*D_];
__device__ float g_ff[BT*FF_];
__device__ float g_att[(size_t)BH*T_*T_];   // 33.5 MB
__device__ float g_pkn[(size_t)L_*NPK*DK];  // all layers, 4.2 MB

// ------------------------- block reduction (for pkn LN only) -------------------------
__device__ __forceinline__ float block_sum64(float v) {
    __shared__ float sh[3];
    #pragma unroll
    for (int o = 16; o > 0; o >>= 1) v += __shfl_xor_sync(0xffffffffu, v, o);
    int lane = threadIdx.x & 31, w = threadIdx.x >> 5;
    if (lane == 0) sh[w] = v;
    __syncthreads();
    float out = sh[0] + sh[1];
    __syncthreads();
    return out;
}

// all-layers pkn LN: grid (NPK, L), block 64
__global__ void ln_pkn_all(const float* __restrict__ pe_k, float* __restrict__ pkn,
                           const float* __restrict__ lnk_g, const float* __restrict__ lnk_b) {
    int row = blockIdx.x, l = blockIdx.y;
    float x = pe_k[(size_t)(489 + row) * DK + threadIdx.x];
    float mean = block_sum64(x) / (float)DK;
    float d = x - mean;
    float var = block_sum64(d * d) / (float)DK;
    float y = d * rsqrtf(var + 1e-12f) * lnk_g[l * DK + threadIdx.x] + lnk_b[l * DK + threadIdx.x];
    pkn[((size_t)l * NPK + row) * DK + threadIdx.x] = y;
}

// ------------------------- warp-per-row LayerNorm, width 256 -------------------------
// block 256 = 8 warps = 8 rows; grid BT/8
__global__ __launch_bounds__(256) void ln_warp(const float* __restrict__ in,
                                               float* __restrict__ out,
                                               const float* __restrict__ g,
                                               const float* __restrict__ bb,
                                               int relu) {
    int warp = threadIdx.x >> 5, lane = threadIdx.x & 31;
    size_t row = (size_t)blockIdx.x * 8 + warp;
    const float* ip = in + row * D_;
    float4 v0 = *(const float4*)&ip[lane * 4];
    float4 v1 = *(const float4*)&ip[128 + lane * 4];
    float s = v0.x + v0.y + v0.z + v0.w + v1.x + v1.y + v1.z + v1.w;
    #pragma unroll
    for (int o = 16; o > 0; o >>= 1) s += __shfl_xor_sync(0xffffffffu, s, o);
    float mean = s * (1.0f / 256.0f);
    float d0x = v0.x - mean, d0y = v0.y - mean, d0z = v0.z - mean, d0w = v0.w - mean;
    float d1x = v1.x - mean, d1y = v1.y - mean, d1z = v1.z - mean, d1w = v1.w - mean;
    float vs = d0x*d0x + d0y*d0y + d0z*d0z + d0w*d0w + d1x*d1x + d1y*d1y + d1z*d1z + d1w*d1w;
    #pragma unroll
    for (int o = 16; o > 0; o >>= 1) vs += __shfl_xor_sync(0xffffffffu, vs, o);
    float rstd = rsqrtf(vs * (1.0f / 256.0f) + 1e-12f);
    float4 g0 = *(const float4*)&g[lane * 4];
    float4 g1 = *(const float4*)&g[128 + lane * 4];
    float4 b0 = *(const float4*)&bb[lane * 4];
    float4 b1 = *(const float4*)&bb[128 + lane * 4];
    float4 o0, o1;
    o0.x = d0x * rstd * g0.x + b0.x;  o0.y = d0y * rstd * g0.y + b0.y;
    o0.z = d0z * rstd * g0.z + b0.z;  o0.w = d0w * rstd * g0.w + b0.w;
    o1.x = d1x * rstd * g1.x + b1.x;  o1.y = d1y * rstd * g1.y + b1.y;
    o1.z = d1z * rstd * g1.z + b1.z;  o1.w = d1w * rstd * g1.w + b1.w;
    if (relu) {
        o0.x = fmaxf(o0.x, 0.f); o0.y = fmaxf(o0.y, 0.f); o0.z = fmaxf(o0.z, 0.f); o0.w = fmaxf(o0.w, 0.f);
        o1.x = fmaxf(o1.x, 0.f); o1.y = fmaxf(o1.y, 0.f); o1.z = fmaxf(o1.z, 0.f); o1.w = fmaxf(o1.w, 0.f);
    }
    float* op = out + row * D_;
    *(float4*)&op[lane * 4] = o0;
    *(float4*)&op[128 + lane * 4] = o1;
}

// ------------------------- tf32 helpers -------------------------
__device__ __forceinline__ unsigned f2tf(float f) {
    unsigned r;
    asm("cvt.rna.tf32.f32 %0, %1;" : "=r"(r) : "f"(f));
    return r;
}

__device__ __forceinline__ void mma_tf32(float c[4],
                                         unsigned a0, unsigned a1, unsigned a2, unsigned a3,
                                         unsigned b0, unsigned b1) {
    asm volatile(
        "mma.sync.aligned.m16n8k8.row.col.f32.tf32.tf32.f32 "
        "{%0,%1,%2,%3}, {%4,%5,%6,%7}, {%8,%9}, {%0,%1,%2,%3};"
        : "+f"(c[0]), "+f"(c[1]), "+f"(c[2]), "+f"(c[3])
        : "r"(a0), "r"(a1), "r"(a2), "r"(a3), "r"(b0), "r"(b1));
}

// ------------------------- TF32 tensor-core GEMM body -------------------------
#define SSTR 36
__device__ __forceinline__ void tgemm_body(
    const float* __restrict__ A, const float* __restrict__ Bm,
    const float* __restrict__ bias, const float* __restrict__ R,
    float* __restrict__ C, int N, int K, int mode, int r0, int c0)
{
    __shared__ unsigned As[64 * SSTR];
    __shared__ unsigned Bs[64 * SSTR];

    int tid = threadIdx.x;
    int lane = tid & 31, warp = tid >> 5;
    int wm = warp >> 1, wn = warp & 1;
    int g = lane >> 2, tg = lane & 3;

    const float* Ab = A + (size_t)r0 * K;
    const float* Bb = Bm + (size_t)c0 * K;

    float acc[2][4][4];
    #pragma unroll
    for (int mt = 0; mt < 2; mt++)
        #pragma unroll
        for (int nt = 0; nt < 4; nt++)
            #pragma unroll
            for (int e = 0; e < 4; e++) acc[mt][nt][e] = 0.0f;

    bool vec = ((K & 3) == 0);

    for (int k0 = 0; k0 < K; k0 += 32) {
        if (vec) {
            #pragma unroll
            for (int i = 0; i < 4; i++) {
                int idx = tid + i * 128;
                int r = idx >> 3, c4 = idx & 7;
                float4 av = *(const float4*)&Ab[(size_t)r * K + k0 + c4 * 4];
                float4 bv = *(const float4*)&Bb[(size_t)r * K + k0 + c4 * 4];
                unsigned* ap = &As[r * SSTR + c4 * 4];
                unsigned* bp = &Bs[r * SSTR + c4 * 4];
                ap[0] = f2tf(av.x); ap[1] = f2tf(av.y); ap[2] = f2tf(av.z); ap[3] = f2tf(av.w);
                bp[0] = f2tf(bv.x); bp[1] = f2tf(bv.y); bp[2] = f2tf(bv.z); bp[3] = f2tf(bv.w);
            }
        } else {
            #pragma unroll
            for (int i = 0; i < 16; i++) {
                int idx = tid + i * 128;
                int r = idx >> 5, c = idx & 31;
                int kk = k0 + c;
                float av = (kk < K) ? Ab[(size_t)r * K + kk] : 0.0f;
                float bv = (kk < K) ? Bb[(size_t)r * K + kk] : 0.0f;
                As[r * SSTR + c] = f2tf(av);
                Bs[r * SSTR + c] = f2tf(bv);
            }
        }
        __syncthreads();

        #pragma unroll
        for (int kc = 0; kc < 4; kc++) {
            int ko = kc * 8;
            unsigned a[2][4], b[4][2];
            #pragma unroll
            for (int mt = 0; mt < 2; mt++) {
                int row = wm * 32 + mt * 16 + g;
                a[mt][0] = As[row * SSTR + ko + tg];
                a[mt][1] = As[(row + 8) * SSTR + ko + tg];
                a[mt][2] = As[row * SSTR + ko + tg + 4];
                a[mt][3] = As[(row + 8) * SSTR + ko + tg + 4];
            }
            #pragma unroll
            for (int nt = 0; nt < 4; nt++) {
                int col = wn * 32 + nt * 8 + g;
                b[nt][0] = Bs[col * SSTR + ko + tg];
                b[nt][1] = Bs[col * SSTR + ko + tg + 4];
            }
            #pragma unroll
            for (int mt = 0; mt < 2; mt++)
                #pragma unroll
                for (int nt = 0; nt < 4; nt++)
                    mma_tf32(acc[mt][nt], a[mt][0], a[mt][1], a[mt][2], a[mt][3],
                             b[nt][0], b[nt][1]);
        }
        __syncthreads();
    }

    #pragma unroll
    for (int mt = 0; mt < 2; mt++) {
        int row = r0 + wm * 32 + mt * 16 + g;
        #pragma unroll
        for (int nt = 0; nt < 4; nt++) {
            int col = c0 + wn * 32 + nt * 8 + 2 * tg;
            float2 bi = *(const float2*)&bias[col];
            #pragma unroll
            for (int half = 0; half < 2; half++) {
                int rr = row + half * 8;
                float x0 = acc[mt][nt][half * 2 + 0] + bi.x;
                float x1 = acc[mt][nt][half * 2 + 1] + bi.y;
                if (mode & 2) {
                    float2 rv = *(const float2*)&R[(size_t)rr * N + col];
                    x0 += rv.x; x1 += rv.y;
                }
                if (mode & 1) { x0 = fmaxf(x0, 0.0f); x1 = fmaxf(x1, 0.0f); }
                float2 o2 = {x0, x1};
                *(float2*)&C[(size_t)rr * N + col] = o2;
            }
        }
    }
}

__global__ __launch_bounds__(128) void tgemm_nt(
    const float* __restrict__ A, const float* __restrict__ Bm,
    const float* __restrict__ bias, const float* __restrict__ R,
    float* __restrict__ C, int M, int N, int K, int mode)
{
    tgemm_body(A, Bm, bias, R, C, N, K, mode, blockIdx.y * 64, blockIdx.x * 64);
}

// batched Q/K/V projection: blockIdx.z selects which of the three
__global__ __launch_bounds__(128) void tgemm_qkv(
    const float* __restrict__ A,
    const float* __restrict__ Wq, const float* __restrict__ Wk, const float* __restrict__ Wv,
    const float* __restrict__ bq, const float* __restrict__ bk, const float* __restrict__ bv,
    float* __restrict__ q, float* __restrict__ k, float* __restrict__ v)
{
    const float* W; const float* bi; float* C;
    if (blockIdx.z == 0)      { W = Wq; bi = bq; C = q; }
    else if (blockIdx.z == 1) { W = Wk; bi = bk; C = k; }
    else                      { W = Wv; bi = bv; C = v; }
    tgemm_body(A, W, bi, nullptr, C, D_, D_, 0, blockIdx.y * 64, blockIdx.x * 64);
}

// ------------------------- scores via tf32 MMA -------------------------
// S[bh,t,s] = scale * ( Q.K^T  +  R[t, t-s+63] ),  R = Q_tile @ PknLocal^T
__global__ __launch_bounds__(128) void scores_mma(
    const float* __restrict__ q, const float* __restrict__ k,
    const float* __restrict__ pkn_l, const int* __restrict__ masks,
    float* __restrict__ att)
{
    __shared__ char sbuf[(64 + 64 + 128) * SSTR * 4];
    unsigned* Qs = (unsigned*)sbuf;
    unsigned* Ks = Qs + 64 * SSTR;
    unsigned* Ps = Ks + 64 * SSTR;
    float*    Rs = (float*)sbuf;

    int tid = threadIdx.x;
    int lane = tid & 31, warp = tid >> 5;
    int wm = warp >> 1, wn = warp & 1;
    int g = lane >> 2, tg = lane & 3;

    int s0 = blockIdx.x * 64, t0 = blockIdx.y * 64, bh = blockIdx.z;
    int b = bh >> 2, h = bh & 3;

    const float* qb = q + ((size_t)(b * T_ + t0)) * D_ + h * DK;
    const float* kb = k + ((size_t)(b * T_ + s0)) * D_ + h * DK;
    const float* pb = pkn_l + (size_t)(t0 - s0 + 448) * DK;

    float accA[2][4][4];
    float accR[2][8][4];
    #pragma unroll
    for (int mt = 0; mt < 2; mt++) {
        #pragma unroll
        for (int nt = 0; nt < 4; nt++)
            #pragma unroll
            for (int e = 0; e < 4; e++) accA[mt][nt][e] = 0.0f;
        #pragma unroll
        for (int nt = 0; nt < 8; nt++)
            #pragma unroll
            for (int e = 0; e < 4; e++) accR[mt][nt][e] = 0.0f;
    }

    for (int dt = 0; dt < 2; dt++) {
        int d0 = dt * 32;
        #pragma unroll
        for (int i = 0; i < 4; i++) {
            int idx = tid + i * 128;
            int r = idx >> 3, c4 = idx & 7;
            float4 qv = *(const float4*)&qb[(size_t)r * D_ + d0 + c4 * 4];
            float4 kv = *(const float4*)&kb[(size_t)r * D_ + d0 + c4 * 4];
            unsigned* qp = &Qs[r * SSTR + c4 * 4];
            unsigned* kp = &Ks[r * SSTR + c4 * 4];
            qp[0] = f2tf(qv.x); qp[1] = f2tf(qv.y); qp[2] = f2tf(qv.z); qp[3] = f2tf(qv.w);
            kp[0] = f2tf(kv.x); kp[1] = f2tf(kv.y); kp[2] = f2tf(kv.z); kp[3] = f2tf(kv.w);
        }
        #pragma unroll
        for (int i = 0; i < 8; i++) {
            int idx = tid + i * 128;
            int r = idx >> 3, c4 = idx & 7;
            unsigned* pp = &Ps[r * SSTR + c4 * 4];
            if (r < 127) {
                float4 pv = *(const float4*)&pb[(size_t)r * DK + d0 + c4 * 4];
                pp[0] = f2tf(pv.x); pp[1] = f2tf(pv.y); pp[2] = f2tf(pv.z); pp[3] = f2tf(pv.w);
            } else {
                pp[0] = 0u; pp[1] = 0u; pp[2] = 0u; pp[3] = 0u;
            }
        }
        __syncthreads();

        #pragma unroll
        for (int kc = 0; kc < 4; kc++) {
            int ko = kc * 8;
            unsigned a[2][4];
            #pragma unroll
            for (int mt = 0; mt < 2; mt++) {
                int row = wm * 32 + mt * 16 + g;
                a[mt][0] = Qs[row * SSTR + ko + tg];
                a[mt][1] = Qs[(row + 8) * SSTR + ko + tg];
                a[mt][2] = Qs[row * SSTR + ko + tg + 4];
                a[mt][3] = Qs[(row + 8) * SSTR + ko + tg + 4];
            }
            #pragma unroll
            for (int nt = 0; nt < 4; nt++) {
                int col = wn * 32 + nt * 8 + g;
                unsigned b0 = Ks[col * SSTR + ko + tg];
                unsigned b1 = Ks[col * SSTR + ko + tg + 4];
                #pragma unroll
                for (int mt = 0; mt < 2; mt++)
                    mma_tf32(accA[mt][nt], a[mt][0], a[mt][1], a[mt][2], a[mt][3], b0, b1);
            }
            #pragma unroll
            for (int nt = 0; nt < 8; nt++) {
                int col = wn * 64 + nt * 8 + g;
                unsigned b0 = Ps[col * SSTR + ko + tg];
                unsigned b1 = Ps[col * SSTR + ko + tg + 4];
                #pragma unroll
                for (int mt = 0; mt < 2; mt++)
                    mma_tf32(accR[mt][nt], a[mt][0], a[mt][1], a[mt][2], a[mt][3], b0, b1);
            }
        }
        __syncthreads();
    }

    #pragma unroll
    for (int mt = 0; mt < 2; mt++) {
        int row = wm * 32 + mt * 16 + g;
        #pragma unroll
        for (int nt = 0; nt < 8; nt++) {
            int col = wn * 64 + nt * 8 + 2 * tg;
            Rs[row * 132 + col]       = accR[mt][nt][0];
            Rs[row * 132 + col + 1]   = accR[mt][nt][1];
            Rs[(row + 8) * 132 + col]     = accR[mt][nt][2];
            Rs[(row + 8) * 132 + col + 1] = accR[mt][nt][3];
        }
    }
    __syncthreads();

    const float scale = 0.125f;
    float* ob = att + ((size_t)bh * T_ + t0) * T_ + s0;
    #pragma unroll
    for (int mt = 0; mt < 2; mt++) {
        int rbase = wm * 32 + mt * 16 + g;
        #pragma unroll
        for (int nt = 0; nt < 4; nt++) {
            int cbase = wn * 32 + nt * 8 + 2 * tg;
            #pragma unroll
            for (int half = 0; half < 2; half++) {
                int rl = rbase + half * 8;
                #pragma unroll
                for (int e = 0; e < 2; e++) {
                    int cl = cbase + e;
                    float vv = (accA[mt][nt][half * 2 + e] + Rs[rl * 132 + (rl - cl + 63)]) * scale;
                    if (masks[b * T_ + s0 + cl] == 0) vv = -FLT_MAX;
                    ob[(size_t)rl * T_ + cl] = vv;
                }
            }
        }
    }
}

// ------------------------- fused online-softmax + P@V -------------------------
// grid (8 t-tiles, 32 bh), 128 threads = 4 warps stacked vertically.
// Warp w owns rows w*16..w*16+15 -> row stats reduce within quads only.
#define PSTR 33
#define VSTR 37
__global__ __launch_bounds__(128) void attnv_fused(const float* __restrict__ att,
                                                   const float* __restrict__ v,
                                                   float* __restrict__ o) {
    __shared__ float    Ss[64 * PSTR];   // S chunk 64 x 32
    __shared__ unsigned Bs[64 * VSTR];   // V^T chunk [d][s_local]

    int tid = threadIdx.x;
    int lane = tid & 31, warp = tid >> 5;
    int g = lane >> 2, tg = lane & 3;

    int t0 = blockIdx.x * 64, bh = blockIdx.y;
    int b = bh >> 2, h = bh & 3;
    const float* ab = att + ((size_t)bh * T_ + t0) * T_;
    const float* vb = v + ((size_t)(b * T_)) * D_ + h * DK;

    float accO[8][4];
    #pragma unroll
    for (int nt = 0; nt < 8; nt++)
        #pragma unroll
        for (int e = 0; e < 4; e++) accO[nt][e] = 0.0f;

    float m0 = -FLT_MAX, m1 = -FLT_MAX;   // running max for rows (warp*16+g), (+8)
    float l0 = 0.0f, l1 = 0.0f;           // running sum

    for (int sc = 0; sc < 16; sc++) {
        int s0c = sc * 32;
        // stage S chunk 64x32
        #pragma unroll
        for (int i = 0; i < 4; i++) {
            int idx = tid + i * 128;
            int r = idx >> 3, c4 = idx & 7;
            float4 sv = *(const float4*)&ab[(size_t)r * T_ + s0c + c4 * 4];
            float* sp = &Ss[r * PSTR + c4 * 4];
            sp[0] = sv.x; sp[1] = sv.y; sp[2] = sv.z; sp[3] = sv.w;
        }
        // stage V chunk 32(s) x 64(d), transposed
        #pragma unroll
        for (int i = 0; i < 4; i++) {
            int idx = tid + i * 128;
            int r = idx >> 4, c4 = idx & 15;
            float4 vv = *(const float4*)&vb[(size_t)(s0c + r) * D_ + c4 * 4];
            Bs[(c4 * 4 + 0) * VSTR + r] = f2tf(vv.x);
            Bs[(c4 * 4 + 1) * VSTR + r] = f2tf(vv.y);
            Bs[(c4 * 4 + 2) * VSTR + r] = f2tf(vv.z);
            Bs[(c4 * 4 + 3) * VSTR + r] = f2tf(vv.w);
        }
        __syncthreads();

        // read this thread's 16 S values: rows (warp*16+g, +8), cols kc*8 + h4*4 + tg
        int rl0 = warp * 16 + g, rl1 = rl0 + 8;
        float s0v[8], s1v[8];
        #pragma unroll
        for (int kc = 0; kc < 4; kc++) {
            #pragma unroll
            for (int h4 = 0; h4 < 2; h4++) {
                int col = kc * 8 + h4 * 4 + tg;
                s0v[kc * 2 + h4] = Ss[rl0 * PSTR + col];
                s1v[kc * 2 + h4] = Ss[rl1 * PSTR + col];
            }
        }
        // chunk max per row (8 local + quad reduce)
        float cm0 = s0v[0], cm1 = s1v[0];
        #pragma unroll
        for (int j = 1; j < 8; j++) { cm0 = fmaxf(cm0, s0v[j]); cm1 = fmaxf(cm1, s1v[j]); }
        cm0 = fmaxf(cm0, __shfl_xor_sync(0xffffffffu, cm0, 1));
        cm0 = fmaxf(cm0, __shfl_xor_sync(0xffffffffu, cm0, 2));
        cm1 = fmaxf(cm1, __shfl_xor_sync(0xffffffffu, cm1, 1));
        cm1 = fmaxf(cm1, __shfl_xor_sync(0xffffffffu, cm1, 2));

        float nm0 = fmaxf(m0, cm0), nm1 = fmaxf(m1, cm1);
        float al0 = __expf(m0 - nm0), al1 = __expf(m1 - nm1);
        // p = exp(s - newm); accumulate sums
        float cs0 = 0.0f, cs1 = 0.0f;
        float p0[8], p1[8];
        #pragma unroll
        for (int j = 0; j < 8; j++) {
            p0[j] = __expf(s0v[j] - nm0);
            p1[j] = __expf(s1v[j] - nm1);
            cs0 += p0[j]; cs1 += p1[j];
        }
        cs0 += __shfl_xor_sync(0xffffffffu, cs0, 1);
        cs0 += __shfl_xor_sync(0xffffffffu, cs0, 2);
        cs1 += __shfl_xor_sync(0xffffffffu, cs1, 1);
        cs1 += __shfl_xor_sync(0xffffffffu, cs1, 2);
        l0 = l0 * al0 + cs0;
        l1 = l1 * al1 + cs1;
        m0 = nm0; m1 = nm1;

        // rescale accO (c0,c1 row0; c2,c3 row1)
        #pragma unroll
        for (int nt = 0; nt < 8; nt++) {
            accO[nt][0] *= al0; accO[nt][1] *= al0;
            accO[nt][2] *= al1; accO[nt][3] *= al1;
        }

        // MMA: P (regs) @ V (smem)
        #pragma unroll
        for (int kc = 0; kc < 4; kc++) {
            int ko = kc * 8;
            unsigned a0 = f2tf(p0[kc * 2 + 0]);
            unsigned a1 = f2tf(p1[kc * 2 + 0]);
            unsigned a2 = f2tf(p0[kc * 2 + 1]);
            unsigned a3 = f2tf(p1[kc * 2 + 1]);
            #pragma unroll
            for (int nt = 0; nt < 8; nt++) {
                int col = nt * 8 + g;
                unsigned b0 = Bs[col * VSTR + ko + tg];
                unsigned b1 = Bs[col * VSTR + ko + tg + 4];
                mma_tf32(accO[nt], a0, a1, a2, a3, b0, b1);
            }
        }
        __syncthreads();
    }

    float inv0 = 1.0f / l0, inv1 = 1.0f / l1;
    int row0 = warp * 16 + g;
    #pragma unroll
    for (int nt = 0; nt < 8; nt++) {
        int col = nt * 8 + 2 * tg;
        float2 oa = {accO[nt][0] * inv0, accO[nt][1] * inv0};
        float2 ob2 = {accO[nt][2] * inv1, accO[nt][3] * inv1};
        *(float2*)&o[((size_t)(b * T_ + t0 + row0)) * D_ + h * DK + col] = oa;
        *(float2*)&o[((size_t)(b * T_ + t0 + row0 + 8)) * D_ + h * DK + col] = ob2;
    }
}

// ------------------------- host orchestration -------------------------
extern "C" void kernel_launch(void* const* d_in, const int* in_sizes, int n_in,
                              void* d_out, int out_size) {
    const float* xs      = (const float*)d_in[0];
    const int*   masks   = (const int*)  d_in[1];
    const float* emb_w   = (const float*)d_in[2];
    const float* emb_b   = (const float*)d_in[3];
    const float* emb_g   = (const float*)d_in[4];
    const float* emb_bt  = (const float*)d_in[5];
    const float* pe_k    = (const float*)d_in[6];
    const float* Wq      = (const float*)d_in[7];
    const float* bq      = (const float*)d_in[8];
    const float* Wk      = (const float*)d_in[9];
    const float* bk      = (const float*)d_in[10];
    const float* Wv      = (const float*)d_in[11];
    const float* bv      = (const float*)d_in[12];
    const float* Wo      = (const float*)d_in[13];
    const float* bo      = (const float*)d_in[14];
    const float* ln1_g   = (const float*)d_in[15];
    const float* ln1_b   = (const float*)d_in[16];
    const float* ln2_g   = (const float*)d_in[17];
    const float* ln2_b   = (const float*)d_in[18];
    const float* lnk_g   = (const float*)d_in[19];
    const float* lnk_b   = (const float*)d_in[20];
    const float* W1      = (const float*)d_in[21];
    const float* b1      = (const float*)d_in[22];
    const float* W2      = (const float*)d_in[23];
    const float* b2      = (const float*)d_in[24];
    const float* after_g = (const float*)d_in[25];
    const float* after_b = (const float*)d_in[26];
    float* out = (float*)d_out;

    float *x, *y, *q, *k, *v, *o, *ff, *att, *pkn;
    cudaGetSymbolAddress((void**)&x,   g_x);
    cudaGetSymbolAddress((void**)&y,   g_y);
    cudaGetSymbolAddress((void**)&q,   g_q);
    cudaGetSymbolAddress((void**)&k,   g_k);
    cudaGetSymbolAddress((void**)&v,   g_v);
    cudaGetSymbolAddress((void**)&o,   g_o);
    cudaGetSymbolAddress((void**)&ff,  g_ff);
    cudaGetSymbolAddress((void**)&att, g_att);
    cudaGetSymbolAddress((void**)&pkn, g_pkn);

    dim3 gProj(D_ / 64, BT / 64);        // (4, 64)
    dim3 gQKV(D_ / 64, BT / 64, 3);      // (4, 64, 3)
    dim3 gFF1(FF_ / 64, BT / 64);        // (32, 64)

    // embed: GEMM + bias -> LN -> ReLU; pkn LN for all layers upfront
    tgemm_nt<<<gProj, 128>>>(xs, emb_w, emb_b, nullptr, y, BT, D_, IDIM, 0);
    ln_pkn_all<<<dim3(NPK, L_), 64>>>(pe_k, pkn, lnk_g, lnk_b);
    ln_warp<<<BT / 8, 256>>>(y, x, emb_g, emb_bt, 1);

    for (int l = 0; l < L_; l++) {
        ln_warp<<<BT / 8, 256>>>(x, y, ln1_g + l * D_, ln1_b + l * D_, 0);

        tgemm_qkv<<<gQKV, 128>>>(y,
            Wq + (size_t)l * D_ * D_, Wk + (size_t)l * D_ * D_, Wv + (size_t)l * D_ * D_,
            bq + l * D_, bk + l * D_, bv + l * D_, q, k, v);

        scores_mma<<<dim3(8, 8, BH), 128>>>(q, k, pkn + (size_t)l * NPK * DK, masks, att);
        attnv_fused<<<dim3(8, BH), 128>>>(att, v, o);

        tgemm_nt<<<gProj, 128>>>(o, Wo + (size_t)l * D_ * D_, bo + l * D_, x, x, BT, D_, D_, 2);

        ln_warp<<<BT / 8, 256>>>(x, y, ln2_g + l * D_, ln2_b + l * D_, 0);
        tgemm_nt<<<gFF1, 128>>>(y, W1 + (size_t)l * FF_ * D_, b1 + l * FF_, nullptr, ff, BT, FF_, D_, 1);
        tgemm_nt<<<gProj, 128>>>(ff, W2 + (size_t)l * D_ * FF_, b2 + l * D_, x, x, BT, D_, FF_, 2);
    }

    ln_warp<<<BT / 8, 256>>>(x, out, after_g, after_b, 0);
}

// round 7
// speedup vs baseline: 2.3867x; 1.0328x over previous
#include <cuda_runtime.h>
#include <math.h>
#include <float.h>

// Problem constants
#define B_    8
#define T_    512
#define IDIM  1799
#define D_    256
#define H_    4
#define FF_   2048
#define L_    16
#define DK    64
#define BT    (B_*T_)    // 4096
#define BH    (B_*H_)    // 32
#define NPK   1023       // distinct rel-pos rows: t-s+511 in [0,1022]

// ------------------------- scratch (device globals) -------------------------
__device__ float g_x[BT*D_];
__device__ float g_y[BT*D_];
__device__ float g_q[BT*D_];
__device__ float g_k[BT*D_];
__device__ float g_v[BT*D_];
__device__ float g_o[BT*D_];
__device__ float g_ff[BT*FF_];
__device__ float g_att[(size_t)BH*T_*T_];   // 33.5 MB
__device__ float g_pkn[(size_t)L_*NPK*DK];  // all layers, 4.2 MB

// ------------------------- block reduction (for pkn LN only) -------------------------
__device__ __forceinline__ float block_sum64(float v) {
    __shared__ float sh[3];
    #pragma unroll
    for (int o = 16; o > 0; o >>= 1) v += __shfl_xor_sync(0xffffffffu, v, o);
    int lane = threadIdx.x & 31, w = threadIdx.x >> 5;
    if (lane == 0) sh[w] = v;
    __syncthreads();
    float out = sh[0] + sh[1];
    __syncthreads();
    return out;
}

// all-layers pkn LN: grid (NPK, L), block 64
__global__ void ln_pkn_all(const float* __restrict__ pe_k, float* __restrict__ pkn,
                           const float* __restrict__ lnk_g, const float* __restrict__ lnk_b) {
    int row = blockIdx.x, l = blockIdx.y;
    float x = pe_k[(size_t)(489 + row) * DK + threadIdx.x];
    float mean = block_sum64(x) / (float)DK;
    float d = x - mean;
    float var = block_sum64(d * d) / (float)DK;
    float y = d * rsqrtf(var + 1e-12f) * lnk_g[l * DK + threadIdx.x] + lnk_b[l * DK + threadIdx.x];
    pkn[((size_t)l * NPK + row) * DK + threadIdx.x] = y;
}

// ------------------------- warp-per-row LayerNorm, width 256 -------------------------
__global__ __launch_bounds__(256) void ln_warp(const float* __restrict__ in,
                                               float* __restrict__ out,
                                               const float* __restrict__ g,
                                               const float* __restrict__ bb,
                                               int relu) {
    int warp = threadIdx.x >> 5, lane = threadIdx.x & 31;
    size_t row = (size_t)blockIdx.x * 8 + warp;
    const float* ip = in + row * D_;
    float4 v0 = *(const float4*)&ip[lane * 4];
    float4 v1 = *(const float4*)&ip[128 + lane * 4];
    float s = v0.x + v0.y + v0.z + v0.w + v1.x + v1.y + v1.z + v1.w;
    #pragma unroll
    for (int o = 16; o > 0; o >>= 1) s += __shfl_xor_sync(0xffffffffu, s, o);
    float mean = s * (1.0f / 256.0f);
    float d0x = v0.x - mean, d0y = v0.y - mean, d0z = v0.z - mean, d0w = v0.w - mean;
    float d1x = v1.x - mean, d1y = v1.y - mean, d1z = v1.z - mean, d1w = v1.w - mean;
    float vs = d0x*d0x + d0y*d0y + d0z*d0z + d0w*d0w + d1x*d1x + d1y*d1y + d1z*d1z + d1w*d1w;
    #pragma unroll
    for (int o = 16; o > 0; o >>= 1) vs += __shfl_xor_sync(0xffffffffu, vs, o);
    float rstd = rsqrtf(vs * (1.0f / 256.0f) + 1e-12f);
    float4 g0 = *(const float4*)&g[lane * 4];
    float4 g1 = *(const float4*)&g[128 + lane * 4];
    float4 b0 = *(const float4*)&bb[lane * 4];
    float4 b1 = *(const float4*)&bb[128 + lane * 4];
    float4 o0, o1;
    o0.x = d0x * rstd * g0.x + b0.x;  o0.y = d0y * rstd * g0.y + b0.y;
    o0.z = d0z * rstd * g0.z + b0.z;  o0.w = d0w * rstd * g0.w + b0.w;
    o1.x = d1x * rstd * g1.x + b1.x;  o1.y = d1y * rstd * g1.y + b1.y;
    o1.z = d1z * rstd * g1.z + b1.z;  o1.w = d1w * rstd * g1.w + b1.w;
    if (relu) {
        o0.x = fmaxf(o0.x, 0.f); o0.y = fmaxf(o0.y, 0.f); o0.z = fmaxf(o0.z, 0.f); o0.w = fmaxf(o0.w, 0.f);
        o1.x = fmaxf(o1.x, 0.f); o1.y = fmaxf(o1.y, 0.f); o1.z = fmaxf(o1.z, 0.f); o1.w = fmaxf(o1.w, 0.f);
    }
    float* op = out + row * D_;
    *(float4*)&op[lane * 4] = o0;
    *(float4*)&op[128 + lane * 4] = o1;
}

// ------------------------- tf32 helpers -------------------------
__device__ __forceinline__ unsigned f2tf(float f) {
    unsigned r;
    asm("cvt.rna.tf32.f32 %0, %1;" : "=r"(r) : "f"(f));
    return r;
}

__device__ __forceinline__ void mma_tf32(float c[4],
                                         unsigned a0, unsigned a1, unsigned a2, unsigned a3,
                                         unsigned b0, unsigned b1) {
    asm volatile(
        "mma.sync.aligned.m16n8k8.row.col.f32.tf32.tf32.f32 "
        "{%0,%1,%2,%3}, {%4,%5,%6,%7}, {%8,%9}, {%0,%1,%2,%3};"
        : "+f"(c[0]), "+f"(c[1]), "+f"(c[2]), "+f"(c[3])
        : "r"(a0), "r"(a1), "r"(a2), "r"(a3), "r"(b0), "r"(b1));
}

// ------------------------- TF32 GEMM, BM=128 BN=64 BK=32, reg-prefetch pipeline ------------
// C[M,N] = A[M,K] @ B[N,K]^T + bias  (mode bit0: relu, bit1: add residual R)
// 256 threads = 8 warps (4m x 2n), warp tile 32x32.
#define SSTR 36
__device__ __forceinline__ void tg128_body(
    const float* __restrict__ A, const float* __restrict__ Bm,
    const float* __restrict__ bias, const float* __restrict__ R,
    float* __restrict__ C, int N, int K, int mode, int r0, int c0)
{
    __shared__ unsigned As[128 * SSTR];
    __shared__ unsigned Bs[64 * SSTR];

    int tid = threadIdx.x;
    int lane = tid & 31, warp = tid >> 5;
    int wm = warp >> 1, wn = warp & 1;
    int g = lane >> 2, tg = lane & 3;

    const float* Ab = A + (size_t)r0 * K;
    const float* Bb = Bm + (size_t)c0 * K;

    float acc[2][4][4];
    #pragma unroll
    for (int mt = 0; mt < 2; mt++)
        #pragma unroll
        for (int nt = 0; nt < 4; nt++)
            #pragma unroll
            for (int e = 0; e < 4; e++) acc[mt][nt][e] = 0.0f;

    auto do_mma = [&]() {
        #pragma unroll
        for (int kc = 0; kc < 4; kc++) {
            int ko = kc * 8;
            unsigned a[2][4], b[4][2];
            #pragma unroll
            for (int mt = 0; mt < 2; mt++) {
                int row = wm * 32 + mt * 16 + g;
                a[mt][0] = As[row * SSTR + ko + tg];
                a[mt][1] = As[(row + 8) * SSTR + ko + tg];
                a[mt][2] = As[row * SSTR + ko + tg + 4];
                a[mt][3] = As[(row + 8) * SSTR + ko + tg + 4];
            }
            #pragma unroll
            for (int nt = 0; nt < 4; nt++) {
                int col = wn * 32 + nt * 8 + g;
                b[nt][0] = Bs[col * SSTR + ko + tg];
                b[nt][1] = Bs[col * SSTR + ko + tg + 4];
            }
            #pragma unroll
            for (int mt = 0; mt < 2; mt++)
                #pragma unroll
                for (int nt = 0; nt < 4; nt++)
                    mma_tf32(acc[mt][nt], a[mt][0], a[mt][1], a[mt][2], a[mt][3],
                             b[nt][0], b[nt][1]);
        }
    };

    if ((K & 31) == 0) {
        // pipelined path (K multiple of 32): prefetch next chunk to regs during MMA
        int nch = K >> 5;
        float4 pa[4], pb[2];
        #pragma unroll
        for (int i = 0; i < 4; i++) {
            int idx = tid + i * 256, r = idx >> 3, c4 = idx & 7;
            pa[i] = *(const float4*)&Ab[(size_t)r * K + c4 * 4];
        }
        #pragma unroll
        for (int i = 0; i < 2; i++) {
            int idx = tid + i * 256, r = idx >> 3, c4 = idx & 7;
            pb[i] = *(const float4*)&Bb[(size_t)r * K + c4 * 4];
        }
        #pragma unroll
        for (int i = 0; i < 4; i++) {
            int idx = tid + i * 256, r = idx >> 3, c4 = idx & 7;
            unsigned* ap = &As[r * SSTR + c4 * 4];
            ap[0] = f2tf(pa[i].x); ap[1] = f2tf(pa[i].y); ap[2] = f2tf(pa[i].z); ap[3] = f2tf(pa[i].w);
        }
        #pragma unroll
        for (int i = 0; i < 2; i++) {
            int idx = tid + i * 256, r = idx >> 3, c4 = idx & 7;
            unsigned* bp = &Bs[r * SSTR + c4 * 4];
            bp[0] = f2tf(pb[i].x); bp[1] = f2tf(pb[i].y); bp[2] = f2tf(pb[i].z); bp[3] = f2tf(pb[i].w);
        }
        __syncthreads();

        for (int ch = 0; ch < nch; ch++) {
            bool more = (ch + 1 < nch);
            if (more) {
                int k1 = (ch + 1) << 5;
                #pragma unroll
                for (int i = 0; i < 4; i++) {
                    int idx = tid + i * 256, r = idx >> 3, c4 = idx & 7;
                    pa[i] = *(const float4*)&Ab[(size_t)r * K + k1 + c4 * 4];
                }
                #pragma unroll
                for (int i = 0; i < 2; i++) {
                    int idx = tid + i * 256, r = idx >> 3, c4 = idx & 7;
                    pb[i] = *(const float4*)&Bb[(size_t)r * K + k1 + c4 * 4];
                }
            }
            do_mma();
            if (more) {
                __syncthreads();   // all reads of this chunk done
                #pragma unroll
                for (int i = 0; i < 4; i++) {
                    int idx = tid + i * 256, r = idx >> 3, c4 = idx & 7;
                    unsigned* ap = &As[r * SSTR + c4 * 4];
                    ap[0] = f2tf(pa[i].x); ap[1] = f2tf(pa[i].y); ap[2] = f2tf(pa[i].z); ap[3] = f2tf(pa[i].w);
                }
                #pragma unroll
                for (int i = 0; i < 2; i++) {
                    int idx = tid + i * 256, r = idx >> 3, c4 = idx & 7;
                    unsigned* bp = &Bs[r * SSTR + c4 * 4];
                    bp[0] = f2tf(pb[i].x); bp[1] = f2tf(pb[i].y); bp[2] = f2tf(pb[i].z); bp[3] = f2tf(pb[i].w);
                }
                __syncthreads();
            }
        }
    } else {
        // guarded scalar path (embed GEMM, K=1799)
        for (int k0 = 0; k0 < K; k0 += 32) {
            #pragma unroll
            for (int i = 0; i < 16; i++) {
                int idx = tid + i * 256, r = idx >> 5, c = idx & 31;
                int kk = k0 + c;
                As[r * SSTR + c] = f2tf((kk < K) ? Ab[(size_t)r * K + kk] : 0.0f);
            }
            #pragma unroll
            for (int i = 0; i < 8; i++) {
                int idx = tid + i * 256, r = idx >> 5, c = idx & 31;
                int kk = k0 + c;
                Bs[r * SSTR + c] = f2tf((kk < K) ? Bb[(size_t)r * K + kk] : 0.0f);
            }
            __syncthreads();
            do_mma();
            __syncthreads();
        }
    }

    #pragma unroll
    for (int mt = 0; mt < 2; mt++) {
        int row = r0 + wm * 32 + mt * 16 + g;
        #pragma unroll
        for (int nt = 0; nt < 4; nt++) {
            int col = c0 + wn * 32 + nt * 8 + 2 * tg;
            float2 bi = *(const float2*)&bias[col];
            #pragma unroll
            for (int half = 0; half < 2; half++) {
                int rr = row + half * 8;
                float x0 = acc[mt][nt][half * 2 + 0] + bi.x;
                float x1 = acc[mt][nt][half * 2 + 1] + bi.y;
                if (mode & 2) {
                    float2 rv = *(const float2*)&R[(size_t)rr * N + col];
                    x0 += rv.x; x1 += rv.y;
                }
                if (mode & 1) { x0 = fmaxf(x0, 0.0f); x1 = fmaxf(x1, 0.0f); }
                float2 o2 = {x0, x1};
                *(float2*)&C[(size_t)rr * N + col] = o2;
            }
        }
    }
}

__global__ __launch_bounds__(256) void tgemm128(
    const float* __restrict__ A, const float* __restrict__ Bm,
    const float* __restrict__ bias, const float* __restrict__ R,
    float* __restrict__ C, int N, int K, int mode)
{
    tg128_body(A, Bm, bias, R, C, N, K, mode, blockIdx.y * 128, blockIdx.x * 64);
}

// batched Q/K/V projection: blockIdx.z selects which of the three
__global__ __launch_bounds__(256) void tgemm128_qkv(
    const float* __restrict__ A,
    const float* __restrict__ Wq, const float* __restrict__ Wk, const float* __restrict__ Wv,
    const float* __restrict__ bq, const float* __restrict__ bk, const float* __restrict__ bv,
    float* __restrict__ q, float* __restrict__ k, float* __restrict__ v)
{
    const float* W; const float* bi; float* C;
    if (blockIdx.z == 0)      { W = Wq; bi = bq; C = q; }
    else if (blockIdx.z == 1) { W = Wk; bi = bk; C = k; }
    else                      { W = Wv; bi = bv; C = v; }
    tg128_body(A, W, bi, nullptr, C, D_, D_, 0, blockIdx.y * 128, blockIdx.x * 64);
}

// ------------------------- scores via tf32 MMA -------------------------
// S[bh,t,s] = scale * ( Q.K^T  +  R[t, t-s+63] ),  R = Q_tile @ PknLocal^T
__global__ __launch_bounds__(128) void scores_mma(
    const float* __restrict__ q, const float* __restrict__ k,
    const float* __restrict__ pkn_l, const int* __restrict__ masks,
    float* __restrict__ att)
{
    __shared__ char sbuf[(64 + 64 + 128) * SSTR * 4];
    unsigned* Qs = (unsigned*)sbuf;
    unsigned* Ks = Qs + 64 * SSTR;
    unsigned* Ps = Ks + 64 * SSTR;
    float*    Rs = (float*)sbuf;

    int tid = threadIdx.x;
    int lane = tid & 31, warp = tid >> 5;
    int wm = warp >> 1, wn = warp & 1;
    int g = lane >> 2, tg = lane & 3;

    int s0 = blockIdx.x * 64, t0 = blockIdx.y * 64, bh = blockIdx.z;
    int b = bh >> 2, h = bh & 3;

    const float* qb = q + ((size_t)(b * T_ + t0)) * D_ + h * DK;
    const float* kb = k + ((size_t)(b * T_ + s0)) * D_ + h * DK;
    const float* pb = pkn_l + (size_t)(t0 - s0 + 448) * DK;

    float accA[2][4][4];
    float accR[2][8][4];
    #pragma unroll
    for (int mt = 0; mt < 2; mt++) {
        #pragma unroll
        for (int nt = 0; nt < 4; nt++)
            #pragma unroll
            for (int e = 0; e < 4; e++) accA[mt][nt][e] = 0.0f;
        #pragma unroll
        for (int nt = 0; nt < 8; nt++)
            #pragma unroll
            for (int e = 0; e < 4; e++) accR[mt][nt][e] = 0.0f;
    }

    for (int dt = 0; dt < 2; dt++) {
        int d0 = dt * 32;
        #pragma unroll
        for (int i = 0; i < 4; i++) {
            int idx = tid + i * 128;
            int r = idx >> 3, c4 = idx & 7;
            float4 qv = *(const float4*)&qb[(size_t)r * D_ + d0 + c4 * 4];
            float4 kv = *(const float4*)&kb[(size_t)r * D_ + d0 + c4 * 4];
            unsigned* qp = &Qs[r * SSTR + c4 * 4];
            unsigned* kp = &Ks[r * SSTR + c4 * 4];
            qp[0] = f2tf(qv.x); qp[1] = f2tf(qv.y); qp[2] = f2tf(qv.z); qp[3] = f2tf(qv.w);
            kp[0] = f2tf(kv.x); kp[1] = f2tf(kv.y); kp[2] = f2tf(kv.z); kp[3] = f2tf(kv.w);
        }
        #pragma unroll
        for (int i = 0; i < 8; i++) {
            int idx = tid + i * 128;
            int r = idx >> 3, c4 = idx & 7;
            unsigned* pp = &Ps[r * SSTR + c4 * 4];
            if (r < 127) {
                float4 pv = *(const float4*)&pb[(size_t)r * DK + d0 + c4 * 4];
                pp[0] = f2tf(pv.x); pp[1] = f2tf(pv.y); pp[2] = f2tf(pv.z); pp[3] = f2tf(pv.w);
            } else {
                pp[0] = 0u; pp[1] = 0u; pp[2] = 0u; pp[3] = 0u;
            }
        }
        __syncthreads();

        #pragma unroll
        for (int kc = 0; kc < 4; kc++) {
            int ko = kc * 8;
            unsigned a[2][4];
            #pragma unroll
            for (int mt = 0; mt < 2; mt++) {
                int row = wm * 32 + mt * 16 + g;
                a[mt][0] = Qs[row * SSTR + ko + tg];
                a[mt][1] = Qs[(row + 8) * SSTR + ko + tg];
                a[mt][2] = Qs[row * SSTR + ko + tg + 4];
                a[mt][3] = Qs[(row + 8) * SSTR + ko + tg + 4];
            }
            #pragma unroll
            for (int nt = 0; nt < 4; nt++) {
                int col = wn * 32 + nt * 8 + g;
                unsigned b0 = Ks[col * SSTR + ko + tg];
                unsigned b1 = Ks[col * SSTR + ko + tg + 4];
                #pragma unroll
                for (int mt = 0; mt < 2; mt++)
                    mma_tf32(accA[mt][nt], a[mt][0], a[mt][1], a[mt][2], a[mt][3], b0, b1);
            }
            #pragma unroll
            for (int nt = 0; nt < 8; nt++) {
                int col = wn * 64 + nt * 8 + g;
                unsigned b0 = Ps[col * SSTR + ko + tg];
                unsigned b1 = Ps[col * SSTR + ko + tg + 4];
                #pragma unroll
                for (int mt = 0; mt < 2; mt++)
                    mma_tf32(accR[mt][nt], a[mt][0], a[mt][1], a[mt][2], a[mt][3], b0, b1);
            }
        }
        __syncthreads();
    }

    #pragma unroll
    for (int mt = 0; mt < 2; mt++) {
        int row = wm * 32 + mt * 16 + g;
        #pragma unroll
        for (int nt = 0; nt < 8; nt++) {
            int col = wn * 64 + nt * 8 + 2 * tg;
            Rs[row * 132 + col]       = accR[mt][nt][0];
            Rs[row * 132 + col + 1]   = accR[mt][nt][1];
            Rs[(row + 8) * 132 + col]     = accR[mt][nt][2];
            Rs[(row + 8) * 132 + col + 1] = accR[mt][nt][3];
        }
    }
    __syncthreads();

    const float scale = 0.125f;
    float* ob = att + ((size_t)bh * T_ + t0) * T_ + s0;
    #pragma unroll
    for (int mt = 0; mt < 2; mt++) {
        int rbase = wm * 32 + mt * 16 + g;
        #pragma unroll
        for (int nt = 0; nt < 4; nt++) {
            int cbase = wn * 32 + nt * 8 + 2 * tg;
            #pragma unroll
            for (int half = 0; half < 2; half++) {
                int rl = rbase + half * 8;
                #pragma unroll
                for (int e = 0; e < 2; e++) {
                    int cl = cbase + e;
                    float vv = (accA[mt][nt][half * 2 + e] + Rs[rl * 132 + (rl - cl + 63)]) * scale;
                    if (masks[b * T_ + s0 + cl] == 0) vv = -FLT_MAX;
                    ob[(size_t)rl * T_ + cl] = vv;
                }
            }
        }
    }
}

// ------------------------- fused online-softmax + P@V -------------------------
#define PSTR 33
#define VSTR 37
__global__ __launch_bounds__(128) void attnv_fused(const float* __restrict__ att,
                                                   const float* __restrict__ v,
                                                   float* __restrict__ o) {
    __shared__ float    Ss[64 * PSTR];
    __shared__ unsigned Bs[64 * VSTR];

    int tid = threadIdx.x;
    int lane = tid & 31, warp = tid >> 5;
    int g = lane >> 2, tg = lane & 3;

    int t0 = blockIdx.x * 64, bh = blockIdx.y;
    int b = bh >> 2, h = bh & 3;
    const float* ab = att + ((size_t)bh * T_ + t0) * T_;
    const float* vb = v + ((size_t)(b * T_)) * D_ + h * DK;

    float accO[8][4];
    #pragma unroll
    for (int nt = 0; nt < 8; nt++)
        #pragma unroll
        for (int e = 0; e < 4; e++) accO[nt][e] = 0.0f;

    float m0 = -FLT_MAX, m1 = -FLT_MAX;
    float l0 = 0.0f, l1 = 0.0f;

    for (int sc = 0; sc < 16; sc++) {
        int s0c = sc * 32;
        #pragma unroll
        for (int i = 0; i < 4; i++) {
            int idx = tid + i * 128;
            int r = idx >> 3, c4 = idx & 7;
            float4 sv = *(const float4*)&ab[(size_t)r * T_ + s0c + c4 * 4];
            float* sp = &Ss[r * PSTR + c4 * 4];
            sp[0] = sv.x; sp[1] = sv.y; sp[2] = sv.z; sp[3] = sv.w;
        }
        #pragma unroll
        for (int i = 0; i < 4; i++) {
            int idx = tid + i * 128;
            int r = idx >> 4, c4 = idx & 15;
            float4 vv = *(const float4*)&vb[(size_t)(s0c + r) * D_ + c4 * 4];
            Bs[(c4 * 4 + 0) * VSTR + r] = f2tf(vv.x);
            Bs[(c4 * 4 + 1) * VSTR + r] = f2tf(vv.y);
            Bs[(c4 * 4 + 2) * VSTR + r] = f2tf(vv.z);
            Bs[(c4 * 4 + 3) * VSTR + r] = f2tf(vv.w);
        }
        __syncthreads();

        int rl0 = warp * 16 + g, rl1 = rl0 + 8;
        float s0v[8], s1v[8];
        #pragma unroll
        for (int kc = 0; kc < 4; kc++) {
            #pragma unroll
            for (int h4 = 0; h4 < 2; h4++) {
                int col = kc * 8 + h4 * 4 + tg;
                s0v[kc * 2 + h4] = Ss[rl0 * PSTR + col];
                s1v[kc * 2 + h4] = Ss[rl1 * PSTR + col];
            }
        }
        float cm0 = s0v[0], cm1 = s1v[0];
        #pragma unroll
        for (int j = 1; j < 8; j++) { cm0 = fmaxf(cm0, s0v[j]); cm1 = fmaxf(cm1, s1v[j]); }
        cm0 = fmaxf(cm0, __shfl_xor_sync(0xffffffffu, cm0, 1));
        cm0 = fmaxf(cm0, __shfl_xor_sync(0xffffffffu, cm0, 2));
        cm1 = fmaxf(cm1, __shfl_xor_sync(0xffffffffu, cm1, 1));
        cm1 = fmaxf(cm1, __shfl_xor_sync(0xffffffffu, cm1, 2));

        float nm0 = fmaxf(m0, cm0), nm1 = fmaxf(m1, cm1);
        float al0 = __expf(m0 - nm0), al1 = __expf(m1 - nm1);
        float cs0 = 0.0f, cs1 = 0.0f;
        float p0[8], p1[8];
        #pragma unroll
        for (int j = 0; j < 8; j++) {
            p0[j] = __expf(s0v[j] - nm0);
            p1[j] = __expf(s1v[j] - nm1);
            cs0 += p0[j]; cs1 += p1[j];
        }
        cs0 += __shfl_xor_sync(0xffffffffu, cs0, 1);
        cs0 += __shfl_xor_sync(0xffffffffu, cs0, 2);
        cs1 += __shfl_xor_sync(0xffffffffu, cs1, 1);
        cs1 += __shfl_xor_sync(0xffffffffu, cs1, 2);
        l0 = l0 * al0 + cs0;
        l1 = l1 * al1 + cs1;
        m0 = nm0; m1 = nm1;

        #pragma unroll
        for (int nt = 0; nt < 8; nt++) {
            accO[nt][0] *= al0; accO[nt][1] *= al0;
            accO[nt][2] *= al1; accO[nt][3] *= al1;
        }

        #pragma unroll
        for (int kc = 0; kc < 4; kc++) {
            int ko = kc * 8;
            unsigned a0 = f2tf(p0[kc * 2 + 0]);
            unsigned a1 = f2tf(p1[kc * 2 + 0]);
            unsigned a2 = f2tf(p0[kc * 2 + 1]);
            unsigned a3 = f2tf(p1[kc * 2 + 1]);
            #pragma unroll
            for (int nt = 0; nt < 8; nt++) {
                int col = nt * 8 + g;
                unsigned b0 = Bs[col * VSTR + ko + tg];
                unsigned b1 = Bs[col * VSTR + ko + tg + 4];
                mma_tf32(accO[nt], a0, a1, a2, a3, b0, b1);
            }
        }
        __syncthreads();
    }

    float inv0 = 1.0f / l0, inv1 = 1.0f / l1;
    int row0 = warp * 16 + g;
    #pragma unroll
    for (int nt = 0; nt < 8; nt++) {
        int col = nt * 8 + 2 * tg;
        float2 oa = {accO[nt][0] * inv0, accO[nt][1] * inv0};
        float2 ob2 = {accO[nt][2] * inv1, accO[nt][3] * inv1};
        *(float2*)&o[((size_t)(b * T_ + t0 + row0)) * D_ + h * DK + col] = oa;
        *(float2*)&o[((size_t)(b * T_ + t0 + row0 + 8)) * D_ + h * DK + col] = ob2;
    }
}

// ------------------------- host orchestration -------------------------
extern "C" void kernel_launch(void* const* d_in, const int* in_sizes, int n_in,
                              void* d_out, int out_size) {
    const float* xs      = (const float*)d_in[0];
    const int*   masks   = (const int*)  d_in[1];
    const float* emb_w   = (const float*)d_in[2];
    const float* emb_b   = (const float*)d_in[3];
    const float* emb_g   = (const float*)d_in[4];
    const float* emb_bt  = (const float*)d_in[5];
    const float* pe_k    = (const float*)d_in[6];
    const float* Wq      = (const float*)d_in[7];
    const float* bq      = (const float*)d_in[8];
    const float* Wk      = (const float*)d_in[9];
    const float* bk      = (const float*)d_in[10];
    const float* Wv      = (const float*)d_in[11];
    const float* bv      = (const float*)d_in[12];
    const float* Wo      = (const float*)d_in[13];
    const float* bo      = (const float*)d_in[14];
    const float* ln1_g   = (const float*)d_in[15];
    const float* ln1_b   = (const float*)d_in[16];
    const float* ln2_g   = (const float*)d_in[17];
    const float* ln2_b   = (const float*)d_in[18];
    const float* lnk_g   = (const float*)d_in[19];
    const float* lnk_b   = (const float*)d_in[20];
    const float* W1      = (const float*)d_in[21];
    const float* b1      = (const float*)d_in[22];
    const float* W2      = (const float*)d_in[23];
    const float* b2      = (const float*)d_in[24];
    const float* after_g = (const float*)d_in[25];
    const float* after_b = (const float*)d_in[26];
    float* out = (float*)d_out;

    float *x, *y, *q, *k, *v, *o, *ff, *att, *pkn;
    cudaGetSymbolAddress((void**)&x,   g_x);
    cudaGetSymbolAddress((void**)&y,   g_y);
    cudaGetSymbolAddress((void**)&q,   g_q);
    cudaGetSymbolAddress((void**)&k,   g_k);
    cudaGetSymbolAddress((void**)&v,   g_v);
    cudaGetSymbolAddress((void**)&o,   g_o);
    cudaGetSymbolAddress((void**)&ff,  g_ff);
    cudaGetSymbolAddress((void**)&att, g_att);
    cudaGetSymbolAddress((void**)&pkn, g_pkn);

    dim3 gProj(D_ / 64, BT / 128);       // (4, 32)
    dim3 gQKV(D_ / 64, BT / 128, 3);     // (4, 32, 3)
    dim3 gFF1(FF_ / 64, BT / 128);       // (32, 32)

    // embed: GEMM + bias -> LN -> ReLU; pkn LN for all layers upfront
    tgemm128<<<gProj, 256>>>(xs, emb_w, emb_b, nullptr, y, D_, IDIM, 0);
    ln_pkn_all<<<dim3(NPK, L_), 64>>>(pe_k, pkn, lnk_g, lnk_b);
    ln_warp<<<BT / 8, 256>>>(y, x, emb_g, emb_bt, 1);

    for (int l = 0; l < L_; l++) {
        ln_warp<<<BT / 8, 256>>>(x, y, ln1_g + l * D_, ln1_b + l * D_, 0);

        tgemm128_qkv<<<gQKV, 256>>>(y,
            Wq + (size_t)l * D_ * D_, Wk + (size_t)l * D_ * D_, Wv + (size_t)l * D_ * D_,
            bq + l * D_, bk + l * D_, bv + l * D_, q, k, v);

        scores_mma<<<dim3(8, 8, BH), 128>>>(q, k, pkn + (size_t)l * NPK * DK, masks, att);
        attnv_fused<<<dim3(8, BH), 128>>>(att, v, o);

        tgemm128<<<gProj, 256>>>(o, Wo + (size_t)l * D_ * D_, bo + l * D_, x, x, D_, D_, 2);

        ln_warp<<<BT / 8, 256>>>(x, y, ln2_g + l * D_, ln2_b + l * D_, 0);
        tgemm128<<<gFF1, 256>>>(y, W1 + (size_t)l * FF_ * D_, b1 + l * FF_, nullptr, ff, FF_, D_, 1);
        tgemm128<<<gProj, 256>>>(ff, W2 + (size_t)l * D_ * FF_, b2 + l * D_, x, x, D_, FF_, 2);
    }

    ln_warp<<<BT / 8, 256>>>(x, out, after_g, after_b, 0);
}

// round 10
// speedup vs baseline: 2.6291x; 1.1016x over previous
#include <cuda_runtime.h>
#include <math.h>
#include <float.h>

// Problem constants
#define B_    8
#define T_    512
#define IDIM  1799
#define D_    256
#define H_    4
#define FF_   2048
#define L_    16
#define DK    64
#define BT    (B_*T_)    // 4096
#define BH    (B_*H_)    // 32
#define NPK   1023       // distinct rel-pos rows: t-s+511 in [0,1022]

// ------------------------- scratch (device globals) -------------------------
__device__ float g_x[BT*D_];
__device__ float g_y[BT*D_];
__device__ float g_q[BT*D_];
__device__ float g_k[BT*D_];
__device__ float g_v[BT*D_];
__device__ float g_o[BT*D_];
__device__ float g_ff[BT*FF_];
__device__ float g_pkn[(size_t)L_*NPK*DK];  // all layers, 4.2 MB

// ------------------------- block reduction (for pkn LN only) -------------------------
__device__ __forceinline__ float block_sum64(float v) {
    __shared__ float sh[3];
    #pragma unroll
    for (int o = 16; o > 0; o >>= 1) v += __shfl_xor_sync(0xffffffffu, v, o);
    int lane = threadIdx.x & 31, w = threadIdx.x >> 5;
    if (lane == 0) sh[w] = v;
    __syncthreads();
    float out = sh[0] + sh[1];
    __syncthreads();
    return out;
}

// all-layers pkn LN: grid (NPK, L), block 64
__global__ void ln_pkn_all(const float* __restrict__ pe_k, float* __restrict__ pkn,
                           const float* __restrict__ lnk_g, const float* __restrict__ lnk_b) {
    int row = blockIdx.x, l = blockIdx.y;
    float x = pe_k[(size_t)(489 + row) * DK + threadIdx.x];
    float mean = block_sum64(x) / (float)DK;
    float d = x - mean;
    float var = block_sum64(d * d) / (float)DK;
    float y = d * rsqrtf(var + 1e-12f) * lnk_g[l * DK + threadIdx.x] + lnk_b[l * DK + threadIdx.x];
    pkn[((size_t)l * NPK + row) * DK + threadIdx.x] = y;
}

// ------------------------- warp-per-row LayerNorm, width 256 -------------------------
__global__ __launch_bounds__(256) void ln_warp(const float* __restrict__ in,
                                               float* __restrict__ out,
                                               const float* __restrict__ g,
                                               const float* __restrict__ bb,
                                               int relu) {
    int warp = threadIdx.x >> 5, lane = threadIdx.x & 31;
    size_t row = (size_t)blockIdx.x * 8 + warp;
    const float* ip = in + row * D_;
    float4 v0 = *(const float4*)&ip[lane * 4];
    float4 v1 = *(const float4*)&ip[128 + lane * 4];
    float s = v0.x + v0.y + v0.z + v0.w + v1.x + v1.y + v1.z + v1.w;
    #pragma unroll
    for (int o = 16; o > 0; o >>= 1) s += __shfl_xor_sync(0xffffffffu, s, o);
    float mean = s * (1.0f / 256.0f);
    float d0x = v0.x - mean, d0y = v0.y - mean, d0z = v0.z - mean, d0w = v0.w - mean;
    float d1x = v1.x - mean, d1y = v1.y - mean, d1z = v1.z - mean, d1w = v1.w - mean;
    float vs = d0x*d0x + d0y*d0y + d0z*d0z + d0w*d0w + d1x*d1x + d1y*d1y + d1z*d1z + d1w*d1w;
    #pragma unroll
    for (int o = 16; o > 0; o >>= 1) vs += __shfl_xor_sync(0xffffffffu, vs, o);
    float rstd = rsqrtf(vs * (1.0f / 256.0f) + 1e-12f);
    float4 g0 = *(const float4*)&g[lane * 4];
    float4 g1 = *(const float4*)&g[128 + lane * 4];
    float4 b0 = *(const float4*)&bb[lane * 4];
    float4 b1 = *(const float4*)&bb[128 + lane * 4];
    float4 o0, o1;
    o0.x = d0x * rstd * g0.x + b0.x;  o0.y = d0y * rstd * g0.y + b0.y;
    o0.z = d0z * rstd * g0.z + b0.z;  o0.w = d0w * rstd * g0.w + b0.w;
    o1.x = d1x * rstd * g1.x + b1.x;  o1.y = d1y * rstd * g1.y + b1.y;
    o1.z = d1z * rstd * g1.z + b1.z;  o1.w = d1w * rstd * g1.w + b1.w;
    if (relu) {
        o0.x = fmaxf(o0.x, 0.f); o0.y = fmaxf(o0.y, 0.f); o0.z = fmaxf(o0.z, 0.f); o0.w = fmaxf(o0.w, 0.f);
        o1.x = fmaxf(o1.x, 0.f); o1.y = fmaxf(o1.y, 0.f); o1.z = fmaxf(o1.z, 0.f); o1.w = fmaxf(o1.w, 0.f);
    }
    float* op = out + row * D_;
    *(float4*)&op[lane * 4] = o0;
    *(float4*)&op[128 + lane * 4] = o1;
}

// ------------------------- tf32 helpers -------------------------
__device__ __forceinline__ unsigned f2tf(float f) {
    unsigned r;
    asm("cvt.rna.tf32.f32 %0, %1;" : "=r"(r) : "f"(f));
    return r;
}

__device__ __forceinline__ void mma_tf32(float c[4],
                                         unsigned a0, unsigned a1, unsigned a2, unsigned a3,
                                         unsigned b0, unsigned b1) {
    asm volatile(
        "mma.sync.aligned.m16n8k8.row.col.f32.tf32.tf32.f32 "
        "{%0,%1,%2,%3}, {%4,%5,%6,%7}, {%8,%9}, {%0,%1,%2,%3};"
        : "+f"(c[0]), "+f"(c[1]), "+f"(c[2]), "+f"(c[3])
        : "r"(a0), "r"(a1), "r"(a2), "r"(a3), "r"(b0), "r"(b1));
}

// ------------------------- TF32 GEMM, BM=128 BN=64 BK=32, reg-prefetch pipeline ------------
#define SSTR 36
__device__ __forceinline__ void tg128_body(
    const float* __restrict__ A, const float* __restrict__ Bm,
    const float* __restrict__ bias, const float* __restrict__ R,
    float* __restrict__ C, int N, int K, int mode, int r0, int c0)
{
    __shared__ unsigned As[128 * SSTR];
    __shared__ unsigned Bs[64 * SSTR];

    int tid = threadIdx.x;
    int lane = tid & 31, warp = tid >> 5;
    int wm = warp >> 1, wn = warp & 1;
    int g = lane >> 2, tg = lane & 3;

    const float* Ab = A + (size_t)r0 * K;
    const float* Bb = Bm + (size_t)c0 * K;

    float acc[2][4][4];
    #pragma unroll
    for (int mt = 0; mt < 2; mt++)
        #pragma unroll
        for (int nt = 0; nt < 4; nt++)
            #pragma unroll
            for (int e = 0; e < 4; e++) acc[mt][nt][e] = 0.0f;

    auto do_mma = [&]() {
        #pragma unroll
        for (int kc = 0; kc < 4; kc++) {
            int ko = kc * 8;
            unsigned a[2][4], b[4][2];
            #pragma unroll
            for (int mt = 0; mt < 2; mt++) {
                int row = wm * 32 + mt * 16 + g;
                a[mt][0] = As[row * SSTR + ko + tg];
                a[mt][1] = As[(row + 8) * SSTR + ko + tg];
                a[mt][2] = As[row * SSTR + ko + tg + 4];
                a[mt][3] = As[(row + 8) * SSTR + ko + tg + 4];
            }
            #pragma unroll
            for (int nt = 0; nt < 4; nt++) {
                int col = wn * 32 + nt * 8 + g;
                b[nt][0] = Bs[col * SSTR + ko + tg];
                b[nt][1] = Bs[col * SSTR + ko + tg + 4];
            }
            #pragma unroll
            for (int mt = 0; mt < 2; mt++)
                #pragma unroll
                for (int nt = 0; nt < 4; nt++)
                    mma_tf32(acc[mt][nt], a[mt][0], a[mt][1], a[mt][2], a[mt][3],
                             b[nt][0], b[nt][1]);
        }
    };

    if ((K & 31) == 0) {
        int nch = K >> 5;
        float4 pa[4], pb[2];
        #pragma unroll
        for (int i = 0; i < 4; i++) {
            int idx = tid + i * 256, r = idx >> 3, c4 = idx & 7;
            pa[i] = *(const float4*)&Ab[(size_t)r * K + c4 * 4];
        }
        #pragma unroll
        for (int i = 0; i < 2; i++) {
            int idx = tid + i * 256, r = idx >> 3, c4 = idx & 7;
            pb[i] = *(const float4*)&Bb[(size_t)r * K + c4 * 4];
        }
        #pragma unroll
        for (int i = 0; i < 4; i++) {
            int idx = tid + i * 256, r = idx >> 3, c4 = idx & 7;
            unsigned* ap = &As[r * SSTR + c4 * 4];
            ap[0] = f2tf(pa[i].x); ap[1] = f2tf(pa[i].y); ap[2] = f2tf(pa[i].z); ap[3] = f2tf(pa[i].w);
        }
        #pragma unroll
        for (int i = 0; i < 2; i++) {
            int idx = tid + i * 256, r = idx >> 3, c4 = idx & 7;
            unsigned* bp = &Bs[r * SSTR + c4 * 4];
            bp[0] = f2tf(pb[i].x); bp[1] = f2tf(pb[i].y); bp[2] = f2tf(pb[i].z); bp[3] = f2tf(pb[i].w);
        }
        __syncthreads();

        for (int ch = 0; ch < nch; ch++) {
            bool more = (ch + 1 < nch);
            if (more) {
                int k1 = (ch + 1) << 5;
                #pragma unroll
                for (int i = 0; i < 4; i++) {
                    int idx = tid + i * 256, r = idx >> 3, c4 = idx & 7;
                    pa[i] = *(const float4*)&Ab[(size_t)r * K + k1 + c4 * 4];
                }
                #pragma unroll
                for (int i = 0; i < 2; i++) {
                    int idx = tid + i * 256, r = idx >> 3, c4 = idx & 7;
                    pb[i] = *(const float4*)&Bb[(size_t)r * K + k1 + c4 * 4];
                }
            }
            do_mma();
            if (more) {
                __syncthreads();
                #pragma unroll
                for (int i = 0; i < 4; i++) {
                    int idx = tid + i * 256, r = idx >> 3, c4 = idx & 7;
                    unsigned* ap = &As[r * SSTR + c4 * 4];
                    ap[0] = f2tf(pa[i].x); ap[1] = f2tf(pa[i].y); ap[2] = f2tf(pa[i].z); ap[3] = f2tf(pa[i].w);
                }
                #pragma unroll
                for (int i = 0; i < 2; i++) {
                    int idx = tid + i * 256, r = idx >> 3, c4 = idx & 7;
                    unsigned* bp = &Bs[r * SSTR + c4 * 4];
                    bp[0] = f2tf(pb[i].x); bp[1] = f2tf(pb[i].y); bp[2] = f2tf(pb[i].z); bp[3] = f2tf(pb[i].w);
                }
                __syncthreads();
            }
        }
    } else {
        for (int k0 = 0; k0 < K; k0 += 32) {
            #pragma unroll
            for (int i = 0; i < 16; i++) {
                int idx = tid + i * 256, r = idx >> 5, c = idx & 31;
                int kk = k0 + c;
                As[r * SSTR + c] = f2tf((kk < K) ? Ab[(size_t)r * K + kk] : 0.0f);
            }
            #pragma unroll
            for (int i = 0; i < 8; i++) {
                int idx = tid + i * 256, r = idx >> 5, c = idx & 31;
                int kk = k0 + c;
                Bs[r * SSTR + c] = f2tf((kk < K) ? Bb[(size_t)r * K + kk] : 0.0f);
            }
            __syncthreads();
            do_mma();
            __syncthreads();
        }
    }

    #pragma unroll
    for (int mt = 0; mt < 2; mt++) {
        int row = r0 + wm * 32 + mt * 16 + g;
        #pragma unroll
        for (int nt = 0; nt < 4; nt++) {
            int col = c0 + wn * 32 + nt * 8 + 2 * tg;
            float2 bi = *(const float2*)&bias[col];
            #pragma unroll
            for (int half = 0; half < 2; half++) {
                int rr = row + half * 8;
                float x0 = acc[mt][nt][half * 2 + 0] + bi.x;
                float x1 = acc[mt][nt][half * 2 + 1] + bi.y;
                if (mode & 2) {
                    float2 rv = *(const float2*)&R[(size_t)rr * N + col];
                    x0 += rv.x; x1 += rv.y;
                }
                if (mode & 1) { x0 = fmaxf(x0, 0.0f); x1 = fmaxf(x1, 0.0f); }
                float2 o2 = {x0, x1};
                *(float2*)&C[(size_t)rr * N + col] = o2;
            }
        }
    }
}

__global__ __launch_bounds__(256) void tgemm128(
    const float* __restrict__ A, const float* __restrict__ Bm,
    const float* __restrict__ bias, const float* __restrict__ R,
    float* __restrict__ C, int N, int K, int mode)
{
    tg128_body(A, Bm, bias, R, C, N, K, mode, blockIdx.y * 128, blockIdx.x * 64);
}

__global__ __launch_bounds__(256) void tgemm128_qkv(
    const float* __restrict__ A,
    const float* __restrict__ Wq, const float* __restrict__ Wk, const float* __restrict__ Wv,
    const float* __restrict__ bq, const float* __restrict__ bk, const float* __restrict__ bv,
    float* __restrict__ q, float* __restrict__ k, float* __restrict__ v)
{
    const float* W; const float* bi; float* C;
    if (blockIdx.z == 0)      { W = Wq; bi = bq; C = q; }
    else if (blockIdx.z == 1) { W = Wk; bi = bk; C = k; }
    else                      { W = Wv; bi = bv; C = v; }
    tg128_body(A, W, bi, nullptr, C, D_, D_, 0, blockIdx.y * 128, blockIdx.x * 64);
}

// ------------------------- fully fused flash attention -------------------------
// One block per (64-row t-tile, bh). 128 threads = 4 warps, warp w owns t-rows
// w*16..w*16+15. Loops over 8 s-chunks of 64: S = Q.K^T (MMA) + rel-pos R (MMA +
// diagonal gather), online softmax, O += P.V (MMA). No gmem intermediate.
// DYNAMIC smem (73216 B):
//   Vs [0, 18944)      : two panes of 64 d-rows x VSTR=37 (32 s-cols each)
//   Ks [18944, 36352)  : 64 rows x KSTR=68
//   Ps [36352, 71168)  : 128 rows x KSTR=68
//   Rs/Ru alias [18944, 52736) : 64 rows x 132 floats (over Ks + part of Ps)
//   msk [71168, 73216)
#define KSTR 68
#define VSTR 37
#define VPANE 2368   // words per V half-pane (64*37)
#define FLASH_SMEM 73216
__global__ __launch_bounds__(128) void flash_attn(
    const float* __restrict__ q, const float* __restrict__ k,
    const float* __restrict__ v, const float* __restrict__ pkn_l,
    const int* __restrict__ masks, float* __restrict__ o)
{
    extern __shared__ char sbuf[];
    unsigned* Vs = (unsigned*)sbuf;
    unsigned* Ks = (unsigned*)(sbuf + 18944);
    unsigned* Ps = (unsigned*)(sbuf + 36352);
    float*    Rs = (float*)(sbuf + 18944);
    unsigned* Ru = (unsigned*)(sbuf + 18944);
    int*      msk = (int*)(sbuf + 71168);

    int tid = threadIdx.x;
    int lane = tid & 31, warp = tid >> 5;
    int g = lane >> 2, tg = lane & 3;
    int rl0 = warp * 16 + g, rl1 = rl0 + 8;

    int t0 = blockIdx.x * 64, bh = blockIdx.y;
    int b = bh >> 2, h = bh & 3;
    const float* qb  = q + ((size_t)(b * T_ + t0)) * D_ + h * DK;
    const float* kb0 = k + ((size_t)(b * T_)) * D_ + h * DK;
    const float* vb0 = v + ((size_t)(b * T_)) * D_ + h * DK;

    // stage masks + Q (Q uses Ks region transiently)
    #pragma unroll
    for (int i = 0; i < 4; i++) msk[tid + i * 128] = masks[b * T_ + tid + i * 128];
    #pragma unroll
    for (int i = 0; i < 8; i++) {
        int idx = tid + i * 128, r = idx >> 4, c4 = idx & 15;
        float4 qv = *(const float4*)&qb[(size_t)r * D_ + c4 * 4];
        unsigned* p = &Ks[r * KSTR + c4 * 4];
        p[0] = f2tf(qv.x); p[1] = f2tf(qv.y); p[2] = f2tf(qv.z); p[3] = f2tf(qv.w);
    }
    __syncthreads();
    unsigned qa[8][4];
    #pragma unroll
    for (int kc = 0; kc < 8; kc++) {
        qa[kc][0] = Ks[rl0 * KSTR + kc * 8 + tg];
        qa[kc][1] = Ks[rl1 * KSTR + kc * 8 + tg];
        qa[kc][2] = Ks[rl0 * KSTR + kc * 8 + tg + 4];
        qa[kc][3] = Ks[rl1 * KSTR + kc * 8 + tg + 4];
    }
    __syncthreads();

    float accO[8][4];
    #pragma unroll
    for (int nt = 0; nt < 8; nt++)
        #pragma unroll
        for (int e = 0; e < 4; e++) accO[nt][e] = 0.0f;
    float m0 = -FLT_MAX, m1 = -FLT_MAX, l0 = 0.0f, l1 = 0.0f;

    const float scale = 0.125f;

    for (int sc = 0; sc < 8; sc++) {
        int s0 = sc * 64;
        // ---- stage K ----
        #pragma unroll
        for (int i = 0; i < 8; i++) {
            int idx = tid + i * 128, r = idx >> 4, c4 = idx & 15;
            float4 kv = *(const float4*)&kb0[(size_t)(s0 + r) * D_ + c4 * 4];
            unsigned* p = &Ks[r * KSTR + c4 * 4];
            p[0] = f2tf(kv.x); p[1] = f2tf(kv.y); p[2] = f2tf(kv.z); p[3] = f2tf(kv.w);
        }
        // ---- stage V transposed into two 32-wide panes (proven R5 pattern) ----
        #pragma unroll
        for (int i = 0; i < 8; i++) {
            int idx = tid + i * 128, r = idx >> 4, c4 = idx & 15;
            int half = r >> 5, rs = r & 31;
            unsigned* vp = &Vs[half * VPANE];
            float4 vv = *(const float4*)&vb0[(size_t)(s0 + r) * D_ + c4 * 4];
            vp[(c4 * 4 + 0) * VSTR + rs] = f2tf(vv.x);
            vp[(c4 * 4 + 1) * VSTR + rs] = f2tf(vv.y);
            vp[(c4 * 4 + 2) * VSTR + rs] = f2tf(vv.z);
            vp[(c4 * 4 + 3) * VSTR + rs] = f2tf(vv.w);
        }
        // ---- stage P (127 diagonal rows + 1 zero row) ----
        const float* pb = pkn_l + (size_t)(t0 - s0 + 448) * DK;
        #pragma unroll
        for (int i = 0; i < 16; i++) {
            int idx = tid + i * 128, r = idx >> 4, c4 = idx & 15;
            unsigned* p = &Ps[r * KSTR + c4 * 4];
            if (r < 127) {
                float4 pv = *(const float4*)&pb[(size_t)r * DK + c4 * 4];
                p[0] = f2tf(pv.x); p[1] = f2tf(pv.y); p[2] = f2tf(pv.z); p[3] = f2tf(pv.w);
            } else {
                p[0] = 0u; p[1] = 0u; p[2] = 0u; p[3] = 0u;
            }
        }
        __syncthreads();

        // ---- S and R MMAs ----
        float accS[8][4], accR[16][4];
        #pragma unroll
        for (int nt = 0; nt < 8; nt++)
            #pragma unroll
            for (int e = 0; e < 4; e++) accS[nt][e] = 0.0f;
        #pragma unroll
        for (int nt = 0; nt < 16; nt++)
            #pragma unroll
            for (int e = 0; e < 4; e++) accR[nt][e] = 0.0f;

        #pragma unroll
        for (int kc = 0; kc < 8; kc++) {
            int ko = kc * 8;
            #pragma unroll
            for (int nt = 0; nt < 8; nt++) {
                int col = nt * 8 + g;
                unsigned b0 = Ks[col * KSTR + ko + tg];
                unsigned b1 = Ks[col * KSTR + ko + tg + 4];
                mma_tf32(accS[nt], qa[kc][0], qa[kc][1], qa[kc][2], qa[kc][3], b0, b1);
            }
            #pragma unroll
            for (int nt = 0; nt < 16; nt++) {
                int col = nt * 8 + g;
                unsigned b0 = Ps[col * KSTR + ko + tg];
                unsigned b1 = Ps[col * KSTR + ko + tg + 4];
                mma_tf32(accR[nt], qa[kc][0], qa[kc][1], qa[kc][2], qa[kc][3], b0, b1);
            }
        }
        __syncthreads();   // Ks/Ps reads complete in all warps before Rs overwrite

        // ---- spill R (warp-private rows; stride 132 conflict-free) ----
        #pragma unroll
        for (int nt = 0; nt < 16; nt++) {
            int col = nt * 8 + 2 * tg;
            Rs[rl0 * 132 + col]     = accR[nt][0];
            Rs[rl0 * 132 + col + 1] = accR[nt][1];
            Rs[rl1 * 132 + col]     = accR[nt][2];
            Rs[rl1 * 132 + col + 1] = accR[nt][3];
        }
        __syncwarp();   // cross-lane visibility + compiler barrier

        // ---- gather diagonals, scale + mask -> accS holds final scores ----
        #pragma unroll
        for (int nt = 0; nt < 8; nt++) {
            #pragma unroll
            for (int e = 0; e < 2; e++) {
                int c = nt * 8 + 2 * tg + e;
                float r0 = Rs[rl0 * 132 + (rl0 - c + 63)];
                float r1 = Rs[rl1 * 132 + (rl1 - c + 63)];
                float x0 = (accS[nt][e] + r0) * scale;
                float x1 = (accS[nt][2 + e] + r1) * scale;
                if (msk[s0 + c] == 0) { x0 = -FLT_MAX; x1 = -FLT_MAX; }
                accS[nt][e] = x0;
                accS[nt][2 + e] = x1;
            }
        }
        __syncwarp();   // all gather loads done before prob stores clobber pane

        // ---- online softmax (quad-local) ----
        float cm0 = -FLT_MAX, cm1 = -FLT_MAX;
        #pragma unroll
        for (int nt = 0; nt < 8; nt++) {
            cm0 = fmaxf(cm0, fmaxf(accS[nt][0], accS[nt][1]));
            cm1 = fmaxf(cm1, fmaxf(accS[nt][2], accS[nt][3]));
        }
        cm0 = fmaxf(cm0, __shfl_xor_sync(0xffffffffu, cm0, 1));
        cm0 = fmaxf(cm0, __shfl_xor_sync(0xffffffffu, cm0, 2));
        cm1 = fmaxf(cm1, __shfl_xor_sync(0xffffffffu, cm1, 1));
        cm1 = fmaxf(cm1, __shfl_xor_sync(0xffffffffu, cm1, 2));

        float nm0 = fmaxf(m0, cm0), nm1 = fmaxf(m1, cm1);
        float al0 = __expf(m0 - nm0), al1 = __expf(m1 - nm1);
        float cs0 = 0.0f, cs1 = 0.0f;
        #pragma unroll
        for (int nt = 0; nt < 8; nt++) {
            accS[nt][0] = __expf(accS[nt][0] - nm0);
            accS[nt][1] = __expf(accS[nt][1] - nm0);
            accS[nt][2] = __expf(accS[nt][2] - nm1);
            accS[nt][3] = __expf(accS[nt][3] - nm1);
            cs0 += accS[nt][0] + accS[nt][1];
            cs1 += accS[nt][2] + accS[nt][3];
        }
        cs0 += __shfl_xor_sync(0xffffffffu, cs0, 1);
        cs0 += __shfl_xor_sync(0xffffffffu, cs0, 2);
        cs1 += __shfl_xor_sync(0xffffffffu, cs1, 1);
        cs1 += __shfl_xor_sync(0xffffffffu, cs1, 2);
        l0 = l0 * al0 + cs0;
        l1 = l1 * al1 + cs1;
        m0 = nm0; m1 = nm1;

        #pragma unroll
        for (int nt = 0; nt < 8; nt++) {
            accO[nt][0] *= al0; accO[nt][1] *= al0;
            accO[nt][2] *= al1; accO[nt][3] *= al1;
        }

        // ---- probs: C-layout regs -> smem pane -> A-layout frags (warp-private) ----
        #pragma unroll
        for (int nt = 0; nt < 8; nt++) {
            int col = nt * 8 + 2 * tg;
            Ru[rl0 * 132 + col]     = f2tf(accS[nt][0]);
            Ru[rl0 * 132 + col + 1] = f2tf(accS[nt][1]);
            Ru[rl1 * 132 + col]     = f2tf(accS[nt][2]);
            Ru[rl1 * 132 + col + 1] = f2tf(accS[nt][3]);
        }
        __syncwarp();   // prob stores visible to all lanes before A-frag reload

        // ---- O += P @ V ----
        #pragma unroll
        for (int kc = 0; kc < 8; kc++) {
            int ko = kc * 8;
            const unsigned* vp = &Vs[(kc >> 2) * VPANE];
            int so = ko & 31;
            unsigned a0 = Ru[rl0 * 132 + ko + tg];
            unsigned a1 = Ru[rl1 * 132 + ko + tg];
            unsigned a2 = Ru[rl0 * 132 + ko + tg + 4];
            unsigned a3 = Ru[rl1 * 132 + ko + tg + 4];
            #pragma unroll
            for (int nt = 0; nt < 8; nt++) {
                int col = nt * 8 + g;
                unsigned b0 = vp[col * VSTR + so + tg];
                unsigned b1 = vp[col * VSTR + so + tg + 4];
                mma_tf32(accO[nt], a0, a1, a2, a3, b0, b1);
            }
        }
        __syncthreads();   // Rs/Vs consumption complete before next stage
    }

    float inv0 = 1.0f / l0, inv1 = 1.0f / l1;
    #pragma unroll
    for (int nt = 0; nt < 8; nt++) {
        int col = nt * 8 + 2 * tg;
        float2 oa  = {accO[nt][0] * inv0, accO[nt][1] * inv0};
        float2 ob2 = {accO[nt][2] * inv1, accO[nt][3] * inv1};
        *(float2*)&o[((size_t)(b * T_ + t0 + rl0)) * D_ + h * DK + col] = oa;
        *(float2*)&o[((size_t)(b * T_ + t0 + rl1)) * D_ + h * DK + col] = ob2;
    }
}

// ------------------------- host orchestration -------------------------
extern "C" void kernel_launch(void* const* d_in, const int* in_sizes, int n_in,
                              void* d_out, int out_size) {
    const float* xs      = (const float*)d_in[0];
    const int*   masks   = (const int*)  d_in[1];
    const float* emb_w   = (const float*)d_in[2];
    const float* emb_b   = (const float*)d_in[3];
    const float* emb_g   = (const float*)d_in[4];
    const float* emb_bt  = (const float*)d_in[5];
    const float* pe_k    = (const float*)d_in[6];
    const float* Wq      = (const float*)d_in[7];
    const float* bq      = (const float*)d_in[8];
    const float* Wk      = (const float*)d_in[9];
    const float* bk      = (const float*)d_in[10];
    const float* Wv      = (const float*)d_in[11];
    const float* bv      = (const float*)d_in[12];
    const float* Wo      = (const float*)d_in[13];
    const float* bo      = (const float*)d_in[14];
    const float* ln1_g   = (const float*)d_in[15];
    const float* ln1_b   = (const float*)d_in[16];
    const float* ln2_g   = (const float*)d_in[17];
    const float* ln2_b   = (const float*)d_in[18];
    const float* lnk_g   = (const float*)d_in[19];
    const float* lnk_b   = (const float*)d_in[20];
    const float* W1      = (const float*)d_in[21];
    const float* b1      = (const float*)d_in[22];
    const float* W2      = (const float*)d_in[23];
    const float* b2      = (const float*)d_in[24];
    const float* after_g = (const float*)d_in[25];
    const float* after_b = (const float*)d_in[26];
    float* out = (float*)d_out;

    float *x, *y, *q, *k, *v, *o, *ff, *pkn;
    cudaGetSymbolAddress((void**)&x,   g_x);
    cudaGetSymbolAddress((void**)&y,   g_y);
    cudaGetSymbolAddress((void**)&q,   g_q);
    cudaGetSymbolAddress((void**)&k,   g_k);
    cudaGetSymbolAddress((void**)&v,   g_v);
    cudaGetSymbolAddress((void**)&o,   g_o);
    cudaGetSymbolAddress((void**)&ff,  g_ff);
    cudaGetSymbolAddress((void**)&pkn, g_pkn);

    cudaFuncSetAttribute(flash_attn, cudaFuncAttributeMaxDynamicSharedMemorySize, FLASH_SMEM);

    dim3 gProj(D_ / 64, BT / 128);       // (4, 32)
    dim3 gQKV(D_ / 64, BT / 128, 3);     // (4, 32, 3)
    dim3 gFF1(FF_ / 64, BT / 128);       // (32, 32)

    tgemm128<<<gProj, 256>>>(xs, emb_w, emb_b, nullptr, y, D_, IDIM, 0);
    ln_pkn_all<<<dim3(NPK, L_), 64>>>(pe_k, pkn, lnk_g, lnk_b);
    ln_warp<<<BT / 8, 256>>>(y, x, emb_g, emb_bt, 1);

    for (int l = 0; l < L_; l++) {
        ln_warp<<<BT / 8, 256>>>(x, y, ln1_g + l * D_, ln1_b + l * D_, 0);

        tgemm128_qkv<<<gQKV, 256>>>(y,
            Wq + (size_t)l * D_ * D_, Wk + (size_t)l * D_ * D_, Wv + (size_t)l * D_ * D_,
            bq + l * D_, bk + l * D_, bv + l * D_, q, k, v);

        flash_attn<<<dim3(8, BH), 128, FLASH_SMEM>>>(q, k, v, pkn + (size_t)l * NPK * DK, masks, o);

        tgemm128<<<gProj, 256>>>(o, Wo + (size_t)l * D_ * D_, bo + l * D_, x, x, D_, D_, 2);

        ln_warp<<<BT / 8, 256>>>(x, y, ln2_g + l * D_, ln2_b + l * D_, 0);
        tgemm128<<<gFF1, 256>>>(y, W1 + (size_t)l * FF_ * D_, b1 + l * FF_, nullptr, ff, FF_, D_, 1);
        tgemm128<<<gProj, 256>>>(ff, W2 + (size_t)l * D_ * FF_, b2 + l * D_, x, x, D_, FF_, 2);
    }

    ln_warp<<<BT / 8, 256>>>(x, out, after_g, after_b, 0);
}

// round 12
// speedup vs baseline: 2.6765x; 1.0180x over previous
#include <cuda_runtime.h>
#include <math.h>
#include <float.h>

// Problem constants
#define B_    8
#define T_    512
#define IDIM  1799
#define D_    256
#define H_    4
#define FF_   2048
#define L_    16
#define DK    64
#define BT    (B_*T_)    // 4096
#define BH    (B_*H_)    // 32
#define NPK   1023       // distinct rel-pos rows: t-s+511 in [0,1022]

// ------------------------- scratch (device globals) -------------------------
__device__ float g_x[BT*D_];
__device__ float g_y[BT*D_];
__device__ float g_q[BT*D_];
__device__ float g_k[BT*D_];
__device__ float g_v[BT*D_];
__device__ float g_o[BT*D_];
__device__ float g_ff[BT*FF_];
__device__ float g_mu[BT];
__device__ float g_rs[BT];
__device__ float g_pkn[(size_t)L_*NPK*DK];  // all layers, 4.2 MB

// ------------------------- block reduction (for pkn LN only) -------------------------
__device__ __forceinline__ float block_sum64(float v) {
    __shared__ float sh[3];
    #pragma unroll
    for (int o = 16; o > 0; o >>= 1) v += __shfl_xor_sync(0xffffffffu, v, o);
    int lane = threadIdx.x & 31, w = threadIdx.x >> 5;
    if (lane == 0) sh[w] = v;
    __syncthreads();
    float out = sh[0] + sh[1];
    __syncthreads();
    return out;
}

// all-layers pkn LN: grid (NPK, L), block 64
__global__ void ln_pkn_all(const float* __restrict__ pe_k, float* __restrict__ pkn,
                           const float* __restrict__ lnk_g, const float* __restrict__ lnk_b) {
    int row = blockIdx.x, l = blockIdx.y;
    float x = pe_k[(size_t)(489 + row) * DK + threadIdx.x];
    float mean = block_sum64(x) / (float)DK;
    float d = x - mean;
    float var = block_sum64(d * d) / (float)DK;
    float y = d * rsqrtf(var + 1e-12f) * lnk_g[l * DK + threadIdx.x] + lnk_b[l * DK + threadIdx.x];
    pkn[((size_t)l * NPK + row) * DK + threadIdx.x] = y;
}

// ------------------------- warp-per-row LayerNorm, width 256 -------------------------
__global__ __launch_bounds__(256) void ln_warp(const float* __restrict__ in,
                                               float* __restrict__ out,
                                               const float* __restrict__ g,
                                               const float* __restrict__ bb,
                                               int relu) {
    int warp = threadIdx.x >> 5, lane = threadIdx.x & 31;
    size_t row = (size_t)blockIdx.x * 8 + warp;
    const float* ip = in + row * D_;
    float4 v0 = *(const float4*)&ip[lane * 4];
    float4 v1 = *(const float4*)&ip[128 + lane * 4];
    float s = v0.x + v0.y + v0.z + v0.w + v1.x + v1.y + v1.z + v1.w;
    #pragma unroll
    for (int o = 16; o > 0; o >>= 1) s += __shfl_xor_sync(0xffffffffu, s, o);
    float mean = s * (1.0f / 256.0f);
    float d0x = v0.x - mean, d0y = v0.y - mean, d0z = v0.z - mean, d0w = v0.w - mean;
    float d1x = v1.x - mean, d1y = v1.y - mean, d1z = v1.z - mean, d1w = v1.w - mean;
    float vs = d0x*d0x + d0y*d0y + d0z*d0z + d0w*d0w + d1x*d1x + d1y*d1y + d1z*d1z + d1w*d1w;
    #pragma unroll
    for (int o = 16; o > 0; o >>= 1) vs += __shfl_xor_sync(0xffffffffu, vs, o);
    float rstd = rsqrtf(vs * (1.0f / 256.0f) + 1e-12f);
    float4 g0 = *(const float4*)&g[lane * 4];
    float4 g1 = *(const float4*)&g[128 + lane * 4];
    float4 b0 = *(const float4*)&bb[lane * 4];
    float4 b1 = *(const float4*)&bb[128 + lane * 4];
    float4 o0, o1;
    o0.x = d0x * rstd * g0.x + b0.x;  o0.y = d0y * rstd * g0.y + b0.y;
    o0.z = d0z * rstd * g0.z + b0.z;  o0.w = d0w * rstd * g0.w + b0.w;
    o1.x = d1x * rstd * g1.x + b1.x;  o1.y = d1y * rstd * g1.y + b1.y;
    o1.z = d1z * rstd * g1.z + b1.z;  o1.w = d1w * rstd * g1.w + b1.w;
    if (relu) {
        o0.x = fmaxf(o0.x, 0.f); o0.y = fmaxf(o0.y, 0.f); o0.z = fmaxf(o0.z, 0.f); o0.w = fmaxf(o0.w, 0.f);
        o1.x = fmaxf(o1.x, 0.f); o1.y = fmaxf(o1.y, 0.f); o1.z = fmaxf(o1.z, 0.f); o1.w = fmaxf(o1.w, 0.f);
    }
    float* op = out + row * D_;
    *(float4*)&op[lane * 4] = o0;
    *(float4*)&op[128 + lane * 4] = o1;
}

// ------------------------- warp-per-row LN stats (mean, rstd) -------------------------
__global__ __launch_bounds__(256) void ln_stats(const float* __restrict__ in,
                                                float* __restrict__ mu,
                                                float* __restrict__ rs) {
    int warp = threadIdx.x >> 5, lane = threadIdx.x & 31;
    size_t row = (size_t)blockIdx.x * 8 + warp;
    const float* ip = in + row * D_;
    float4 v0 = *(const float4*)&ip[lane * 4];
    float4 v1 = *(const float4*)&ip[128 + lane * 4];
    float s = v0.x + v0.y + v0.z + v0.w + v1.x + v1.y + v1.z + v1.w;
    #pragma unroll
    for (int o = 16; o > 0; o >>= 1) s += __shfl_xor_sync(0xffffffffu, s, o);
    float mean = s * (1.0f / 256.0f);
    float d0x = v0.x - mean, d0y = v0.y - mean, d0z = v0.z - mean, d0w = v0.w - mean;
    float d1x = v1.x - mean, d1y = v1.y - mean, d1z = v1.z - mean, d1w = v1.w - mean;
    float vs = d0x*d0x + d0y*d0y + d0z*d0z + d0w*d0w + d1x*d1x + d1y*d1y + d1z*d1z + d1w*d1w;
    #pragma unroll
    for (int o = 16; o > 0; o >>= 1) vs += __shfl_xor_sync(0xffffffffu, vs, o);
    if (lane == 0) {
        mu[row] = mean;
        rs[row] = rsqrtf(vs * (1.0f / 256.0f) + 1e-12f);
    }
}

// ------------------------- tf32 helpers -------------------------
__device__ __forceinline__ unsigned f2tf(float f) {
    unsigned r;
    asm("cvt.rna.tf32.f32 %0, %1;" : "=r"(r) : "f"(f));
    return r;
}

__device__ __forceinline__ void mma_tf32(float c[4],
                                         unsigned a0, unsigned a1, unsigned a2, unsigned a3,
                                         unsigned b0, unsigned b1) {
    asm volatile(
        "mma.sync.aligned.m16n8k8.row.col.f32.tf32.tf32.f32 "
        "{%0,%1,%2,%3}, {%4,%5,%6,%7}, {%8,%9}, {%0,%1,%2,%3};"
        : "+f"(c[0]), "+f"(c[1]), "+f"(c[2]), "+f"(c[3])
        : "r"(a0), "r"(a1), "r"(a2), "r"(a3), "r"(b0), "r"(b1));
}

// ------------------------- TF32 GEMM, BM=128 BN=64 BK=32, reg-prefetch pipeline ------------
// Optional fused LayerNorm on A: if lg != nullptr, A row r is normalized with
// (a - mu[r]) * rs[r] * lg[k] + lb[k] during staging (vec path only).
#define SSTR 36
__device__ __forceinline__ void tg128_body(
    const float* __restrict__ A, const float* __restrict__ Bm,
    const float* __restrict__ bias, const float* __restrict__ R,
    float* __restrict__ C, int N, int K, int mode, int r0, int c0,
    const float* __restrict__ mu, const float* __restrict__ rs,
    const float* __restrict__ lg, const float* __restrict__ lb)
{
    __shared__ unsigned As[128 * SSTR];
    __shared__ unsigned Bs[64 * SSTR];

    int tid = threadIdx.x;
    int lane = tid & 31, warp = tid >> 5;
    int wm = warp >> 1, wn = warp & 1;
    int g = lane >> 2, tg = lane & 3;

    const float* Ab = A + (size_t)r0 * K;
    const float* Bb = Bm + (size_t)c0 * K;

    float acc[2][4][4];
    #pragma unroll
    for (int mt = 0; mt < 2; mt++)
        #pragma unroll
        for (int nt = 0; nt < 4; nt++)
            #pragma unroll
            for (int e = 0; e < 4; e++) acc[mt][nt][e] = 0.0f;

    // per-thread LN row stats (A rows are fixed per i across chunks)
    float muv[4], rsv[4];
    if (lg) {
        #pragma unroll
        for (int i = 0; i < 4; i++) {
            int r = (tid + i * 256) >> 3;
            muv[i] = mu[r0 + r];
            rsv[i] = rs[r0 + r];
        }
    }

    auto do_mma = [&]() {
        #pragma unroll
        for (int kc = 0; kc < 4; kc++) {
            int ko = kc * 8;
            unsigned a[2][4], b[4][2];
            #pragma unroll
            for (int mt = 0; mt < 2; mt++) {
                int row = wm * 32 + mt * 16 + g;
                a[mt][0] = As[row * SSTR + ko + tg];
                a[mt][1] = As[(row + 8) * SSTR + ko + tg];
                a[mt][2] = As[row * SSTR + ko + tg + 4];
                a[mt][3] = As[(row + 8) * SSTR + ko + tg + 4];
            }
            #pragma unroll
            for (int nt = 0; nt < 4; nt++) {
                int col = wn * 32 + nt * 8 + g;
                b[nt][0] = Bs[col * SSTR + ko + tg];
                b[nt][1] = Bs[col * SSTR + ko + tg + 4];
            }
            #pragma unroll
            for (int mt = 0; mt < 2; mt++)
                #pragma unroll
                for (int nt = 0; nt < 4; nt++)
                    mma_tf32(acc[mt][nt], a[mt][0], a[mt][1], a[mt][2], a[mt][3],
                             b[nt][0], b[nt][1]);
        }
    };

    auto store_a = [&](float4 av, int i, int kbase) {
        int idx = tid + i * 256, r = idx >> 3, c4 = idx & 7;
        if (lg) {
            float4 ga = *(const float4*)&lg[kbase + c4 * 4];
            float4 be = *(const float4*)&lb[kbase + c4 * 4];
            float m = muv[i], rr = rsv[i];
            av.x = (av.x - m) * rr * ga.x + be.x;
            av.y = (av.y - m) * rr * ga.y + be.y;
            av.z = (av.z - m) * rr * ga.z + be.z;
            av.w = (av.w - m) * rr * ga.w + be.w;
        }
        unsigned* ap = &As[r * SSTR + c4 * 4];
        ap[0] = f2tf(av.x); ap[1] = f2tf(av.y); ap[2] = f2tf(av.z); ap[3] = f2tf(av.w);
    };

    if ((K & 31) == 0) {
        int nch = K >> 5;
        float4 pa[4], pb[2];
        #pragma unroll
        for (int i = 0; i < 4; i++) {
            int idx = tid + i * 256, r = idx >> 3, c4 = idx & 7;
            pa[i] = *(const float4*)&Ab[(size_t)r * K + c4 * 4];
        }
        #pragma unroll
        for (int i = 0; i < 2; i++) {
            int idx = tid + i * 256, r = idx >> 3, c4 = idx & 7;
            pb[i] = *(const float4*)&Bb[(size_t)r * K + c4 * 4];
        }
        #pragma unroll
        for (int i = 0; i < 4; i++) store_a(pa[i], i, 0);
        #pragma unroll
        for (int i = 0; i < 2; i++) {
            int idx = tid + i * 256, r = idx >> 3, c4 = idx & 7;
            unsigned* bp = &Bs[r * SSTR + c4 * 4];
            bp[0] = f2tf(pb[i].x); bp[1] = f2tf(pb[i].y); bp[2] = f2tf(pb[i].z); bp[3] = f2tf(pb[i].w);
        }
        __syncthreads();

        for (int ch = 0; ch < nch; ch++) {
            bool more = (ch + 1 < nch);
            int k1 = (ch + 1) << 5;
            if (more) {
                #pragma unroll
                for (int i = 0; i < 4; i++) {
                    int idx = tid + i * 256, r = idx >> 3, c4 = idx & 7;
                    pa[i] = *(const float4*)&Ab[(size_t)r * K + k1 + c4 * 4];
                }
                #pragma unroll
                for (int i = 0; i < 2; i++) {
                    int idx = tid + i * 256, r = idx >> 3, c4 = idx & 7;
                    pb[i] = *(const float4*)&Bb[(size_t)r * K + k1 + c4 * 4];
                }
            }
            do_mma();
            if (more) {
                __syncthreads();
                #pragma unroll
                for (int i = 0; i < 4; i++) store_a(pa[i], i, k1);
                #pragma unroll
                for (int i = 0; i < 2; i++) {
                    int idx = tid + i * 256, r = idx >> 3, c4 = idx & 7;
                    unsigned* bp = &Bs[r * SSTR + c4 * 4];
                    bp[0] = f2tf(pb[i].x); bp[1] = f2tf(pb[i].y); bp[2] = f2tf(pb[i].z); bp[3] = f2tf(pb[i].w);
                }
                __syncthreads();
            }
        }
    } else {
        // guarded scalar path (embed GEMM, K=1799) — no LN fusion here
        for (int k0 = 0; k0 < K; k0 += 32) {
            #pragma unroll
            for (int i = 0; i < 16; i++) {
                int idx = tid + i * 256, r = idx >> 5, c = idx & 31;
                int kk = k0 + c;
                As[r * SSTR + c] = f2tf((kk < K) ? Ab[(size_t)r * K + kk] : 0.0f);
            }
            #pragma unroll
            for (int i = 0; i < 8; i++) {
                int idx = tid + i * 256, r = idx >> 5, c = idx & 31;
                int kk = k0 + c;
                Bs[r * SSTR + c] = f2tf((kk < K) ? Bb[(size_t)r * K + kk] : 0.0f);
            }
            __syncthreads();
            do_mma();
            __syncthreads();
        }
    }

    #pragma unroll
    for (int mt = 0; mt < 2; mt++) {
        int row = r0 + wm * 32 + mt * 16 + g;
        #pragma unroll
        for (int nt = 0; nt < 4; nt++) {
            int col = c0 + wn * 32 + nt * 8 + 2 * tg;
            float2 bi = *(const float2*)&bias[col];
            #pragma unroll
            for (int half = 0; half < 2; half++) {
                int rr = row + half * 8;
                float x0 = acc[mt][nt][half * 2 + 0] + bi.x;
                float x1 = acc[mt][nt][half * 2 + 1] + bi.y;
                if (mode & 2) {
                    float2 rv = *(const float2*)&R[(size_t)rr * N + col];
                    x0 += rv.x; x1 += rv.y;
                }
                if (mode & 1) { x0 = fmaxf(x0, 0.0f); x1 = fmaxf(x1, 0.0f); }
                float2 o2 = {x0, x1};
                *(float2*)&C[(size_t)rr * N + col] = o2;
            }
        }
    }
}

__global__ __launch_bounds__(256) void tgemm128(
    const float* __restrict__ A, const float* __restrict__ Bm,
    const float* __restrict__ bias, const float* __restrict__ R,
    float* __restrict__ C, int N, int K, int mode,
    const float* __restrict__ mu, const float* __restrict__ rs,
    const float* __restrict__ lg, const float* __restrict__ lb)
{
    tg128_body(A, Bm, bias, R, C, N, K, mode, blockIdx.y * 128, blockIdx.x * 64,
               mu, rs, lg, lb);
}

__global__ __launch_bounds__(256) void tgemm128_qkv(
    const float* __restrict__ A,
    const float* __restrict__ Wq, const float* __restrict__ Wk, const float* __restrict__ Wv,
    const float* __restrict__ bq, const float* __restrict__ bk, const float* __restrict__ bv,
    float* __restrict__ q, float* __restrict__ k, float* __restrict__ v,
    const float* __restrict__ mu, const float* __restrict__ rs,
    const float* __restrict__ lg, const float* __restrict__ lb)
{
    const float* W; const float* bi; float* C;
    if (blockIdx.z == 0)      { W = Wq; bi = bq; C = q; }
    else if (blockIdx.z == 1) { W = Wk; bi = bk; C = k; }
    else                      { W = Wv; bi = bv; C = v; }
    tg128_body(A, W, bi, nullptr, C, D_, D_, 0, blockIdx.y * 128, blockIdx.x * 64,
               mu, rs, lg, lb);
}

// ------------------------- TF32 GEMM, BM=128 BN=128 BK=32 (for FF1) -------------------------
// 256 threads = 8 warps (2m x 4n), warp tile 64x32. Optional fused LN on A.
__global__ __launch_bounds__(256) void tgemm256(
    const float* __restrict__ A, const float* __restrict__ Bm,
    const float* __restrict__ bias, float* __restrict__ C,
    int N, int K, int mode,
    const float* __restrict__ mu, const float* __restrict__ rs,
    const float* __restrict__ lg, const float* __restrict__ lb)
{
    __shared__ unsigned As[128 * SSTR];
    __shared__ unsigned Bs[128 * SSTR];

    int tid = threadIdx.x;
    int lane = tid & 31, warp = tid >> 5;
    int wm = warp >> 2, wn = warp & 3;
    int g = lane >> 2, tg = lane & 3;

    int r0 = blockIdx.y * 128, c0 = blockIdx.x * 128;
    const float* Ab = A + (size_t)r0 * K;
    const float* Bb = Bm + (size_t)c0 * K;

    float acc[4][4][4];
    #pragma unroll
    for (int mt = 0; mt < 4; mt++)
        #pragma unroll
        for (int nt = 0; nt < 4; nt++)
            #pragma unroll
            for (int e = 0; e < 4; e++) acc[mt][nt][e] = 0.0f;

    float muv[4], rsv[4];
    if (lg) {
        #pragma unroll
        for (int i = 0; i < 4; i++) {
            int r = (tid + i * 256) >> 3;
            muv[i] = mu[r0 + r];
            rsv[i] = rs[r0 + r];
        }
    }

    for (int k0 = 0; k0 < K; k0 += 32) {
        // stage A (128x32) with optional LN
        #pragma unroll
        for (int i = 0; i < 4; i++) {
            int idx = tid + i * 256, r = idx >> 3, c4 = idx & 7;
            float4 av = *(const float4*)&Ab[(size_t)r * K + k0 + c4 * 4];
            if (lg) {
                float4 ga = *(const float4*)&lg[k0 + c4 * 4];
                float4 be = *(const float4*)&lb[k0 + c4 * 4];
                float m = muv[i], rr = rsv[i];
                av.x = (av.x - m) * rr * ga.x + be.x;
                av.y = (av.y - m) * rr * ga.y + be.y;
                av.z = (av.z - m) * rr * ga.z + be.z;
                av.w = (av.w - m) * rr * ga.w + be.w;
            }
            unsigned* ap = &As[r * SSTR + c4 * 4];
            ap[0] = f2tf(av.x); ap[1] = f2tf(av.y); ap[2] = f2tf(av.z); ap[3] = f2tf(av.w);
        }
        // stage B (128x32)
        #pragma unroll
        for (int i = 0; i < 4; i++) {
            int idx = tid + i * 256, r = idx >> 3, c4 = idx & 7;
            float4 bv = *(const float4*)&Bb[(size_t)r * K + k0 + c4 * 4];
            unsigned* bp = &Bs[r * SSTR + c4 * 4];
            bp[0] = f2tf(bv.x); bp[1] = f2tf(bv.y); bp[2] = f2tf(bv.z); bp[3] = f2tf(bv.w);
        }
        __syncthreads();

        #pragma unroll
        for (int kc = 0; kc < 4; kc++) {
            int ko = kc * 8;
            unsigned a[4][4], b[4][2];
            #pragma unroll
            for (int mt = 0; mt < 4; mt++) {
                int row = wm * 64 + mt * 16 + g;
                a[mt][0] = As[row * SSTR + ko + tg];
                a[mt][1] = As[(row + 8) * SSTR + ko + tg];
                a[mt][2] = As[row * SSTR + ko + tg + 4];
                a[mt][3] = As[(row + 8) * SSTR + ko + tg + 4];
            }
            #pragma unroll
            for (int nt = 0; nt < 4; nt++) {
                int col = wn * 32 + nt * 8 + g;
                b[nt][0] = Bs[col * SSTR + ko + tg];
                b[nt][1] = Bs[col * SSTR + ko + tg + 4];
            }
            #pragma unroll
            for (int mt = 0; mt < 4; mt++)
                #pragma unroll
                for (int nt = 0; nt < 4; nt++)
                    mma_tf32(acc[mt][nt], a[mt][0], a[mt][1], a[mt][2], a[mt][3],
                             b[nt][0], b[nt][1]);
        }
        __syncthreads();
    }

    #pragma unroll
    for (int mt = 0; mt < 4; mt++) {
        int row = r0 + wm * 64 + mt * 16 + g;
        #pragma unroll
        for (int nt = 0; nt < 4; nt++) {
            int col = c0 + wn * 32 + nt * 8 + 2 * tg;
            float2 bi = *(const float2*)&bias[col];
            #pragma unroll
            for (int half = 0; half < 2; half++) {
                int rr = row + half * 8;
                float x0 = acc[mt][nt][half * 2 + 0] + bi.x;
                float x1 = acc[mt][nt][half * 2 + 1] + bi.y;
                if (mode & 1) { x0 = fmaxf(x0, 0.0f); x1 = fmaxf(x1, 0.0f); }
                float2 o2 = {x0, x1};
                *(float2*)&C[(size_t)rr * N + col] = o2;
            }
        }
    }
}

// ------------------------- fully fused flash attention -------------------------
#define KSTR 68
#define VSTR 37
#define VPANE 2368   // words per V half-pane (64*37)
#define FLASH_SMEM 73216
__global__ __launch_bounds__(128) void flash_attn(
    const float* __restrict__ q, const float* __restrict__ k,
    const float* __restrict__ v, const float* __restrict__ pkn_l,
    const int* __restrict__ masks, float* __restrict__ o)
{
    extern __shared__ char sbuf[];
    unsigned* Vs = (unsigned*)sbuf;
    unsigned* Ks = (unsigned*)(sbuf + 18944);
    unsigned* Ps = (unsigned*)(sbuf + 36352);
    float*    Rs = (float*)(sbuf + 18944);
    unsigned* Ru = (unsigned*)(sbuf + 18944);
    int*      msk = (int*)(sbuf + 71168);

    int tid = threadIdx.x;
    int lane = tid & 31, warp = tid >> 5;
    int g = lane >> 2, tg = lane & 3;
    int rl0 = warp * 16 + g, rl1 = rl0 + 8;

    int t0 = blockIdx.x * 64, bh = blockIdx.y;
    int b = bh >> 2, h = bh & 3;
    const float* qb  = q + ((size_t)(b * T_ + t0)) * D_ + h * DK;
    const float* kb0 = k + ((size_t)(b * T_)) * D_ + h * DK;
    const float* vb0 = v + ((size_t)(b * T_)) * D_ + h * DK;

    #pragma unroll
    for (int i = 0; i < 4; i++) msk[tid + i * 128] = masks[b * T_ + tid + i * 128];
    #pragma unroll
    for (int i = 0; i < 8; i++) {
        int idx = tid + i * 128, r = idx >> 4, c4 = idx & 15;
        float4 qv = *(const float4*)&qb[(size_t)r * D_ + c4 * 4];
        unsigned* p = &Ks[r * KSTR + c4 * 4];
        p[0] = f2tf(qv.x); p[1] = f2tf(qv.y); p[2] = f2tf(qv.z); p[3] = f2tf(qv.w);
    }
    __syncthreads();
    unsigned qa[8][4];
    #pragma unroll
    for (int kc = 0; kc < 8; kc++) {
        qa[kc][0] = Ks[rl0 * KSTR + kc * 8 + tg];
        qa[kc][1] = Ks[rl1 * KSTR + kc * 8 + tg];
        qa[kc][2] = Ks[rl0 * KSTR + kc * 8 + tg + 4];
        qa[kc][3] = Ks[rl1 * KSTR + kc * 8 + tg + 4];
    }
    __syncthreads();

    float accO[8][4];
    #pragma unroll
    for (int nt = 0; nt < 8; nt++)
        #pragma unroll
        for (int e = 0; e < 4; e++) accO[nt][e] = 0.0f;
    float m0 = -FLT_MAX, m1 = -FLT_MAX, l0 = 0.0f, l1 = 0.0f;

    const float scale = 0.125f;

    for (int sc = 0; sc < 8; sc++) {
        int s0 = sc * 64;
        #pragma unroll
        for (int i = 0; i < 8; i++) {
            int idx = tid + i * 128, r = idx >> 4, c4 = idx & 15;
            float4 kv = *(const float4*)&kb0[(size_t)(s0 + r) * D_ + c4 * 4];
            unsigned* p = &Ks[r * KSTR + c4 * 4];
            p[0] = f2tf(kv.x); p[1] = f2tf(kv.y); p[2] = f2tf(kv.z); p[3] = f2tf(kv.w);
        }
        #pragma unroll
        for (int i = 0; i < 8; i++) {
            int idx = tid + i * 128, r = idx >> 4, c4 = idx & 15;
            int half = r >> 5, rsl = r & 31;
            unsigned* vp = &Vs[half * VPANE];
            float4 vv = *(const float4*)&vb0[(size_t)(s0 + r) * D_ + c4 * 4];
            vp[(c4 * 4 + 0) * VSTR + rsl] = f2tf(vv.x);
            vp[(c4 * 4 + 1) * VSTR + rsl] = f2tf(vv.y);
            vp[(c4 * 4 + 2) * VSTR + rsl] = f2tf(vv.z);
            vp[(c4 * 4 + 3) * VSTR + rsl] = f2tf(vv.w);
        }
        const float* pb = pkn_l + (size_t)(t0 - s0 + 448) * DK;
        #pragma unroll
        for (int i = 0; i < 16; i++) {
            int idx = tid + i * 128, r = idx >> 4, c4 = idx & 15;
            unsigned* p = &Ps[r * KSTR + c4 * 4];
            if (r < 127) {
                float4 pv = *(const float4*)&pb[(size_t)r * DK + c4 * 4];
                p[0] = f2tf(pv.x); p[1] = f2tf(pv.y); p[2] = f2tf(pv.z); p[3] = f2tf(pv.w);
            } else {
                p[0] = 0u; p[1] = 0u; p[2] = 0u; p[3] = 0u;
            }
        }
        __syncthreads();

        float accS[8][4], accR[16][4];
        #pragma unroll
        for (int nt = 0; nt < 8; nt++)
            #pragma unroll
            for (int e = 0; e < 4; e++) accS[nt][e] = 0.0f;
        #pragma unroll
        for (int nt = 0; nt < 16; nt++)
            #pragma unroll
            for (int e = 0; e < 4; e++) accR[nt][e] = 0.0f;

        #pragma unroll
        for (int kc = 0; kc < 8; kc++) {
            int ko = kc * 8;
            #pragma unroll
            for (int nt = 0; nt < 8; nt++) {
                int col = nt * 8 + g;
                unsigned b0 = Ks[col * KSTR + ko + tg];
                unsigned b1 = Ks[col * KSTR + ko + tg + 4];
                mma_tf32(accS[nt], qa[kc][0], qa[kc][1], qa[kc][2], qa[kc][3], b0, b1);
            }
            #pragma unroll
            for (int nt = 0; nt < 16; nt++) {
                int col = nt * 8 + g;
                unsigned b0 = Ps[col * KSTR + ko + tg];
                unsigned b1 = Ps[col * KSTR + ko + tg + 4];
                mma_tf32(accR[nt], qa[kc][0], qa[kc][1], qa[kc][2], qa[kc][3], b0, b1);
            }
        }
        __syncthreads();

        #pragma unroll
        for (int nt = 0; nt < 16; nt++) {
            int col = nt * 8 + 2 * tg;
            Rs[rl0 * 132 + col]     = accR[nt][0];
            Rs[rl0 * 132 + col + 1] = accR[nt][1];
            Rs[rl1 * 132 + col]     = accR[nt][2];
            Rs[rl1 * 132 + col + 1] = accR[nt][3];
        }
        __syncwarp();

        #pragma unroll
        for (int nt = 0; nt < 8; nt++) {
            #pragma unroll
            for (int e = 0; e < 2; e++) {
                int c = nt * 8 + 2 * tg + e;
                float r0 = Rs[rl0 * 132 + (rl0 - c + 63)];
                float r1 = Rs[rl1 * 132 + (rl1 - c + 63)];
                float x0 = (accS[nt][e] + r0) * scale;
                float x1 = (accS[nt][2 + e] + r1) * scale;
                if (msk[s0 + c] == 0) { x0 = -FLT_MAX; x1 = -FLT_MAX; }
                accS[nt][e] = x0;
                accS[nt][2 + e] = x1;
            }
        }
        __syncwarp();

        float cm0 = -FLT_MAX, cm1 = -FLT_MAX;
        #pragma unroll
        for (int nt = 0; nt < 8; nt++) {
            cm0 = fmaxf(cm0, fmaxf(accS[nt][0], accS[nt][1]));
            cm1 = fmaxf(cm1, fmaxf(accS[nt][2], accS[nt][3]));
        }
        cm0 = fmaxf(cm0, __shfl_xor_sync(0xffffffffu, cm0, 1));
        cm0 = fmaxf(cm0, __shfl_xor_sync(0xffffffffu, cm0, 2));
        cm1 = fmaxf(cm1, __shfl_xor_sync(0xffffffffu, cm1, 1));
        cm1 = fmaxf(cm1, __shfl_xor_sync(0xffffffffu, cm1, 2));

        float nm0 = fmaxf(m0, cm0), nm1 = fmaxf(m1, cm1);
        float al0 = __expf(m0 - nm0), al1 = __expf(m1 - nm1);
        float cs0 = 0.0f, cs1 = 0.0f;
        #pragma unroll
        for (int nt = 0; nt < 8; nt++) {
            accS[nt][0] = __expf(accS[nt][0] - nm0);
            accS[nt][1] = __expf(accS[nt][1] - nm0);
            accS[nt][2] = __expf(accS[nt][2] - nm1);
            accS[nt][3] = __expf(accS[nt][3] - nm1);
            cs0 += accS[nt][0] + accS[nt][1];
            cs1 += accS[nt][2] + accS[nt][3];
        }
        cs0 += __shfl_xor_sync(0xffffffffu, cs0, 1);
        cs0 += __shfl_xor_sync(0xffffffffu, cs0, 2);
        cs1 += __shfl_xor_sync(0xffffffffu, cs1, 1);
        cs1 += __shfl_xor_sync(0xffffffffu, cs1, 2);
        l0 = l0 * al0 + cs0;
        l1 = l1 * al1 + cs1;
        m0 = nm0; m1 = nm1;

        #pragma unroll
        for (int nt = 0; nt < 8; nt++) {
            accO[nt][0] *= al0; accO[nt][1] *= al0;
            accO[nt][2] *= al1; accO[nt][3] *= al1;
        }

        #pragma unroll
        for (int nt = 0; nt < 8; nt++) {
            int col = nt * 8 + 2 * tg;
            Ru[rl0 * 132 + col]     = f2tf(accS[nt][0]);
            Ru[rl0 * 132 + col + 1] = f2tf(accS[nt][1]);
            Ru[rl1 * 132 + col]     = f2tf(accS[nt][2]);
            Ru[rl1 * 132 + col + 1] = f2tf(accS[nt][3]);
        }
        __syncwarp();

        #pragma unroll
        for (int kc = 0; kc < 8; kc++) {
            int ko = kc * 8;
            const unsigned* vp = &Vs[(kc >> 2) * VPANE];
            int so = ko & 31;
            unsigned a0 = Ru[rl0 * 132 + ko + tg];
            unsigned a1 = Ru[rl1 * 132 + ko + tg];
            unsigned a2 = Ru[rl0 * 132 + ko + tg + 4];
            unsigned a3 = Ru[rl1 * 132 + ko + tg + 4];
            #pragma unroll
            for (int nt = 0; nt < 8; nt++) {
                int col = nt * 8 + g;
                unsigned b0 = vp[col * VSTR + so + tg];
                unsigned b1 = vp[col * VSTR + so + tg + 4];
                mma_tf32(accO[nt], a0, a1, a2, a3, b0, b1);
            }
        }
        __syncthreads();
    }

    float inv0 = 1.0f / l0, inv1 = 1.0f / l1;
    #pragma unroll
    for (int nt = 0; nt < 8; nt++) {
        int col = nt * 8 + 2 * tg;
        float2 oa  = {accO[nt][0] * inv0, accO[nt][1] * inv0};
        float2 ob2 = {accO[nt][2] * inv1, accO[nt][3] * inv1};
        *(float2*)&o[((size_t)(b * T_ + t0 + rl0)) * D_ + h * DK + col] = oa;
        *(float2*)&o[((size_t)(b * T_ + t0 + rl1)) * D_ + h * DK + col] = ob2;
    }
}

// ------------------------- host orchestration -------------------------
extern "C" void kernel_launch(void* const* d_in, const int* in_sizes, int n_in,
                              void* d_out, int out_size) {
    const float* xs      = (const float*)d_in[0];
    const int*   masks   = (const int*)  d_in[1];
    const float* emb_w   = (const float*)d_in[2];
    const float* emb_b   = (const float*)d_in[3];
    const float* emb_g   = (const float*)d_in[4];
    const float* emb_bt  = (const float*)d_in[5];
    const float* pe_k    = (const float*)d_in[6];
    const float* Wq      = (const float*)d_in[7];
    const float* bq      = (const float*)d_in[8];
    const float* Wk      = (const float*)d_in[9];
    const float* bk      = (const float*)d_in[10];
    const float* Wv      = (const float*)d_in[11];
    const float* bv      = (const float*)d_in[12];
    const float* Wo      = (const float*)d_in[13];
    const float* bo      = (const float*)d_in[14];
    const float* ln1_g   = (const float*)d_in[15];
    const float* ln1_b   = (const float*)d_in[16];
    const float* ln2_g   = (const float*)d_in[17];
    const float* ln2_b   = (const float*)d_in[18];
    const float* lnk_g   = (const float*)d_in[19];
    const float* lnk_b   = (const float*)d_in[20];
    const float* W1      = (const float*)d_in[21];
    const float* b1      = (const float*)d_in[22];
    const float* W2      = (const float*)d_in[23];
    const float* b2      = (const float*)d_in[24];
    const float* after_g = (const float*)d_in[25];
    const float* after_b = (const float*)d_in[26];
    float* out = (float*)d_out;

    float *x, *y, *q, *k, *v, *o, *ff, *pkn, *mu, *rs;
    cudaGetSymbolAddress((void**)&x,   g_x);
    cudaGetSymbolAddress((void**)&y,   g_y);
    cudaGetSymbolAddress((void**)&q,   g_q);
    cudaGetSymbolAddress((void**)&k,   g_k);
    cudaGetSymbolAddress((void**)&v,   g_v);
    cudaGetSymbolAddress((void**)&o,   g_o);
    cudaGetSymbolAddress((void**)&ff,  g_ff);
    cudaGetSymbolAddress((void**)&pkn, g_pkn);
    cudaGetSymbolAddress((void**)&mu,  g_mu);
    cudaGetSymbolAddress((void**)&rs,  g_rs);

    cudaFuncSetAttribute(flash_attn, cudaFuncAttributeMaxDynamicSharedMemorySize, FLASH_SMEM);

    dim3 gProj(D_ / 64, BT / 128);       // (4, 32)
    dim3 gQKV(D_ / 64, BT / 128, 3);     // (4, 32, 3)
    dim3 gFF1(FF_ / 128, BT / 128);      // (16, 32)

    // embed: GEMM + bias -> LN(+relu); pkn LN for all layers upfront
    tgemm128<<<gProj, 256>>>(xs, emb_w, emb_b, nullptr, y, D_, IDIM, 0,
                             nullptr, nullptr, nullptr, nullptr);
    ln_pkn_all<<<dim3(NPK, L_), 64>>>(pe_k, pkn, lnk_g, lnk_b);
    ln_warp<<<BT / 8, 256>>>(y, x, emb_g, emb_bt, 1);

    for (int l = 0; l < L_; l++) {
        // ln1 fused into QKV staging
        ln_stats<<<BT / 8, 256>>>(x, mu, rs);
        tgemm128_qkv<<<gQKV, 256>>>(x,
            Wq + (size_t)l * D_ * D_, Wk + (size_t)l * D_ * D_, Wv + (size_t)l * D_ * D_,
            bq + l * D_, bk + l * D_, bv + l * D_, q, k, v,
            mu, rs, ln1_g + l * D_, ln1_b + l * D_);

        flash_attn<<<dim3(8, BH), 128, FLASH_SMEM>>>(q, k, v, pkn + (size_t)l * NPK * DK, masks, o);

        tgemm128<<<gProj, 256>>>(o, Wo + (size_t)l * D_ * D_, bo + l * D_, x, x, D_, D_, 2,
                                 nullptr, nullptr, nullptr, nullptr);

        // ln2 fused into FF1 staging
        ln_stats<<<BT / 8, 256>>>(x, mu, rs);
        tgemm256<<<gFF1, 256>>>(x, W1 + (size_t)l * FF_ * D_, b1 + l * FF_, ff,
                                FF_, D_, 1, mu, rs, ln2_g + l * D_, ln2_b + l * D_);
        tgemm128<<<gProj, 256>>>(ff, W2 + (size_t)l * D_ * FF_, b2 + l * D_, x, x, D_, FF_, 2,
                                 nullptr, nullptr, nullptr, nullptr);
    }

    ln_warp<<<BT / 8, 256>>>(x, out, after_g, after_b, 0);
}

// round 13
// speedup vs baseline: 2.8937x; 1.0812x over previous
#include <cuda_runtime.h>
#include <cuda_fp16.h>
#include <math.h>
#include <float.h>

// Problem constants
#define B_    8
#define T_    512
#define IDIM  1799
#define D_    256
#define H_    4
#define FF_   2048
#define L_    16
#define DK    64
#define BT    (B_*T_)    // 4096
#define BH    (B_*H_)    // 32
#define NPK   1023       // distinct rel-pos rows: t-s+511 in [0,1022]

// ------------------------- scratch (device globals) -------------------------
__device__ float g_x[BT*D_];
__device__ float g_y[BT*D_];
__device__ float g_q[BT*D_];
__device__ float g_k[BT*D_];
__device__ float g_v[BT*D_];
__device__ float g_o[BT*D_];
__device__ float g_ff[BT*FF_];
__device__ float g_mu[BT];
__device__ float g_rs[BT];
__device__ float g_pkn[(size_t)L_*NPK*DK];  // all layers, 4.2 MB

// ------------------------- block reduction (for pkn LN only) -------------------------
__device__ __forceinline__ float block_sum64(float v) {
    __shared__ float sh[3];
    #pragma unroll
    for (int o = 16; o > 0; o >>= 1) v += __shfl_xor_sync(0xffffffffu, v, o);
    int lane = threadIdx.x & 31, w = threadIdx.x >> 5;
    if (lane == 0) sh[w] = v;
    __syncthreads();
    float out = sh[0] + sh[1];
    __syncthreads();
    return out;
}

// all-layers pkn LN: grid (NPK, L), block 64
__global__ void ln_pkn_all(const float* __restrict__ pe_k, float* __restrict__ pkn,
                           const float* __restrict__ lnk_g, const float* __restrict__ lnk_b) {
    int row = blockIdx.x, l = blockIdx.y;
    float x = pe_k[(size_t)(489 + row) * DK + threadIdx.x];
    float mean = block_sum64(x) / (float)DK;
    float d = x - mean;
    float var = block_sum64(d * d) / (float)DK;
    float y = d * rsqrtf(var + 1e-12f) * lnk_g[l * DK + threadIdx.x] + lnk_b[l * DK + threadIdx.x];
    pkn[((size_t)l * NPK + row) * DK + threadIdx.x] = y;
}

// ------------------------- warp-per-row LayerNorm, width 256 -------------------------
__global__ __launch_bounds__(256) void ln_warp(const float* __restrict__ in,
                                               float* __restrict__ out,
                                               const float* __restrict__ g,
                                               const float* __restrict__ bb,
                                               int relu) {
    int warp = threadIdx.x >> 5, lane = threadIdx.x & 31;
    size_t row = (size_t)blockIdx.x * 8 + warp;
    const float* ip = in + row * D_;
    float4 v0 = *(const float4*)&ip[lane * 4];
    float4 v1 = *(const float4*)&ip[128 + lane * 4];
    float s = v0.x + v0.y + v0.z + v0.w + v1.x + v1.y + v1.z + v1.w;
    #pragma unroll
    for (int o = 16; o > 0; o >>= 1) s += __shfl_xor_sync(0xffffffffu, s, o);
    float mean = s * (1.0f / 256.0f);
    float d0x = v0.x - mean, d0y = v0.y - mean, d0z = v0.z - mean, d0w = v0.w - mean;
    float d1x = v1.x - mean, d1y = v1.y - mean, d1z = v1.z - mean, d1w = v1.w - mean;
    float vs = d0x*d0x + d0y*d0y + d0z*d0z + d0w*d0w + d1x*d1x + d1y*d1y + d1z*d1z + d1w*d1w;
    #pragma unroll
    for (int o = 16; o > 0; o >>= 1) vs += __shfl_xor_sync(0xffffffffu, vs, o);
    float rstd = rsqrtf(vs * (1.0f / 256.0f) + 1e-12f);
    float4 g0 = *(const float4*)&g[lane * 4];
    float4 g1 = *(const float4*)&g[128 + lane * 4];
    float4 b0 = *(const float4*)&bb[lane * 4];
    float4 b1 = *(const float4*)&bb[128 + lane * 4];
    float4 o0, o1;
    o0.x = d0x * rstd * g0.x + b0.x;  o0.y = d0y * rstd * g0.y + b0.y;
    o0.z = d0z * rstd * g0.z + b0.z;  o0.w = d0w * rstd * g0.w + b0.w;
    o1.x = d1x * rstd * g1.x + b1.x;  o1.y = d1y * rstd * g1.y + b1.y;
    o1.z = d1z * rstd * g1.z + b1.z;  o1.w = d1w * rstd * g1.w + b1.w;
    if (relu) {
        o0.x = fmaxf(o0.x, 0.f); o0.y = fmaxf(o0.y, 0.f); o0.z = fmaxf(o0.z, 0.f); o0.w = fmaxf(o0.w, 0.f);
        o1.x = fmaxf(o1.x, 0.f); o1.y = fmaxf(o1.y, 0.f); o1.z = fmaxf(o1.z, 0.f); o1.w = fmaxf(o1.w, 0.f);
    }
    float* op = out + row * D_;
    *(float4*)&op[lane * 4] = o0;
    *(float4*)&op[128 + lane * 4] = o1;
}

// ------------------------- warp-per-row LN stats (mean, rstd) -------------------------
__global__ __launch_bounds__(256) void ln_stats(const float* __restrict__ in,
                                                float* __restrict__ mu,
                                                float* __restrict__ rs) {
    int warp = threadIdx.x >> 5, lane = threadIdx.x & 31;
    size_t row = (size_t)blockIdx.x * 8 + warp;
    const float* ip = in + row * D_;
    float4 v0 = *(const float4*)&ip[lane * 4];
    float4 v1 = *(const float4*)&ip[128 + lane * 4];
    float s = v0.x + v0.y + v0.z + v0.w + v1.x + v1.y + v1.z + v1.w;
    #pragma unroll
    for (int o = 16; o > 0; o >>= 1) s += __shfl_xor_sync(0xffffffffu, s, o);
    float mean = s * (1.0f / 256.0f);
    float d0x = v0.x - mean, d0y = v0.y - mean, d0z = v0.z - mean, d0w = v0.w - mean;
    float d1x = v1.x - mean, d1y = v1.y - mean, d1z = v1.z - mean, d1w = v1.w - mean;
    float vs = d0x*d0x + d0y*d0y + d0z*d0z + d0w*d0w + d1x*d1x + d1y*d1y + d1z*d1z + d1w*d1w;
    #pragma unroll
    for (int o = 16; o > 0; o >>= 1) vs += __shfl_xor_sync(0xffffffffu, vs, o);
    if (lane == 0) {
        mu[row] = mean;
        rs[row] = rsqrtf(vs * (1.0f / 256.0f) + 1e-12f);
    }
}

// ------------------------- fp16 / tf32 helpers -------------------------
__device__ __forceinline__ unsigned f2tf(float f) {
    unsigned r;
    asm("cvt.rna.tf32.f32 %0, %1;" : "=r"(r) : "f"(f));
    return r;
}

// pack two floats into half2 word: low = lo, high = hi (round-to-nearest)
__device__ __forceinline__ unsigned pack_h2(float lo, float hi) {
    unsigned u;
    asm("cvt.rn.f16x2.f32 %0, %1, %2;" : "=r"(u) : "f"(hi), "f"(lo));
    return u;
}

__device__ __forceinline__ void mma_tf32(float c[4],
                                         unsigned a0, unsigned a1, unsigned a2, unsigned a3,
                                         unsigned b0, unsigned b1) {
    asm volatile(
        "mma.sync.aligned.m16n8k8.row.col.f32.tf32.tf32.f32 "
        "{%0,%1,%2,%3}, {%4,%5,%6,%7}, {%8,%9}, {%0,%1,%2,%3};"
        : "+f"(c[0]), "+f"(c[1]), "+f"(c[2]), "+f"(c[3])
        : "r"(a0), "r"(a1), "r"(a2), "r"(a3), "r"(b0), "r"(b1));
}

__device__ __forceinline__ void mma_f16(float c[4],
                                        unsigned a0, unsigned a1, unsigned a2, unsigned a3,
                                        unsigned b0, unsigned b1) {
    asm volatile(
        "mma.sync.aligned.m16n8k16.row.col.f32.f16.f16.f32 "
        "{%0,%1,%2,%3}, {%4,%5,%6,%7}, {%8,%9}, {%0,%1,%2,%3};"
        : "+f"(c[0]), "+f"(c[1]), "+f"(c[2]), "+f"(c[3])
        : "r"(a0), "r"(a1), "r"(a2), "r"(a3), "r"(b0), "r"(b1));
}

// ------------------------- FP16 GEMM, BM=128 BN=64 BK=32, reg-prefetch pipeline ------------
// Operands half2-packed along K: row entry k2 holds (k=2*k2 low, k=2*k2+1 high).
// Per 32-K chunk: 2 MMA k-steps of m16n8k16. C-layout identical to tf32 path.
// Optional fused LayerNorm on A (vec path).
#define STRH 20   // 16 h2 words per 32-K chunk + 4 pad; gcd(20,32)=4 -> conflict-free frags
__device__ __forceinline__ void tg128_body(
    const float* __restrict__ A, const float* __restrict__ Bm,
    const float* __restrict__ bias, const float* __restrict__ R,
    float* __restrict__ C, int N, int K, int mode, int r0, int c0,
    const float* __restrict__ mu, const float* __restrict__ rs,
    const float* __restrict__ lg, const float* __restrict__ lb)
{
    __shared__ unsigned As[128 * STRH];
    __shared__ unsigned Bs[64 * STRH];

    int tid = threadIdx.x;
    int lane = tid & 31, warp = tid >> 5;
    int wm = warp >> 1, wn = warp & 1;
    int g = lane >> 2, tg = lane & 3;

    const float* Ab = A + (size_t)r0 * K;
    const float* Bb = Bm + (size_t)c0 * K;

    float acc[2][4][4];
    #pragma unroll
    for (int mt = 0; mt < 2; mt++)
        #pragma unroll
        for (int nt = 0; nt < 4; nt++)
            #pragma unroll
            for (int e = 0; e < 4; e++) acc[mt][nt][e] = 0.0f;

    float muv[4], rsv[4];
    if (lg) {
        #pragma unroll
        for (int i = 0; i < 4; i++) {
            int r = (tid + i * 256) >> 3;
            muv[i] = mu[r0 + r];
            rsv[i] = rs[r0 + r];
        }
    }

    auto do_mma = [&]() {
        #pragma unroll
        for (int kc = 0; kc < 2; kc++) {
            int ko = kc * 8;
            unsigned a[2][4], b[4][2];
            #pragma unroll
            for (int mt = 0; mt < 2; mt++) {
                int row = wm * 32 + mt * 16 + g;
                a[mt][0] = As[row * STRH + ko + tg];
                a[mt][1] = As[(row + 8) * STRH + ko + tg];
                a[mt][2] = As[row * STRH + ko + tg + 4];
                a[mt][3] = As[(row + 8) * STRH + ko + tg + 4];
            }
            #pragma unroll
            for (int nt = 0; nt < 4; nt++) {
                int col = wn * 32 + nt * 8 + g;
                b[nt][0] = Bs[col * STRH + ko + tg];
                b[nt][1] = Bs[col * STRH + ko + tg + 4];
            }
            #pragma unroll
            for (int mt = 0; mt < 2; mt++)
                #pragma unroll
                for (int nt = 0; nt < 4; nt++)
                    mma_f16(acc[mt][nt], a[mt][0], a[mt][1], a[mt][2], a[mt][3],
                            b[nt][0], b[nt][1]);
        }
    };

    auto store_a = [&](float4 av, int i, int kbase) {
        int idx = tid + i * 256, r = idx >> 3, c4 = idx & 7;
        if (lg) {
            float4 ga = *(const float4*)&lg[kbase + c4 * 4];
            float4 be = *(const float4*)&lb[kbase + c4 * 4];
            float m = muv[i], rr = rsv[i];
            av.x = (av.x - m) * rr * ga.x + be.x;
            av.y = (av.y - m) * rr * ga.y + be.y;
            av.z = (av.z - m) * rr * ga.z + be.z;
            av.w = (av.w - m) * rr * ga.w + be.w;
        }
        unsigned* ap = &As[r * STRH + c4 * 2];
        ap[0] = pack_h2(av.x, av.y);
        ap[1] = pack_h2(av.z, av.w);
    };

    if ((K & 31) == 0) {
        int nch = K >> 5;
        float4 pa[4], pb[2];
        #pragma unroll
        for (int i = 0; i < 4; i++) {
            int idx = tid + i * 256, r = idx >> 3, c4 = idx & 7;
            pa[i] = *(const float4*)&Ab[(size_t)r * K + c4 * 4];
        }
        #pragma unroll
        for (int i = 0; i < 2; i++) {
            int idx = tid + i * 256, r = idx >> 3, c4 = idx & 7;
            pb[i] = *(const float4*)&Bb[(size_t)r * K + c4 * 4];
        }
        #pragma unroll
        for (int i = 0; i < 4; i++) store_a(pa[i], i, 0);
        #pragma unroll
        for (int i = 0; i < 2; i++) {
            int idx = tid + i * 256, r = idx >> 3, c4 = idx & 7;
            unsigned* bp = &Bs[r * STRH + c4 * 2];
            bp[0] = pack_h2(pb[i].x, pb[i].y);
            bp[1] = pack_h2(pb[i].z, pb[i].w);
        }
        __syncthreads();

        for (int ch = 0; ch < nch; ch++) {
            bool more = (ch + 1 < nch);
            int k1 = (ch + 1) << 5;
            if (more) {
                #pragma unroll
                for (int i = 0; i < 4; i++) {
                    int idx = tid + i * 256, r = idx >> 3, c4 = idx & 7;
                    pa[i] = *(const float4*)&Ab[(size_t)r * K + k1 + c4 * 4];
                }
                #pragma unroll
                for (int i = 0; i < 2; i++) {
                    int idx = tid + i * 256, r = idx >> 3, c4 = idx & 7;
                    pb[i] = *(const float4*)&Bb[(size_t)r * K + k1 + c4 * 4];
                }
            }
            do_mma();
            if (more) {
                __syncthreads();
                #pragma unroll
                for (int i = 0; i < 4; i++) store_a(pa[i], i, k1);
                #pragma unroll
                for (int i = 0; i < 2; i++) {
                    int idx = tid + i * 256, r = idx >> 3, c4 = idx & 7;
                    unsigned* bp = &Bs[r * STRH + c4 * 2];
                    bp[0] = pack_h2(pb[i].x, pb[i].y);
                    bp[1] = pack_h2(pb[i].z, pb[i].w);
                }
                __syncthreads();
            }
        }
    } else {
        // guarded scalar path (embed GEMM, K=1799) — no LN fusion here
        for (int k0 = 0; k0 < K; k0 += 32) {
            #pragma unroll
            for (int i = 0; i < 8; i++) {
                int idx = tid + i * 256, r = idx >> 4, c2 = idx & 15;
                int kk = k0 + c2 * 2;
                float f0 = (kk < K)     ? Ab[(size_t)r * K + kk]     : 0.0f;
                float f1 = (kk + 1 < K) ? Ab[(size_t)r * K + kk + 1] : 0.0f;
                As[r * STRH + c2] = pack_h2(f0, f1);
            }
            #pragma unroll
            for (int i = 0; i < 4; i++) {
                int idx = tid + i * 256, r = idx >> 4, c2 = idx & 15;
                int kk = k0 + c2 * 2;
                float f0 = (kk < K)     ? Bb[(size_t)r * K + kk]     : 0.0f;
                float f1 = (kk + 1 < K) ? Bb[(size_t)r * K + kk + 1] : 0.0f;
                Bs[r * STRH + c2] = pack_h2(f0, f1);
            }
            __syncthreads();
            do_mma();
            __syncthreads();
        }
    }

    #pragma unroll
    for (int mt = 0; mt < 2; mt++) {
        int row = r0 + wm * 32 + mt * 16 + g;
        #pragma unroll
        for (int nt = 0; nt < 4; nt++) {
            int col = c0 + wn * 32 + nt * 8 + 2 * tg;
            float2 bi = *(const float2*)&bias[col];
            #pragma unroll
            for (int half = 0; half < 2; half++) {
                int rr = row + half * 8;
                float x0 = acc[mt][nt][half * 2 + 0] + bi.x;
                float x1 = acc[mt][nt][half * 2 + 1] + bi.y;
                if (mode & 2) {
                    float2 rv = *(const float2*)&R[(size_t)rr * N + col];
                    x0 += rv.x; x1 += rv.y;
                }
                if (mode & 1) { x0 = fmaxf(x0, 0.0f); x1 = fmaxf(x1, 0.0f); }
                float2 o2 = {x0, x1};
                *(float2*)&C[(size_t)rr * N + col] = o2;
            }
        }
    }
}

__global__ __launch_bounds__(256) void tgemm128(
    const float* __restrict__ A, const float* __restrict__ Bm,
    const float* __restrict__ bias, const float* __restrict__ R,
    float* __restrict__ C, int N, int K, int mode,
    const float* __restrict__ mu, const float* __restrict__ rs,
    const float* __restrict__ lg, const float* __restrict__ lb)
{
    tg128_body(A, Bm, bias, R, C, N, K, mode, blockIdx.y * 128, blockIdx.x * 64,
               mu, rs, lg, lb);
}

__global__ __launch_bounds__(256) void tgemm128_qkv(
    const float* __restrict__ A,
    const float* __restrict__ Wq, const float* __restrict__ Wk, const float* __restrict__ Wv,
    const float* __restrict__ bq, const float* __restrict__ bk, const float* __restrict__ bv,
    float* __restrict__ q, float* __restrict__ k, float* __restrict__ v,
    const float* __restrict__ mu, const float* __restrict__ rs,
    const float* __restrict__ lg, const float* __restrict__ lb)
{
    const float* W; const float* bi; float* C;
    if (blockIdx.z == 0)      { W = Wq; bi = bq; C = q; }
    else if (blockIdx.z == 1) { W = Wk; bi = bk; C = k; }
    else                      { W = Wv; bi = bv; C = v; }
    tg128_body(A, W, bi, nullptr, C, D_, D_, 0, blockIdx.y * 128, blockIdx.x * 64,
               mu, rs, lg, lb);
}

// ------------------------- FP16 GEMM, BM=128 BN=128 BK=32 (for FF1) -------------------------
// 256 threads = 8 warps (2m x 4n), warp tile 64x32. Optional fused LN on A.
__global__ __launch_bounds__(256) void tgemm256(
    const float* __restrict__ A, const float* __restrict__ Bm,
    const float* __restrict__ bias, float* __restrict__ C,
    int N, int K, int mode,
    const float* __restrict__ mu, const float* __restrict__ rs,
    const float* __restrict__ lg, const float* __restrict__ lb)
{
    __shared__ unsigned As[128 * STRH];
    __shared__ unsigned Bs[128 * STRH];

    int tid = threadIdx.x;
    int lane = tid & 31, warp = tid >> 5;
    int wm = warp >> 2, wn = warp & 3;
    int g = lane >> 2, tg = lane & 3;

    int r0 = blockIdx.y * 128, c0 = blockIdx.x * 128;
    const float* Ab = A + (size_t)r0 * K;
    const float* Bb = Bm + (size_t)c0 * K;

    float acc[4][4][4];
    #pragma unroll
    for (int mt = 0; mt < 4; mt++)
        #pragma unroll
        for (int nt = 0; nt < 4; nt++)
            #pragma unroll
            for (int e = 0; e < 4; e++) acc[mt][nt][e] = 0.0f;

    float muv[4], rsv[4];
    if (lg) {
        #pragma unroll
        for (int i = 0; i < 4; i++) {
            int r = (tid + i * 256) >> 3;
            muv[i] = mu[r0 + r];
            rsv[i] = rs[r0 + r];
        }
    }

    for (int k0 = 0; k0 < K; k0 += 32) {
        #pragma unroll
        for (int i = 0; i < 4; i++) {
            int idx = tid + i * 256, r = idx >> 3, c4 = idx & 7;
            float4 av = *(const float4*)&Ab[(size_t)r * K + k0 + c4 * 4];
            if (lg) {
                float4 ga = *(const float4*)&lg[k0 + c4 * 4];
                float4 be = *(const float4*)&lb[k0 + c4 * 4];
                float m = muv[i], rr = rsv[i];
                av.x = (av.x - m) * rr * ga.x + be.x;
                av.y = (av.y - m) * rr * ga.y + be.y;
                av.z = (av.z - m) * rr * ga.z + be.z;
                av.w = (av.w - m) * rr * ga.w + be.w;
            }
            unsigned* ap = &As[r * STRH + c4 * 2];
            ap[0] = pack_h2(av.x, av.y);
            ap[1] = pack_h2(av.z, av.w);
        }
        #pragma unroll
        for (int i = 0; i < 4; i++) {
            int idx = tid + i * 256, r = idx >> 3, c4 = idx & 7;
            float4 bv = *(const float4*)&Bb[(size_t)r * K + k0 + c4 * 4];
            unsigned* bp = &Bs[r * STRH + c4 * 2];
            bp[0] = pack_h2(bv.x, bv.y);
            bp[1] = pack_h2(bv.z, bv.w);
        }
        __syncthreads();

        #pragma unroll
        for (int kc = 0; kc < 2; kc++) {
            int ko = kc * 8;
            unsigned a[4][4], b[4][2];
            #pragma unroll
            for (int mt = 0; mt < 4; mt++) {
                int row = wm * 64 + mt * 16 + g;
                a[mt][0] = As[row * STRH + ko + tg];
                a[mt][1] = As[(row + 8) * STRH + ko + tg];
                a[mt][2] = As[row * STRH + ko + tg + 4];
                a[mt][3] = As[(row + 8) * STRH + ko + tg + 4];
            }
            #pragma unroll
            for (int nt = 0; nt < 4; nt++) {
                int col = wn * 32 + nt * 8 + g;
                b[nt][0] = Bs[col * STRH + ko + tg];
                b[nt][1] = Bs[col * STRH + ko + tg + 4];
            }
            #pragma unroll
            for (int mt = 0; mt < 4; mt++)
                #pragma unroll
                for (int nt = 0; nt < 4; nt++)
                    mma_f16(acc[mt][nt], a[mt][0], a[mt][1], a[mt][2], a[mt][3],
                            b[nt][0], b[nt][1]);
        }
        __syncthreads();
    }

    #pragma unroll
    for (int mt = 0; mt < 4; mt++) {
        int row = r0 + wm * 64 + mt * 16 + g;
        #pragma unroll
        for (int nt = 0; nt < 4; nt++) {
            int col = c0 + wn * 32 + nt * 8 + 2 * tg;
            float2 bi = *(const float2*)&bias[col];
            #pragma unroll
            for (int half = 0; half < 2; half++) {
                int rr = row + half * 8;
                float x0 = acc[mt][nt][half * 2 + 0] + bi.x;
                float x1 = acc[mt][nt][half * 2 + 1] + bi.y;
                if (mode & 1) { x0 = fmaxf(x0, 0.0f); x1 = fmaxf(x1, 0.0f); }
                float2 o2 = {x0, x1};
                *(float2*)&C[(size_t)rr * N + col] = o2;
            }
        }
    }
}

// ------------------------- fully fused flash attention (tf32, unchanged) -------------------------
#define KSTR 68
#define VSTR 37
#define VPANE 2368   // words per V half-pane (64*37)
#define FLASH_SMEM 73216
__global__ __launch_bounds__(128) void flash_attn(
    const float* __restrict__ q, const float* __restrict__ k,
    const float* __restrict__ v, const float* __restrict__ pkn_l,
    const int* __restrict__ masks, float* __restrict__ o)
{
    extern __shared__ char sbuf[];
    unsigned* Vs = (unsigned*)sbuf;
    unsigned* Ks = (unsigned*)(sbuf + 18944);
    unsigned* Ps = (unsigned*)(sbuf + 36352);
    float*    Rs = (float*)(sbuf + 18944);
    unsigned* Ru = (unsigned*)(sbuf + 18944);
    int*      msk = (int*)(sbuf + 71168);

    int tid = threadIdx.x;
    int lane = tid & 31, warp = tid >> 5;
    int g = lane >> 2, tg = lane & 3;
    int rl0 = warp * 16 + g, rl1 = rl0 + 8;

    int t0 = blockIdx.x * 64, bh = blockIdx.y;
    int b = bh >> 2, h = bh & 3;
    const float* qb  = q + ((size_t)(b * T_ + t0)) * D_ + h * DK;
    const float* kb0 = k + ((size_t)(b * T_)) * D_ + h * DK;
    const float* vb0 = v + ((size_t)(b * T_)) * D_ + h * DK;

    #pragma unroll
    for (int i = 0; i < 4; i++) msk[tid + i * 128] = masks[b * T_ + tid + i * 128];
    #pragma unroll
    for (int i = 0; i < 8; i++) {
        int idx = tid + i * 128, r = idx >> 4, c4 = idx & 15;
        float4 qv = *(const float4*)&qb[(size_t)r * D_ + c4 * 4];
        unsigned* p = &Ks[r * KSTR + c4 * 4];
        p[0] = f2tf(qv.x); p[1] = f2tf(qv.y); p[2] = f2tf(qv.z); p[3] = f2tf(qv.w);
    }
    __syncthreads();
    unsigned qa[8][4];
    #pragma unroll
    for (int kc = 0; kc < 8; kc++) {
        qa[kc][0] = Ks[rl0 * KSTR + kc * 8 + tg];
        qa[kc][1] = Ks[rl1 * KSTR + kc * 8 + tg];
        qa[kc][2] = Ks[rl0 * KSTR + kc * 8 + tg + 4];
        qa[kc][3] = Ks[rl1 * KSTR + kc * 8 + tg + 4];
    }
    __syncthreads();

    float accO[8][4];
    #pragma unroll
    for (int nt = 0; nt < 8; nt++)
        #pragma unroll
        for (int e = 0; e < 4; e++) accO[nt][e] = 0.0f;
    float m0 = -FLT_MAX, m1 = -FLT_MAX, l0 = 0.0f, l1 = 0.0f;

    const float scale = 0.125f;

    for (int sc = 0; sc < 8; sc++) {
        int s0 = sc * 64;
        #pragma unroll
        for (int i = 0; i < 8; i++) {
            int idx = tid + i * 128, r = idx >> 4, c4 = idx & 15;
            float4 kv = *(const float4*)&kb0[(size_t)(s0 + r) * D_ + c4 * 4];
            unsigned* p = &Ks[r * KSTR + c4 * 4];
            p[0] = f2tf(kv.x); p[1] = f2tf(kv.y); p[2] = f2tf(kv.z); p[3] = f2tf(kv.w);
        }
        #pragma unroll
        for (int i = 0; i < 8; i++) {
            int idx = tid + i * 128, r = idx >> 4, c4 = idx & 15;
            int half = r >> 5, rsl = r & 31;
            unsigned* vp = &Vs[half * VPANE];
            float4 vv = *(const float4*)&vb0[(size_t)(s0 + r) * D_ + c4 * 4];
            vp[(c4 * 4 + 0) * VSTR + rsl] = f2tf(vv.x);
            vp[(c4 * 4 + 1) * VSTR + rsl] = f2tf(vv.y);
            vp[(c4 * 4 + 2) * VSTR + rsl] = f2tf(vv.z);
            vp[(c4 * 4 + 3) * VSTR + rsl] = f2tf(vv.w);
        }
        const float* pb = pkn_l + (size_t)(t0 - s0 + 448) * DK;
        #pragma unroll
        for (int i = 0; i < 16; i++) {
            int idx = tid + i * 128, r = idx >> 4, c4 = idx & 15;
            unsigned* p = &Ps[r * KSTR + c4 * 4];
            if (r < 127) {
                float4 pv = *(const float4*)&pb[(size_t)r * DK + c4 * 4];
                p[0] = f2tf(pv.x); p[1] = f2tf(pv.y); p[2] = f2tf(pv.z); p[3] = f2tf(pv.w);
            } else {
                p[0] = 0u; p[1] = 0u; p[2] = 0u; p[3] = 0u;
            }
        }
        __syncthreads();

        float accS[8][4], accR[16][4];
        #pragma unroll
        for (int nt = 0; nt < 8; nt++)
            #pragma unroll
            for (int e = 0; e < 4; e++) accS[nt][e] = 0.0f;
        #pragma unroll
        for (int nt = 0; nt < 16; nt++)
            #pragma unroll
            for (int e = 0; e < 4; e++) accR[nt][e] = 0.0f;

        #pragma unroll
        for (int kc = 0; kc < 8; kc++) {
            int ko = kc * 8;
            #pragma unroll
            for (int nt = 0; nt < 8; nt++) {
                int col = nt * 8 + g;
                unsigned b0 = Ks[col * KSTR + ko + tg];
                unsigned b1 = Ks[col * KSTR + ko + tg + 4];
                mma_tf32(accS[nt], qa[kc][0], qa[kc][1], qa[kc][2], qa[kc][3], b0, b1);
            }
            #pragma unroll
            for (int nt = 0; nt < 16; nt++) {
                int col = nt * 8 + g;
                unsigned b0 = Ps[col * KSTR + ko + tg];
                unsigned b1 = Ps[col * KSTR + ko + tg + 4];
                mma_tf32(accR[nt], qa[kc][0], qa[kc][1], qa[kc][2], qa[kc][3], b0, b1);
            }
        }
        __syncthreads();

        #pragma unroll
        for (int nt = 0; nt < 16; nt++) {
            int col = nt * 8 + 2 * tg;
            Rs[rl0 * 132 + col]     = accR[nt][0];
            Rs[rl0 * 132 + col + 1] = accR[nt][1];
            Rs[rl1 * 132 + col]     = accR[nt][2];
            Rs[rl1 * 132 + col + 1] = accR[nt][3];
        }
        __syncwarp();

        #pragma unroll
        for (int nt = 0; nt < 8; nt++) {
            #pragma unroll
            for (int e = 0; e < 2; e++) {
                int c = nt * 8 + 2 * tg + e;
                float r0 = Rs[rl0 * 132 + (rl0 - c + 63)];
                float r1 = Rs[rl1 * 132 + (rl1 - c + 63)];
                float x0 = (accS[nt][e] + r0) * scale;
                float x1 = (accS[nt][2 + e] + r1) * scale;
                if (msk[s0 + c] == 0) { x0 = -FLT_MAX; x1 = -FLT_MAX; }
                accS[nt][e] = x0;
                accS[nt][2 + e] = x1;
            }
        }
        __syncwarp();

        float cm0 = -FLT_MAX, cm1 = -FLT_MAX;
        #pragma unroll
        for (int nt = 0; nt < 8; nt++) {
            cm0 = fmaxf(cm0, fmaxf(accS[nt][0], accS[nt][1]));
            cm1 = fmaxf(cm1, fmaxf(accS[nt][2], accS[nt][3]));
        }
        cm0 = fmaxf(cm0, __shfl_xor_sync(0xffffffffu, cm0, 1));
        cm0 = fmaxf(cm0, __shfl_xor_sync(0xffffffffu, cm0, 2));
        cm1 = fmaxf(cm1, __shfl_xor_sync(0xffffffffu, cm1, 1));
        cm1 = fmaxf(cm1, __shfl_xor_sync(0xffffffffu, cm1, 2));

        float nm0 = fmaxf(m0, cm0), nm1 = fmaxf(m1, cm1);
        float al0 = __expf(m0 - nm0), al1 = __expf(m1 - nm1);
        float cs0 = 0.0f, cs1 = 0.0f;
        #pragma unroll
        for (int nt = 0; nt < 8; nt++) {
            accS[nt][0] = __expf(accS[nt][0] - nm0);
            accS[nt][1] = __expf(accS[nt][1] - nm0);
            accS[nt][2] = __expf(accS[nt][2] - nm1);
            accS[nt][3] = __expf(accS[nt][3] - nm1);
            cs0 += accS[nt][0] + accS[nt][1];
            cs1 += accS[nt][2] + accS[nt][3];
        }
        cs0 += __shfl_xor_sync(0xffffffffu, cs0, 1);
        cs0 += __shfl_xor_sync(0xffffffffu, cs0, 2);
        cs1 += __shfl_xor_sync(0xffffffffu, cs1, 1);
        cs1 += __shfl_xor_sync(0xffffffffu, cs1, 2);
        l0 = l0 * al0 + cs0;
        l1 = l1 * al1 + cs1;
        m0 = nm0; m1 = nm1;

        #pragma unroll
        for (int nt = 0; nt < 8; nt++) {
            accO[nt][0] *= al0; accO[nt][1] *= al0;
            accO[nt][2] *= al1; accO[nt][3] *= al1;
        }

        #pragma unroll
        for (int nt = 0; nt < 8; nt++) {
            int col = nt * 8 + 2 * tg;
            Ru[rl0 * 132 + col]     = f2tf(accS[nt][0]);
            Ru[rl0 * 132 + col + 1] = f2tf(accS[nt][1]);
            Ru[rl1 * 132 + col]     = f2tf(accS[nt][2]);
            Ru[rl1 * 132 + col + 1] = f2tf(accS[nt][3]);
        }
        __syncwarp();

        #pragma unroll
        for (int kc = 0; kc < 8; kc++) {
            int ko = kc * 8;
            const unsigned* vp = &Vs[(kc >> 2) * VPANE];
            int so = ko & 31;
            unsigned a0 = Ru[rl0 * 132 + ko + tg];
            unsigned a1 = Ru[rl1 * 132 + ko + tg];
            unsigned a2 = Ru[rl0 * 132 + ko + tg + 4];
            unsigned a3 = Ru[rl1 * 132 + ko + tg + 4];
            #pragma unroll
            for (int nt = 0; nt < 8; nt++) {
                int col = nt * 8 + g;
                unsigned b0 = vp[col * VSTR + so + tg];
                unsigned b1 = vp[col * VSTR + so + tg + 4];
                mma_tf32(accO[nt], a0, a1, a2, a3, b0, b1);
            }
        }
        __syncthreads();
    }

    float inv0 = 1.0f / l0, inv1 = 1.0f / l1;
    #pragma unroll
    for (int nt = 0; nt < 8; nt++) {
        int col = nt * 8 + 2 * tg;
        float2 oa  = {accO[nt][0] * inv0, accO[nt][1] * inv0};
        float2 ob2 = {accO[nt][2] * inv1, accO[nt][3] * inv1};
        *(float2*)&o[((size_t)(b * T_ + t0 + rl0)) * D_ + h * DK + col] = oa;
        *(float2*)&o[((size_t)(b * T_ + t0 + rl1)) * D_ + h * DK + col] = ob2;
    }
}

// ------------------------- host orchestration -------------------------
extern "C" void kernel_launch(void* const* d_in, const int* in_sizes, int n_in,
                              void* d_out, int out_size) {
    const float* xs      = (const float*)d_in[0];
    const int*   masks   = (const int*)  d_in[1];
    const float* emb_w   = (const float*)d_in[2];
    const float* emb_b   = (const float*)d_in[3];
    const float* emb_g   = (const float*)d_in[4];
    const float* emb_bt  = (const float*)d_in[5];
    const float* pe_k    = (const float*)d_in[6];
    const float* Wq      = (const float*)d_in[7];
    const float* bq      = (const float*)d_in[8];
    const float* Wk      = (const float*)d_in[9];
    const float* bk      = (const float*)d_in[10];
    const float* Wv      = (const float*)d_in[11];
    const float* bv      = (const float*)d_in[12];
    const float* Wo      = (const float*)d_in[13];
    const float* bo      = (const float*)d_in[14];
    const float* ln1_g   = (const float*)d_in[15];
    const float* ln1_b   = (const float*)d_in[16];
    const float* ln2_g   = (const float*)d_in[17];
    const float* ln2_b   = (const float*)d_in[18];
    const float* lnk_g   = (const float*)d_in[19];
    const float* lnk_b   = (const float*)d_in[20];
    const float* W1      = (const float*)d_in[21];
    const float* b1      = (const float*)d_in[22];
    const float* W2      = (const float*)d_in[23];
    const float* b2      = (const float*)d_in[24];
    const float* after_g = (const float*)d_in[25];
    const float* after_b = (const float*)d_in[26];
    float* out = (float*)d_out;

    float *x, *y, *q, *k, *v, *o, *ff, *pkn, *mu, *rs;
    cudaGetSymbolAddress((void**)&x,   g_x);
    cudaGetSymbolAddress((void**)&y,   g_y);
    cudaGetSymbolAddress((void**)&q,   g_q);
    cudaGetSymbolAddress((void**)&k,   g_k);
    cudaGetSymbolAddress((void**)&v,   g_v);
    cudaGetSymbolAddress((void**)&o,   g_o);
    cudaGetSymbolAddress((void**)&ff,  g_ff);
    cudaGetSymbolAddress((void**)&pkn, g_pkn);
    cudaGetSymbolAddress((void**)&mu,  g_mu);
    cudaGetSymbolAddress((void**)&rs,  g_rs);

    cudaFuncSetAttribute(flash_attn, cudaFuncAttributeMaxDynamicSharedMemorySize, FLASH_SMEM);

    dim3 gProj(D_ / 64, BT / 128);       // (4, 32)
    dim3 gQKV(D_ / 64, BT / 128, 3);     // (4, 32, 3)
    dim3 gFF1(FF_ / 128, BT / 128);      // (16, 32)

    // embed: GEMM + bias -> LN(+relu); pkn LN for all layers upfront
    tgemm128<<<gProj, 256>>>(xs, emb_w, emb_b, nullptr, y, D_, IDIM, 0,
                             nullptr, nullptr, nullptr, nullptr);
    ln_pkn_all<<<dim3(NPK, L_), 64>>>(pe_k, pkn, lnk_g, lnk_b);
    ln_warp<<<BT / 8, 256>>>(y, x, emb_g, emb_bt, 1);

    for (int l = 0; l < L_; l++) {
        // ln1 fused into QKV staging
        ln_stats<<<BT / 8, 256>>>(x, mu, rs);
        tgemm128_qkv<<<gQKV, 256>>>(x,
            Wq + (size_t)l * D_ * D_, Wk + (size_t)l * D_ * D_, Wv + (size_t)l * D_ * D_,
            bq + l * D_, bk + l * D_, bv + l * D_, q, k, v,
            mu, rs, ln1_g + l * D_, ln1_b + l * D_);

        flash_attn<<<dim3(8, BH), 128, FLASH_SMEM>>>(q, k, v, pkn + (size_t)l * NPK * DK, masks, o);

        tgemm128<<<gProj, 256>>>(o, Wo + (size_t)l * D_ * D_, bo + l * D_, x, x, D_, D_, 2,
                                 nullptr, nullptr, nullptr, nullptr);

        // ln2 fused into FF1 staging
        ln_stats<<<BT / 8, 256>>>(x, mu, rs);
        tgemm256<<<gFF1, 256>>>(x, W1 + (size_t)l * FF_ * D_, b1 + l * FF_, ff,
                                FF_, D_, 1, mu, rs, ln2_g + l * D_, ln2_b + l * D_);
        tgemm128<<<gProj, 256>>>(ff, W2 + (size_t)l * D_ * FF_, b2 + l * D_, x, x, D_, FF_, 2,
                                 nullptr, nullptr, nullptr, nullptr);
    }

    ln_warp<<<BT / 8, 256>>>(x, out, after_g, after_b, 0);
}

// round 14
// speedup vs baseline: 3.5117x; 1.2136x over previous
#include <cuda_runtime.h>
#include <cuda_fp16.h>
#include <math.h>
#include <float.h>

// Problem constants
#define B_    8
#define T_    512
#define IDIM  1799
#define D_    256
#define H_    4
#define FF_   2048
#define L_    16
#define DK    64
#define BT    (B_*T_)    // 4096
#define BH    (B_*H_)    // 32
#define NPK   1023       // distinct rel-pos rows: t-s+511 in [0,1022]

// ------------------------- scratch (device globals) -------------------------
__device__ float g_x[BT*D_];
__device__ float g_y[BT*D_];
__device__ float g_v[BT*D_];
__device__ float g_o[BT*D_];
__device__ float g_mu[BT];
__device__ float g_rs[BT];
__device__ __half g_qh[BT*D_];
__device__ __half g_kh[BT*D_];
__device__ __half g_ffh[(size_t)BT*FF_];
__device__ __half g_pkn[(size_t)L_*NPK*DK];
// fp16 weights
__device__ __half g_hemb[D_*IDIM];
__device__ __half g_hq[(size_t)L_*D_*D_];
__device__ __half g_hk[(size_t)L_*D_*D_];
__device__ __half g_hv[(size_t)L_*D_*D_];
__device__ __half g_ho[(size_t)L_*D_*D_];
__device__ __half g_h1[(size_t)L_*FF_*D_];
__device__ __half g_h2[(size_t)L_*D_*FF_];

// ------------------------- fp16 / tf32 helpers -------------------------
__device__ __forceinline__ unsigned f2tf(float f) {
    unsigned r;
    asm("cvt.rna.tf32.f32 %0, %1;" : "=r"(r) : "f"(f));
    return r;
}
__device__ __forceinline__ unsigned pack_h2(float lo, float hi) {
    unsigned u;
    asm("cvt.rn.f16x2.f32 %0, %1, %2;" : "=r"(u) : "f"(hi), "f"(lo));
    return u;
}
__device__ __forceinline__ void mma_tf32(float c[4],
                                         unsigned a0, unsigned a1, unsigned a2, unsigned a3,
                                         unsigned b0, unsigned b1) {
    asm volatile(
        "mma.sync.aligned.m16n8k8.row.col.f32.tf32.tf32.f32 "
        "{%0,%1,%2,%3}, {%4,%5,%6,%7}, {%8,%9}, {%0,%1,%2,%3};"
        : "+f"(c[0]), "+f"(c[1]), "+f"(c[2]), "+f"(c[3])
        : "r"(a0), "r"(a1), "r"(a2), "r"(a3), "r"(b0), "r"(b1));
}
__device__ __forceinline__ void mma_f16(float c[4],
                                        unsigned a0, unsigned a1, unsigned a2, unsigned a3,
                                        unsigned b0, unsigned b1) {
    asm volatile(
        "mma.sync.aligned.m16n8k16.row.col.f32.f16.f16.f32 "
        "{%0,%1,%2,%3}, {%4,%5,%6,%7}, {%8,%9}, {%0,%1,%2,%3};"
        : "+f"(c[0]), "+f"(c[1]), "+f"(c[2]), "+f"(c[3])
        : "r"(a0), "r"(a1), "r"(a2), "r"(a3), "r"(b0), "r"(b1));
}

// ------------------------- fp32 -> fp16 bulk convert -------------------------
__global__ __launch_bounds__(256) void f2h(const float* __restrict__ in,
                                           __half* __restrict__ out, int n4) {
    int i = blockIdx.x * 256 + threadIdx.x;
    if (i < n4) {
        float4 v = *(const float4*)&in[i * 4];
        uint2 o;
        o.x = pack_h2(v.x, v.y);
        o.y = pack_h2(v.z, v.w);
        *(uint2*)&out[i * 4] = o;
    }
}

// ------------------------- block reduction (for pkn LN only) -------------------------
__device__ __forceinline__ float block_sum64(float v) {
    __shared__ float sh[3];
    #pragma unroll
    for (int o = 16; o > 0; o >>= 1) v += __shfl_xor_sync(0xffffffffu, v, o);
    int lane = threadIdx.x & 31, w = threadIdx.x >> 5;
    if (lane == 0) sh[w] = v;
    __syncthreads();
    float out = sh[0] + sh[1];
    __syncthreads();
    return out;
}

// all-layers pkn LN -> fp16: grid (NPK, L), block 64
__global__ void ln_pkn_all(const float* __restrict__ pe_k, __half* __restrict__ pkn,
                           const float* __restrict__ lnk_g, const float* __restrict__ lnk_b) {
    int row = blockIdx.x, l = blockIdx.y;
    float x = pe_k[(size_t)(489 + row) * DK + threadIdx.x];
    float mean = block_sum64(x) / (float)DK;
    float d = x - mean;
    float var = block_sum64(d * d) / (float)DK;
    float y = d * rsqrtf(var + 1e-12f) * lnk_g[l * DK + threadIdx.x] + lnk_b[l * DK + threadIdx.x];
    pkn[((size_t)l * NPK + row) * DK + threadIdx.x] = __float2half_rn(y);
}

// ------------------------- warp-per-row LayerNorm, width 256 -------------------------
__global__ __launch_bounds__(256) void ln_warp(const float* __restrict__ in,
                                               float* __restrict__ out,
                                               const float* __restrict__ g,
                                               const float* __restrict__ bb,
                                               int relu) {
    int warp = threadIdx.x >> 5, lane = threadIdx.x & 31;
    size_t row = (size_t)blockIdx.x * 8 + warp;
    const float* ip = in + row * D_;
    float4 v0 = *(const float4*)&ip[lane * 4];
    float4 v1 = *(const float4*)&ip[128 + lane * 4];
    float s = v0.x + v0.y + v0.z + v0.w + v1.x + v1.y + v1.z + v1.w;
    #pragma unroll
    for (int o = 16; o > 0; o >>= 1) s += __shfl_xor_sync(0xffffffffu, s, o);
    float mean = s * (1.0f / 256.0f);
    float d0x = v0.x - mean, d0y = v0.y - mean, d0z = v0.z - mean, d0w = v0.w - mean;
    float d1x = v1.x - mean, d1y = v1.y - mean, d1z = v1.z - mean, d1w = v1.w - mean;
    float vs = d0x*d0x + d0y*d0y + d0z*d0z + d0w*d0w + d1x*d1x + d1y*d1y + d1z*d1z + d1w*d1w;
    #pragma unroll
    for (int o = 16; o > 0; o >>= 1) vs += __shfl_xor_sync(0xffffffffu, vs, o);
    float rstd = rsqrtf(vs * (1.0f / 256.0f) + 1e-12f);
    float4 g0 = *(const float4*)&g[lane * 4];
    float4 g1 = *(const float4*)&g[128 + lane * 4];
    float4 b0 = *(const float4*)&bb[lane * 4];
    float4 b1 = *(const float4*)&bb[128 + lane * 4];
    float4 o0, o1;
    o0.x = d0x * rstd * g0.x + b0.x;  o0.y = d0y * rstd * g0.y + b0.y;
    o0.z = d0z * rstd * g0.z + b0.z;  o0.w = d0w * rstd * g0.w + b0.w;
    o1.x = d1x * rstd * g1.x + b1.x;  o1.y = d1y * rstd * g1.y + b1.y;
    o1.z = d1z * rstd * g1.z + b1.z;  o1.w = d1w * rstd * g1.w + b1.w;
    if (relu) {
        o0.x = fmaxf(o0.x, 0.f); o0.y = fmaxf(o0.y, 0.f); o0.z = fmaxf(o0.z, 0.f); o0.w = fmaxf(o0.w, 0.f);
        o1.x = fmaxf(o1.x, 0.f); o1.y = fmaxf(o1.y, 0.f); o1.z = fmaxf(o1.z, 0.f); o1.w = fmaxf(o1.w, 0.f);
    }
    float* op = out + row * D_;
    *(float4*)&op[lane * 4] = o0;
    *(float4*)&op[128 + lane * 4] = o1;
}

// ------------------------- warp-per-row LN stats (mean, rstd) -------------------------
__global__ __launch_bounds__(256) void ln_stats(const float* __restrict__ in,
                                                float* __restrict__ mu,
                                                float* __restrict__ rs) {
    int warp = threadIdx.x >> 5, lane = threadIdx.x & 31;
    size_t row = (size_t)blockIdx.x * 8 + warp;
    const float* ip = in + row * D_;
    float4 v0 = *(const float4*)&ip[lane * 4];
    float4 v1 = *(const float4*)&ip[128 + lane * 4];
    float s = v0.x + v0.y + v0.z + v0.w + v1.x + v1.y + v1.z + v1.w;
    #pragma unroll
    for (int o = 16; o > 0; o >>= 1) s += __shfl_xor_sync(0xffffffffu, s, o);
    float mean = s * (1.0f / 256.0f);
    float d0x = v0.x - mean, d0y = v0.y - mean, d0z = v0.z - mean, d0w = v0.w - mean;
    float d1x = v1.x - mean, d1y = v1.y - mean, d1z = v1.z - mean, d1w = v1.w - mean;
    float vs = d0x*d0x + d0y*d0y + d0z*d0z + d0w*d0w + d1x*d1x + d1y*d1y + d1z*d1z + d1w*d1w;
    #pragma unroll
    for (int o = 16; o > 0; o >>= 1) vs += __shfl_xor_sync(0xffffffffu, vs, o);
    if (lane == 0) {
        mu[row] = mean;
        rs[row] = rsqrtf(vs * (1.0f / 256.0f) + 1e-12f);
    }
}

// ------------------------- FP16 GEMM body, BM=128 BN=64 BK=32 -------------------------
// B always fp16 (pre-converted weights). A fp32 (+opt LN) or fp16 (template AH).
// C fp32 (+opt residual) or fp16 (runtime c_half).
#define STRH 20
template<bool AH>
__device__ __forceinline__ void tg128_body(
    const void* __restrict__ Ap, const __half* __restrict__ Bm,
    const float* __restrict__ bias, const float* __restrict__ R,
    void* __restrict__ Cp, int N, int K, int mode, int c_half, int r0, int c0,
    const float* __restrict__ mu, const float* __restrict__ rs,
    const float* __restrict__ lg, const float* __restrict__ lb)
{
    __shared__ unsigned As[128 * STRH];
    __shared__ unsigned Bs[64 * STRH];

    int tid = threadIdx.x;
    int lane = tid & 31, warp = tid >> 5;
    int wm = warp >> 1, wn = warp & 1;
    int g = lane >> 2, tg = lane & 3;

    const float*  Af = AH ? nullptr : (const float*)Ap + (size_t)r0 * K;
    const __half* Ah = AH ? (const __half*)Ap + (size_t)r0 * K : nullptr;
    const __half* Bb = Bm + (size_t)c0 * K;

    float acc[2][4][4];
    #pragma unroll
    for (int mt = 0; mt < 2; mt++)
        #pragma unroll
        for (int nt = 0; nt < 4; nt++)
            #pragma unroll
            for (int e = 0; e < 4; e++) acc[mt][nt][e] = 0.0f;

    float muv[4], rsv[4];
    if (!AH && lg) {
        #pragma unroll
        for (int i = 0; i < 4; i++) {
            int r = (tid + i * 256) >> 3;
            muv[i] = mu[r0 + r];
            rsv[i] = rs[r0 + r];
        }
    }

    auto do_mma = [&]() {
        #pragma unroll
        for (int kc = 0; kc < 2; kc++) {
            int ko = kc * 8;
            unsigned a[2][4], b[4][2];
            #pragma unroll
            for (int mt = 0; mt < 2; mt++) {
                int row = wm * 32 + mt * 16 + g;
                a[mt][0] = As[row * STRH + ko + tg];
                a[mt][1] = As[(row + 8) * STRH + ko + tg];
                a[mt][2] = As[row * STRH + ko + tg + 4];
                a[mt][3] = As[(row + 8) * STRH + ko + tg + 4];
            }
            #pragma unroll
            for (int nt = 0; nt < 4; nt++) {
                int col = wn * 32 + nt * 8 + g;
                b[nt][0] = Bs[col * STRH + ko + tg];
                b[nt][1] = Bs[col * STRH + ko + tg + 4];
            }
            #pragma unroll
            for (int mt = 0; mt < 2; mt++)
                #pragma unroll
                for (int nt = 0; nt < 4; nt++)
                    mma_f16(acc[mt][nt], a[mt][0], a[mt][1], a[mt][2], a[mt][3],
                            b[nt][0], b[nt][1]);
        }
    };

    if ((K & 31) == 0) {
        int nch = K >> 5;
        // B prefetch: 64 rows x 4 uint4 per chunk = 256 -> 1 per thread
        int br = tid >> 2, bc8 = tid & 3;
        uint4 pbh = *(const uint4*)&Bb[(size_t)br * K + bc8 * 8];

        if (AH) {
            // A: 128 rows x 4 uint4 = 512 -> 2 per thread
            uint4 pah[2];
            #pragma unroll
            for (int i = 0; i < 2; i++) {
                int idx = tid + i * 256, r = idx >> 2, c8 = idx & 3;
                pah[i] = *(const uint4*)&Ah[(size_t)r * K + c8 * 8];
            }
            #pragma unroll
            for (int i = 0; i < 2; i++) {
                int idx = tid + i * 256, r = idx >> 2, c8 = idx & 3;
                *(uint4*)&As[r * STRH + c8 * 4] = pah[i];
            }
            *(uint4*)&Bs[br * STRH + bc8 * 4] = pbh;
            __syncthreads();
            for (int ch = 0; ch < nch; ch++) {
                bool more = (ch + 1 < nch);
                int k1 = (ch + 1) << 5;
                if (more) {
                    #pragma unroll
                    for (int i = 0; i < 2; i++) {
                        int idx = tid + i * 256, r = idx >> 2, c8 = idx & 3;
                        pah[i] = *(const uint4*)&Ah[(size_t)r * K + k1 + c8 * 8];
                    }
                    pbh = *(const uint4*)&Bb[(size_t)br * K + k1 + bc8 * 8];
                }
                do_mma();
                if (more) {
                    __syncthreads();
                    #pragma unroll
                    for (int i = 0; i < 2; i++) {
                        int idx = tid + i * 256, r = idx >> 2, c8 = idx & 3;
                        *(uint4*)&As[r * STRH + c8 * 4] = pah[i];
                    }
                    *(uint4*)&Bs[br * STRH + bc8 * 4] = pbh;
                    __syncthreads();
                }
            }
        } else {
            float4 pa[4];
            #pragma unroll
            for (int i = 0; i < 4; i++) {
                int idx = tid + i * 256, r = idx >> 3, c4 = idx & 7;
                pa[i] = *(const float4*)&Af[(size_t)r * K + c4 * 4];
            }
            auto store_a = [&](float4 av, int i, int kbase) {
                int idx = tid + i * 256, r = idx >> 3, c4 = idx & 7;
                if (lg) {
                    float4 ga = *(const float4*)&lg[kbase + c4 * 4];
                    float4 be = *(const float4*)&lb[kbase + c4 * 4];
                    float m = muv[i], rr = rsv[i];
                    av.x = (av.x - m) * rr * ga.x + be.x;
                    av.y = (av.y - m) * rr * ga.y + be.y;
                    av.z = (av.z - m) * rr * ga.z + be.z;
                    av.w = (av.w - m) * rr * ga.w + be.w;
                }
                unsigned* ap = &As[r * STRH + c4 * 2];
                ap[0] = pack_h2(av.x, av.y);
                ap[1] = pack_h2(av.z, av.w);
            };
            #pragma unroll
            for (int i = 0; i < 4; i++) store_a(pa[i], i, 0);
            *(uint4*)&Bs[br * STRH + bc8 * 4] = pbh;
            __syncthreads();
            for (int ch = 0; ch < nch; ch++) {
                bool more = (ch + 1 < nch);
                int k1 = (ch + 1) << 5;
                if (more) {
                    #pragma unroll
                    for (int i = 0; i < 4; i++) {
                        int idx = tid + i * 256, r = idx >> 3, c4 = idx & 7;
                        pa[i] = *(const float4*)&Af[(size_t)r * K + k1 + c4 * 4];
                    }
                    pbh = *(const uint4*)&Bb[(size_t)br * K + k1 + bc8 * 8];
                }
                do_mma();
                if (more) {
                    __syncthreads();
                    #pragma unroll
                    for (int i = 0; i < 4; i++) store_a(pa[i], i, k1);
                    *(uint4*)&Bs[br * STRH + bc8 * 4] = pbh;
                    __syncthreads();
                }
            }
        }
    } else {
        // guarded scalar path (embed GEMM, K=1799): A fp32, B fp16
        for (int k0 = 0; k0 < K; k0 += 32) {
            #pragma unroll
            for (int i = 0; i < 8; i++) {
                int idx = tid + i * 256, r = idx >> 4, c2 = idx & 15;
                int kk = k0 + c2 * 2;
                float f0 = (kk < K)     ? Af[(size_t)r * K + kk]     : 0.0f;
                float f1 = (kk + 1 < K) ? Af[(size_t)r * K + kk + 1] : 0.0f;
                As[r * STRH + c2] = pack_h2(f0, f1);
            }
            #pragma unroll
            for (int i = 0; i < 4; i++) {
                int idx = tid + i * 256, r = idx >> 4, c2 = idx & 15;
                int kk = k0 + c2 * 2;
                float f0 = (kk < K)     ? __half2float(Bb[(size_t)r * K + kk])     : 0.0f;
                float f1 = (kk + 1 < K) ? __half2float(Bb[(size_t)r * K + kk + 1]) : 0.0f;
                Bs[r * STRH + c2] = pack_h2(f0, f1);
            }
            __syncthreads();
            do_mma();
            __syncthreads();
        }
    }

    #pragma unroll
    for (int mt = 0; mt < 2; mt++) {
        int row = r0 + wm * 32 + mt * 16 + g;
        #pragma unroll
        for (int nt = 0; nt < 4; nt++) {
            int col = c0 + wn * 32 + nt * 8 + 2 * tg;
            float2 bi = *(const float2*)&bias[col];
            #pragma unroll
            for (int half = 0; half < 2; half++) {
                int rr = row + half * 8;
                float x0 = acc[mt][nt][half * 2 + 0] + bi.x;
                float x1 = acc[mt][nt][half * 2 + 1] + bi.y;
                if (mode & 2) {
                    float2 rv = *(const float2*)&R[(size_t)rr * N + col];
                    x0 += rv.x; x1 += rv.y;
                }
                if (mode & 1) { x0 = fmaxf(x0, 0.0f); x1 = fmaxf(x1, 0.0f); }
                if (c_half) {
                    *(unsigned*)&((__half*)Cp)[(size_t)rr * N + col] = pack_h2(x0, x1);
                } else {
                    float2 o2 = {x0, x1};
                    *(float2*)&((float*)Cp)[(size_t)rr * N + col] = o2;
                }
            }
        }
    }
}

__global__ __launch_bounds__(256) void tgemm128_f(
    const float* __restrict__ A, const __half* __restrict__ Bm,
    const float* __restrict__ bias, const float* __restrict__ R,
    float* __restrict__ C, int N, int K, int mode)
{
    tg128_body<false>(A, Bm, bias, R, C, N, K, mode, 0,
                      blockIdx.y * 128, blockIdx.x * 64,
                      nullptr, nullptr, nullptr, nullptr);
}

__global__ __launch_bounds__(256) void tgemm128_h(
    const __half* __restrict__ A, const __half* __restrict__ Bm,
    const float* __restrict__ bias, const float* __restrict__ R,
    float* __restrict__ C, int N, int K, int mode)
{
    tg128_body<true>(A, Bm, bias, R, C, N, K, mode, 0,
                     blockIdx.y * 128, blockIdx.x * 64,
                     nullptr, nullptr, nullptr, nullptr);
}

// batched Q/K/V: z=0 -> q (fp16 out), z=1 -> k (fp16 out), z=2 -> v (fp32 out)
__global__ __launch_bounds__(256) void tgemm128_qkv(
    const float* __restrict__ A,
    const __half* __restrict__ Wq, const __half* __restrict__ Wk, const __half* __restrict__ Wv,
    const float* __restrict__ bq, const float* __restrict__ bk, const float* __restrict__ bv,
    __half* __restrict__ qh, __half* __restrict__ kh, float* __restrict__ v,
    const float* __restrict__ mu, const float* __restrict__ rs,
    const float* __restrict__ lg, const float* __restrict__ lb)
{
    const __half* W; const float* bi; void* C; int ch;
    if (blockIdx.z == 0)      { W = Wq; bi = bq; C = qh; ch = 1; }
    else if (blockIdx.z == 1) { W = Wk; bi = bk; C = kh; ch = 1; }
    else                      { W = Wv; bi = bv; C = v;  ch = 0; }
    tg128_body<false>(A, W, bi, nullptr, C, D_, D_, 0, ch,
                      blockIdx.y * 128, blockIdx.x * 64, mu, rs, lg, lb);
}

// ------------------------- FP16 GEMM, BM=128 BN=128 BK=32 (FF1, fp16 out) -----------------
__global__ __launch_bounds__(256) void tgemm256(
    const float* __restrict__ A, const __half* __restrict__ Bm,
    const float* __restrict__ bias, __half* __restrict__ C,
    int N, int K, int mode,
    const float* __restrict__ mu, const float* __restrict__ rs,
    const float* __restrict__ lg, const float* __restrict__ lb)
{
    __shared__ unsigned As[128 * STRH];
    __shared__ unsigned Bs[128 * STRH];

    int tid = threadIdx.x;
    int lane = tid & 31, warp = tid >> 5;
    int wm = warp >> 2, wn = warp & 3;
    int g = lane >> 2, tg = lane & 3;

    int r0 = blockIdx.y * 128, c0 = blockIdx.x * 128;
    const float* Ab = A + (size_t)r0 * K;
    const __half* Bb = Bm + (size_t)c0 * K;

    float acc[4][4][4];
    #pragma unroll
    for (int mt = 0; mt < 4; mt++)
        #pragma unroll
        for (int nt = 0; nt < 4; nt++)
            #pragma unroll
            for (int e = 0; e < 4; e++) acc[mt][nt][e] = 0.0f;

    float muv[4], rsv[4];
    if (lg) {
        #pragma unroll
        for (int i = 0; i < 4; i++) {
            int r = (tid + i * 256) >> 3;
            muv[i] = mu[r0 + r];
            rsv[i] = rs[r0 + r];
        }
    }

    for (int k0 = 0; k0 < K; k0 += 32) {
        #pragma unroll
        for (int i = 0; i < 4; i++) {
            int idx = tid + i * 256, r = idx >> 3, c4 = idx & 7;
            float4 av = *(const float4*)&Ab[(size_t)r * K + k0 + c4 * 4];
            if (lg) {
                float4 ga = *(const float4*)&lg[k0 + c4 * 4];
                float4 be = *(const float4*)&lb[k0 + c4 * 4];
                float m = muv[i], rr = rsv[i];
                av.x = (av.x - m) * rr * ga.x + be.x;
                av.y = (av.y - m) * rr * ga.y + be.y;
                av.z = (av.z - m) * rr * ga.z + be.z;
                av.w = (av.w - m) * rr * ga.w + be.w;
            }
            unsigned* ap = &As[r * STRH + c4 * 2];
            ap[0] = pack_h2(av.x, av.y);
            ap[1] = pack_h2(av.z, av.w);
        }
        // B: 128 rows x 4 uint4 = 512 -> 2 per thread
        #pragma unroll
        for (int i = 0; i < 2; i++) {
            int idx = tid + i * 256, r = idx >> 2, c8 = idx & 3;
            uint4 bw = *(const uint4*)&Bb[(size_t)r * K + k0 + c8 * 8];
            *(uint4*)&Bs[r * STRH + c8 * 4] = bw;
        }
        __syncthreads();

        #pragma unroll
        for (int kc = 0; kc < 2; kc++) {
            int ko = kc * 8;
            unsigned a[4][4], b[4][2];
            #pragma unroll
            for (int mt = 0; mt < 4; mt++) {
                int row = wm * 64 + mt * 16 + g;
                a[mt][0] = As[row * STRH + ko + tg];
                a[mt][1] = As[(row + 8) * STRH + ko + tg];
                a[mt][2] = As[row * STRH + ko + tg + 4];
                a[mt][3] = As[(row + 8) * STRH + ko + tg + 4];
            }
            #pragma unroll
            for (int nt = 0; nt < 4; nt++) {
                int col = wn * 32 + nt * 8 + g;
                b[nt][0] = Bs[col * STRH + ko + tg];
                b[nt][1] = Bs[col * STRH + ko + tg + 4];
            }
            #pragma unroll
            for (int mt = 0; mt < 4; mt++)
                #pragma unroll
                for (int nt = 0; nt < 4; nt++)
                    mma_f16(acc[mt][nt], a[mt][0], a[mt][1], a[mt][2], a[mt][3],
                            b[nt][0], b[nt][1]);
        }
        __syncthreads();
    }

    #pragma unroll
    for (int mt = 0; mt < 4; mt++) {
        int row = r0 + wm * 64 + mt * 16 + g;
        #pragma unroll
        for (int nt = 0; nt < 4; nt++) {
            int col = c0 + wn * 32 + nt * 8 + 2 * tg;
            float2 bi = *(const float2*)&bias[col];
            #pragma unroll
            for (int half = 0; half < 2; half++) {
                int rr = row + half * 8;
                float x0 = acc[mt][nt][half * 2 + 0] + bi.x;
                float x1 = acc[mt][nt][half * 2 + 1] + bi.y;
                if (mode & 1) { x0 = fmaxf(x0, 0.0f); x1 = fmaxf(x1, 0.0f); }
                *(unsigned*)&C[(size_t)rr * N + col] = pack_h2(x0, x1);
            }
        }
    }
}

// ------------------------- fully fused flash attention -------------------------
// S/R MMAs fp16 (q,k,pkn fp16 inputs); P.V stays tf32 (V fp32, probs fp32->tf32).
// DYNAMIC smem (54784 B):
//   Vs [0, 18944)      : two tf32 panes, 64 d-rows x VSTR=37 (32 s-cols each)
//   Kh [18944, 28160)  : 64 rows x KSTRH=36 h2 words
//   Ph [28160, 46592)  : 128 rows x KSTRH=36 h2 words
//   Rs/Ru alias [18944, 52736) : 64 rows x 132 fp32
//   msk [52736, 54784)
#define KSTRH 36
#define VSTR 37
#define VPANE 2368
#define FLASH_SMEM 54784
__global__ __launch_bounds__(128) void flash_attn(
    const __half* __restrict__ q, const __half* __restrict__ k,
    const float* __restrict__ v, const __half* __restrict__ pkn_l,
    const int* __restrict__ masks, float* __restrict__ o)
{
    extern __shared__ char sbuf[];
    unsigned* Vs = (unsigned*)sbuf;
    unsigned* Kh = (unsigned*)(sbuf + 18944);
    unsigned* Ph = (unsigned*)(sbuf + 28160);
    float*    Rs = (float*)(sbuf + 18944);
    unsigned* Ru = (unsigned*)(sbuf + 18944);
    int*      msk = (int*)(sbuf + 52736);

    int tid = threadIdx.x;
    int lane = tid & 31, warp = tid >> 5;
    int g = lane >> 2, tg = lane & 3;
    int rl0 = warp * 16 + g, rl1 = rl0 + 8;

    int t0 = blockIdx.x * 64, bh = blockIdx.y;
    int b = bh >> 2, h = bh & 3;
    const __half* qb  = q + ((size_t)(b * T_ + t0)) * D_ + h * DK;
    const __half* kb0 = k + ((size_t)(b * T_)) * D_ + h * DK;
    const float*  vb0 = v + ((size_t)(b * T_)) * D_ + h * DK;

    // stage masks + Q (Q uses Kh region transiently); rows: 64 x 8 uint4 = 512 -> 4 iters
    #pragma unroll
    for (int i = 0; i < 4; i++) msk[tid + i * 128] = masks[b * T_ + tid + i * 128];
    #pragma unroll
    for (int i = 0; i < 4; i++) {
        int idx = tid + i * 128, r = idx >> 3, c8 = idx & 7;
        uint4 w = *(const uint4*)&qb[(size_t)r * D_ + c8 * 8];
        *(uint4*)&Kh[r * KSTRH + c8 * 4] = w;
    }
    __syncthreads();
    unsigned qa[4][4];
    #pragma unroll
    for (int ks = 0; ks < 4; ks++) {
        qa[ks][0] = Kh[rl0 * KSTRH + ks * 8 + tg];
        qa[ks][1] = Kh[rl1 * KSTRH + ks * 8 + tg];
        qa[ks][2] = Kh[rl0 * KSTRH + ks * 8 + tg + 4];
        qa[ks][3] = Kh[rl1 * KSTRH + ks * 8 + tg + 4];
    }
    __syncthreads();

    float accO[8][4];
    #pragma unroll
    for (int nt = 0; nt < 8; nt++)
        #pragma unroll
        for (int e = 0; e < 4; e++) accO[nt][e] = 0.0f;
    float m0 = -FLT_MAX, m1 = -FLT_MAX, l0 = 0.0f, l1 = 0.0f;

    const float scale = 0.125f;

    for (int sc = 0; sc < 8; sc++) {
        int s0 = sc * 64;
        // ---- stage K (fp16 direct copy) ----
        #pragma unroll
        for (int i = 0; i < 4; i++) {
            int idx = tid + i * 128, r = idx >> 3, c8 = idx & 7;
            uint4 w = *(const uint4*)&kb0[(size_t)(s0 + r) * D_ + c8 * 8];
            *(uint4*)&Kh[r * KSTRH + c8 * 4] = w;
        }
        // ---- stage V transposed tf32, two 32-wide panes (unchanged) ----
        #pragma unroll
        for (int i = 0; i < 8; i++) {
            int idx = tid + i * 128, r = idx >> 4, c4 = idx & 15;
            int half = r >> 5, rsl = r & 31;
            unsigned* vp = &Vs[half * VPANE];
            float4 vv = *(const float4*)&vb0[(size_t)(s0 + r) * D_ + c4 * 4];
            vp[(c4 * 4 + 0) * VSTR + rsl] = f2tf(vv.x);
            vp[(c4 * 4 + 1) * VSTR + rsl] = f2tf(vv.y);
            vp[(c4 * 4 + 2) * VSTR + rsl] = f2tf(vv.z);
            vp[(c4 * 4 + 3) * VSTR + rsl] = f2tf(vv.w);
        }
        // ---- stage P (fp16 direct copy; 127 rows + zero row) ----
        const __half* pb = pkn_l + (size_t)(t0 - s0 + 448) * DK;
        #pragma unroll
        for (int i = 0; i < 8; i++) {
            int idx = tid + i * 128, r = idx >> 3, c8 = idx & 7;
            uint4 w;
            if (r < 127) w = *(const uint4*)&pb[(size_t)r * DK + c8 * 8];
            else { w.x = 0u; w.y = 0u; w.z = 0u; w.w = 0u; }
            *(uint4*)&Ph[r * KSTRH + c8 * 4] = w;
        }
        __syncthreads();

        // ---- S and R MMAs (fp16, 4 k16 steps over d=64) ----
        float accS[8][4], accR[16][4];
        #pragma unroll
        for (int nt = 0; nt < 8; nt++)
            #pragma unroll
            for (int e = 0; e < 4; e++) accS[nt][e] = 0.0f;
        #pragma unroll
        for (int nt = 0; nt < 16; nt++)
            #pragma unroll
            for (int e = 0; e < 4; e++) accR[nt][e] = 0.0f;

        #pragma unroll
        for (int ks = 0; ks < 4; ks++) {
            int ko = ks * 8;
            #pragma unroll
            for (int nt = 0; nt < 8; nt++) {
                int col = nt * 8 + g;
                unsigned b0 = Kh[col * KSTRH + ko + tg];
                unsigned b1 = Kh[col * KSTRH + ko + tg + 4];
                mma_f16(accS[nt], qa[ks][0], qa[ks][1], qa[ks][2], qa[ks][3], b0, b1);
            }
            #pragma unroll
            for (int nt = 0; nt < 16; nt++) {
                int col = nt * 8 + g;
                unsigned b0 = Ph[col * KSTRH + ko + tg];
                unsigned b1 = Ph[col * KSTRH + ko + tg + 4];
                mma_f16(accR[nt], qa[ks][0], qa[ks][1], qa[ks][2], qa[ks][3], b0, b1);
            }
        }
        __syncthreads();   // Kh/Ph reads complete before Rs overwrite

        // ---- spill R (warp-private rows; stride 132 conflict-free) ----
        #pragma unroll
        for (int nt = 0; nt < 16; nt++) {
            int col = nt * 8 + 2 * tg;
            Rs[rl0 * 132 + col]     = accR[nt][0];
            Rs[rl0 * 132 + col + 1] = accR[nt][1];
            Rs[rl1 * 132 + col]     = accR[nt][2];
            Rs[rl1 * 132 + col + 1] = accR[nt][3];
        }
        __syncwarp();

        // ---- gather diagonals, scale + mask ----
        #pragma unroll
        for (int nt = 0; nt < 8; nt++) {
            #pragma unroll
            for (int e = 0; e < 2; e++) {
                int c = nt * 8 + 2 * tg + e;
                float r0 = Rs[rl0 * 132 + (rl0 - c + 63)];
                float r1 = Rs[rl1 * 132 + (rl1 - c + 63)];
                float x0 = (accS[nt][e] + r0) * scale;
                float x1 = (accS[nt][2 + e] + r1) * scale;
                if (msk[s0 + c] == 0) { x0 = -FLT_MAX; x1 = -FLT_MAX; }
                accS[nt][e] = x0;
                accS[nt][2 + e] = x1;
            }
        }
        __syncwarp();

        // ---- online softmax (quad-local) ----
        float cm0 = -FLT_MAX, cm1 = -FLT_MAX;
        #pragma unroll
        for (int nt = 0; nt < 8; nt++) {
            cm0 = fmaxf(cm0, fmaxf(accS[nt][0], accS[nt][1]));
            cm1 = fmaxf(cm1, fmaxf(accS[nt][2], accS[nt][3]));
        }
        cm0 = fmaxf(cm0, __shfl_xor_sync(0xffffffffu, cm0, 1));
        cm0 = fmaxf(cm0, __shfl_xor_sync(0xffffffffu, cm0, 2));
        cm1 = fmaxf(cm1, __shfl_xor_sync(0xffffffffu, cm1, 1));
        cm1 = fmaxf(cm1, __shfl_xor_sync(0xffffffffu, cm1, 2));

        float nm0 = fmaxf(m0, cm0), nm1 = fmaxf(m1, cm1);
        float al0 = __expf(m0 - nm0), al1 = __expf(m1 - nm1);
        float cs0 = 0.0f, cs1 = 0.0f;
        #pragma unroll
        for (int nt = 0; nt < 8; nt++) {
            accS[nt][0] = __expf(accS[nt][0] - nm0);
            accS[nt][1] = __expf(accS[nt][1] - nm0);
            accS[nt][2] = __expf(accS[nt][2] - nm1);
            accS[nt][3] = __expf(accS[nt][3] - nm1);
            cs0 += accS[nt][0] + accS[nt][1];
            cs1 += accS[nt][2] + accS[nt][3];
        }
        cs0 += __shfl_xor_sync(0xffffffffu, cs0, 1);
        cs0 += __shfl_xor_sync(0xffffffffu, cs0, 2);
        cs1 += __shfl_xor_sync(0xffffffffu, cs1, 1);
        cs1 += __shfl_xor_sync(0xffffffffu, cs1, 2);
        l0 = l0 * al0 + cs0;
        l1 = l1 * al1 + cs1;
        m0 = nm0; m1 = nm1;

        #pragma unroll
        for (int nt = 0; nt < 8; nt++) {
            accO[nt][0] *= al0; accO[nt][1] *= al0;
            accO[nt][2] *= al1; accO[nt][3] *= al1;
        }

        // ---- probs -> tf32 pane (warp-private) ----
        #pragma unroll
        for (int nt = 0; nt < 8; nt++) {
            int col = nt * 8 + 2 * tg;
            Ru[rl0 * 132 + col]     = f2tf(accS[nt][0]);
            Ru[rl0 * 132 + col + 1] = f2tf(accS[nt][1]);
            Ru[rl1 * 132 + col]     = f2tf(accS[nt][2]);
            Ru[rl1 * 132 + col + 1] = f2tf(accS[nt][3]);
        }
        __syncwarp();

        // ---- O += P @ V (tf32) ----
        #pragma unroll
        for (int kc = 0; kc < 8; kc++) {
            int ko = kc * 8;
            const unsigned* vp = &Vs[(kc >> 2) * VPANE];
            int so = ko & 31;
            unsigned a0 = Ru[rl0 * 132 + ko + tg];
            unsigned a1 = Ru[rl1 * 132 + ko + tg];
            unsigned a2 = Ru[rl0 * 132 + ko + tg + 4];
            unsigned a3 = Ru[rl1 * 132 + ko + tg + 4];
            #pragma unroll
            for (int nt = 0; nt < 8; nt++) {
                int col = nt * 8 + g;
                unsigned b0 = vp[col * VSTR + so + tg];
                unsigned b1 = vp[col * VSTR + so + tg + 4];
                mma_tf32(accO[nt], a0, a1, a2, a3, b0, b1);
            }
        }
        __syncthreads();
    }

    float inv0 = 1.0f / l0, inv1 = 1.0f / l1;
    #pragma unroll
    for (int nt = 0; nt < 8; nt++) {
        int col = nt * 8 + 2 * tg;
        float2 oa  = {accO[nt][0] * inv0, accO[nt][1] * inv0};
        float2 ob2 = {accO[nt][2] * inv1, accO[nt][3] * inv1};
        *(float2*)&o[((size_t)(b * T_ + t0 + rl0)) * D_ + h * DK + col] = oa;
        *(float2*)&o[((size_t)(b * T_ + t0 + rl1)) * D_ + h * DK + col] = ob2;
    }
}

// ------------------------- host orchestration -------------------------
extern "C" void kernel_launch(void* const* d_in, const int* in_sizes, int n_in,
                              void* d_out, int out_size) {
    const float* xs      = (const float*)d_in[0];
    const int*   masks   = (const int*)  d_in[1];
    const float* emb_w   = (const float*)d_in[2];
    const float* emb_b   = (const float*)d_in[3];
    const float* emb_g   = (const float*)d_in[4];
    const float* emb_bt  = (const float*)d_in[5];
    const float* pe_k    = (const float*)d_in[6];
    const float* Wq      = (const float*)d_in[7];
    const float* bq      = (const float*)d_in[8];
    const float* Wk      = (const float*)d_in[9];
    const float* bk      = (const float*)d_in[10];
    const float* Wv      = (const float*)d_in[11];
    const float* bv      = (const float*)d_in[12];
    const float* Wo      = (const float*)d_in[13];
    const float* bo      = (const float*)d_in[14];
    const float* ln1_g   = (const float*)d_in[15];
    const float* ln1_b   = (const float*)d_in[16];
    const float* ln2_g   = (const float*)d_in[17];
    const float* ln2_b   = (const float*)d_in[18];
    const float* lnk_g   = (const float*)d_in[19];
    const float* lnk_b   = (const float*)d_in[20];
    const float* W1      = (const float*)d_in[21];
    const float* b1      = (const float*)d_in[22];
    const float* W2      = (const float*)d_in[23];
    const float* b2      = (const float*)d_in[24];
    const float* after_g = (const float*)d_in[25];
    const float* after_b = (const float*)d_in[26];
    float* out = (float*)d_out;

    float *x, *y, *v, *o, *mu, *rs;
    __half *qh, *kh, *ffh, *pkn, *hemb, *hq, *hk, *hv, *ho, *h1, *h2;
    cudaGetSymbolAddress((void**)&x,    g_x);
    cudaGetSymbolAddress((void**)&y,    g_y);
    cudaGetSymbolAddress((void**)&v,    g_v);
    cudaGetSymbolAddress((void**)&o,    g_o);
    cudaGetSymbolAddress((void**)&mu,   g_mu);
    cudaGetSymbolAddress((void**)&rs,   g_rs);
    cudaGetSymbolAddress((void**)&qh,   g_qh);
    cudaGetSymbolAddress((void**)&kh,   g_kh);
    cudaGetSymbolAddress((void**)&ffh,  g_ffh);
    cudaGetSymbolAddress((void**)&pkn,  g_pkn);
    cudaGetSymbolAddress((void**)&hemb, g_hemb);
    cudaGetSymbolAddress((void**)&hq,   g_hq);
    cudaGetSymbolAddress((void**)&hk,   g_hk);
    cudaGetSymbolAddress((void**)&hv,   g_hv);
    cudaGetSymbolAddress((void**)&ho,   g_ho);
    cudaGetSymbolAddress((void**)&h1,   g_h1);
    cudaGetSymbolAddress((void**)&h2,   g_h2);

    cudaFuncSetAttribute(flash_attn, cudaFuncAttributeMaxDynamicSharedMemorySize, FLASH_SMEM);

    // weight pre-conversion to fp16
    auto conv = [](const float* src, __half* dst, size_t n) {
        int n4 = (int)(n / 4);
        f2h<<<(n4 + 255) / 256, 256>>>(src, dst, n4);
    };
    conv(emb_w, hemb, (size_t)D_ * IDIM);
    conv(Wq, hq, (size_t)L_ * D_ * D_);
    conv(Wk, hk, (size_t)L_ * D_ * D_);
    conv(Wv, hv, (size_t)L_ * D_ * D_);
    conv(Wo, ho, (size_t)L_ * D_ * D_);
    conv(W1, h1, (size_t)L_ * FF_ * D_);
    conv(W2, h2, (size_t)L_ * D_ * FF_);

    dim3 gProj(D_ / 64, BT / 128);       // (4, 32)
    dim3 gQKV(D_ / 64, BT / 128, 3);     // (4, 32, 3)
    dim3 gFF1(FF_ / 128, BT / 128);      // (16, 32)

    // embed: GEMM + bias -> LN(+relu); pkn LN (fp16) for all layers upfront
    tgemm128_f<<<gProj, 256>>>(xs, hemb, emb_b, nullptr, y, D_, IDIM, 0);
    ln_pkn_all<<<dim3(NPK, L_), 64>>>(pe_k, pkn, lnk_g, lnk_b);
    ln_warp<<<BT / 8, 256>>>(y, x, emb_g, emb_bt, 1);

    for (int l = 0; l < L_; l++) {
        // ln1 fused into QKV staging; q,k written fp16, v fp32
        ln_stats<<<BT / 8, 256>>>(x, mu, rs);
        tgemm128_qkv<<<gQKV, 256>>>(x,
            hq + (size_t)l * D_ * D_, hk + (size_t)l * D_ * D_, hv + (size_t)l * D_ * D_,
            bq + l * D_, bk + l * D_, bv + l * D_, qh, kh, v,
            mu, rs, ln1_g + l * D_, ln1_b + l * D_);

        flash_attn<<<dim3(8, BH), 128, FLASH_SMEM>>>(qh, kh, v,
            pkn + (size_t)l * NPK * DK, masks, o);

        tgemm128_f<<<gProj, 256>>>(o, ho + (size_t)l * D_ * D_, bo + l * D_, x, x, D_, D_, 2);

        // ln2 fused into FF1 staging; ff intermediate fp16
        ln_stats<<<BT / 8, 256>>>(x, mu, rs);
        tgemm256<<<gFF1, 256>>>(x, h1 + (size_t)l * FF_ * D_, b1 + l * FF_, ffh,
                                FF_, D_, 1, mu, rs, ln2_g + l * D_, ln2_b + l * D_);
        tgemm128_h<<<gProj, 256>>>(ffh, h2 + (size_t)l * D_ * FF_, b2 + l * D_, x, x, D_, FF_, 2);
    }

    ln_warp<<<BT / 8, 256>>>(x, out, after_g, after_b, 0);
}